// round 7
// baseline (speedup 1.0000x reference)
#include <cuda_runtime.h>
#include <cstddef>

#define C_SEQ   2304
#define C_DIM   2048
#define C_ROWS  4608
#define C_FFN   8192
#define C_SCALE 0.08838834764831845f   // 1/sqrt(128)

typedef unsigned long long ull;

// ----------------------------------------------------------------- scratch
__device__ float g_t1[6144];
__device__ float g_t2[6144];
__device__ float g_norm[(size_t)C_ROWS * C_DIM];
__device__ float g_q [(size_t)C_ROWS * C_DIM];
__device__ float g_k [(size_t)C_ROWS * C_DIM];
__device__ float g_v [(size_t)C_ROWS * C_DIM];
__device__ float g_ao[(size_t)C_ROWS * C_DIM];
__device__ float g_tp[(size_t)C_ROWS * C_DIM];
__device__ float g_mid[(size_t)C_ROWS * C_FFN];

// ----------------------------------------------------------------- f32x2
__device__ __forceinline__ ull pack2(float lo, float hi) {
    ull r; asm("mov.b64 %0, {%1, %2};" : "=l"(r) : "f"(lo), "f"(hi)); return r;
}
__device__ __forceinline__ float2 unpack2(ull v) {
    float2 r; asm("mov.b64 {%0, %1}, %2;" : "=f"(r.x), "=f"(r.y) : "l"(v)); return r;
}
__device__ __forceinline__ void fma2(ull &d, ull a, ull b) {
    asm("fma.rn.f32x2 %0, %1, %2, %0;" : "+l"(d) : "l"(a), "l"(b));
}

// ----------------------------------------------------------------- temb -> t1/t2
__global__ __launch_bounds__(256) void temb_kernel(
    const float* __restrict__ temb,
    const float* __restrict__ lw1, const float* __restrict__ lb1,
    const float* __restrict__ lw2, const float* __restrict__ lb2,
    float* __restrict__ t1, float* __restrict__ t2)
{
    __shared__ float s[512];
    int tid = threadIdx.x;
    float a = temb[tid], b = temb[tid + 256];
    s[tid]       = a / (1.f + __expf(-a));
    s[tid + 256] = b / (1.f + __expf(-b));
    __syncthreads();
    const float* lw = blockIdx.y ? lw2 : lw1;
    const float* lb = blockIdx.y ? lb2 : lb1;
    float* t        = blockIdx.y ? t2  : t1;
    int j = blockIdx.x * 256 + tid;
    float acc = lb[j];
#pragma unroll 8
    for (int i = 0; i < 512; ++i) acc += s[i] * lw[(size_t)i * 6144 + j];
    t[j] = acc;
}

// ----------------------------------------------------------------- LN + modulation
__global__ __launch_bounds__(256) void ln_mod_kernel(
    const float* __restrict__ st, const float* __restrict__ t,
    const float* __restrict__ nw, const float* __restrict__ nb,
    float* __restrict__ dst)
{
    int row = blockIdx.x, tid = threadIdx.x;
    const float* x = st + (size_t)row * C_DIM;
    float4 v0 = *(const float4*)(x + tid * 8);
    float4 v1 = *(const float4*)(x + tid * 8 + 4);
    float xv[8] = {v0.x, v0.y, v0.z, v0.w, v1.x, v1.y, v1.z, v1.w};
    float s = 0.f, ss = 0.f;
#pragma unroll
    for (int e = 0; e < 8; ++e) { s += xv[e]; ss += xv[e] * xv[e]; }
#pragma unroll
    for (int o = 16; o > 0; o >>= 1) {
        s  += __shfl_xor_sync(0xffffffffu, s, o);
        ss += __shfl_xor_sync(0xffffffffu, ss, o);
    }
    __shared__ float rs[8], rss[8];
    if ((tid & 31) == 0) { rs[tid >> 5] = s; rss[tid >> 5] = ss; }
    __syncthreads();
    float tot = 0.f, tot2 = 0.f;
#pragma unroll
    for (int w = 0; w < 8; ++w) { tot += rs[w]; tot2 += rss[w]; }
    float mu   = tot * (1.f / 2048.f);
    float var  = tot2 * (1.f / 2048.f) - mu * mu;
    float rstd = rsqrtf(var + 1e-5f);
    float out[8];
#pragma unroll
    for (int e = 0; e < 8; ++e) {
        int c = tid * 8 + e;
        float xn = (xv[e] - mu) * rstd * nw[c] + nb[c];
        out[e] = xn * (1.f + t[2048 + c]) + t[c];
    }
    float* d = dst + (size_t)row * C_DIM + tid * 8;
    *(float4*)d       = make_float4(out[0], out[1], out[2], out[3]);
    *(float4*)(d + 4) = make_float4(out[4], out[5], out[6], out[7]);
}

// ----------------------------------------------------------------- GEMM (f32x2)
__device__ __forceinline__ float gelu_t(float x) {
    float x3 = x * x * x;
    return 0.5f * x * (1.f + tanhf(0.7978845608028654f * (x + 0.044715f * x3)));
}

__global__ __launch_bounds__(256, 2) void gemm_kernel(
    const float* __restrict__ A, const float* __restrict__ B,
    const float* __restrict__ bias, float* __restrict__ C,
    int M, int N, int K, int act)
{
    __shared__ float As[8][128];
    __shared__ float Bs[8][128];
    const int tid  = threadIdx.x;
    const int bm   = blockIdx.y << 7;
    const int bn   = blockIdx.x << 7;
    const int arow = tid >> 1;
    const int acol = (tid & 1) << 2;
    const int brow = tid >> 5;
    const int bcol = (tid & 31) << 2;
    const int rb   = (tid >> 4) << 3;
    const int cb   = (tid & 15) << 3;

    const float* Ap = A + (size_t)(bm + arow) * K + acol;
    const float* Bp = B + (size_t)brow * N + bn + bcol;

    ull acc[4][8];
#pragma unroll
    for (int p = 0; p < 4; ++p)
#pragma unroll
        for (int j = 0; j < 8; ++j) acc[p][j] = 0ull;

    float4 a4 = *(const float4*)Ap;
    float4 b4 = *(const float4*)Bp;
    const int nt = K >> 3;
    for (int tI = 0; tI < nt; ++tI) {
        As[acol + 0][arow] = a4.x;
        As[acol + 1][arow] = a4.y;
        As[acol + 2][arow] = a4.z;
        As[acol + 3][arow] = a4.w;
        *(float4*)&Bs[brow][bcol] = b4;
        __syncthreads();
        if (tI + 1 < nt) {
            a4 = *(const float4*)(Ap + (tI + 1) * 8);
            b4 = *(const float4*)(Bp + (size_t)(tI + 1) * 8 * N);
        }
#pragma unroll
        for (int k = 0; k < 8; ++k) {
            float4 af0 = *(const float4*)&As[k][rb];
            float4 af1 = *(const float4*)&As[k][rb + 4];
            float4 bf0 = *(const float4*)&Bs[k][cb];
            float4 bf1 = *(const float4*)&Bs[k][cb + 4];
            ull ap[4] = {pack2(af0.x, af0.y), pack2(af0.z, af0.w),
                         pack2(af1.x, af1.y), pack2(af1.z, af1.w)};
            ull bd[8] = {pack2(bf0.x, bf0.x), pack2(bf0.y, bf0.y),
                         pack2(bf0.z, bf0.z), pack2(bf0.w, bf0.w),
                         pack2(bf1.x, bf1.x), pack2(bf1.y, bf1.y),
                         pack2(bf1.z, bf1.z), pack2(bf1.w, bf1.w)};
#pragma unroll
            for (int p = 0; p < 4; ++p)
#pragma unroll
                for (int j = 0; j < 8; ++j)
                    fma2(acc[p][j], ap[p], bd[j]);
        }
        __syncthreads();
    }
#pragma unroll
    for (int p = 0; p < 4; ++p) {
        float o0[8], o1[8];
#pragma unroll
        for (int j = 0; j < 8; ++j) {
            float2 u = unpack2(acc[p][j]);
            float bz = bias[bn + cb + j];
            o0[j] = u.x + bz;
            o1[j] = u.y + bz;
        }
        if (act == 1) {
#pragma unroll
            for (int j = 0; j < 8; ++j) { o0[j] = gelu_t(o0[j]); o1[j] = gelu_t(o1[j]); }
        }
        size_t r0 = (size_t)(bm + rb + 2 * p) * N + bn + cb;
        *(float4*)&C[r0]         = make_float4(o0[0], o0[1], o0[2], o0[3]);
        *(float4*)&C[r0 + 4]     = make_float4(o0[4], o0[5], o0[6], o0[7]);
        *(float4*)&C[r0 + N]     = make_float4(o1[0], o1[1], o1[2], o1[3]);
        *(float4*)&C[r0 + N + 4] = make_float4(o1[4], o1[5], o1[6], o1[7]);
    }
}

// ----------------------------------------------------------------- RMSNorm + RoPE
__global__ __launch_bounds__(256) void rmsrope_kernel(
    float* __restrict__ Qm, float* __restrict__ Km,
    const float* __restrict__ nq, const float* __restrict__ nk,
    const float* __restrict__ cos_h, const float* __restrict__ sin_h,
    const float* __restrict__ cos_r, const float* __restrict__ sin_r)
{
    int row = blockIdx.x, tid = threadIdx.x;
    float* x = (blockIdx.y ? Km : Qm) + (size_t)row * C_DIM;
    const float* nw = blockIdx.y ? nk : nq;
    int isr = row >= C_SEQ;
    int pos = isr ? row - C_SEQ : row;
    const float* cp = (isr ? cos_r : cos_h) + (size_t)pos * 128;
    const float* sp = (isr ? sin_r : sin_h) + (size_t)pos * 128;
    float4 v0 = *(const float4*)(x + tid * 8);
    float4 v1 = *(const float4*)(x + tid * 8 + 4);
    float xv[8] = {v0.x, v0.y, v0.z, v0.w, v1.x, v1.y, v1.z, v1.w};
    float ss = 0.f;
#pragma unroll
    for (int e = 0; e < 8; ++e) ss += xv[e] * xv[e];
#pragma unroll
    for (int o = 16; o > 0; o >>= 1) ss += __shfl_xor_sync(0xffffffffu, ss, o);
    __shared__ float rss[8];
    if ((tid & 31) == 0) rss[tid >> 5] = ss;
    __syncthreads();
    float tot = 0.f;
#pragma unroll
    for (int w = 0; w < 8; ++w) tot += rss[w];
    float rstd = rsqrtf(tot * (1.f / 2048.f) + 1e-6f);
    float out[8];
#pragma unroll
    for (int p = 0; p < 4; ++p) {
        int ce = tid * 8 + 2 * p;
        int de = ce & 127;
        float x1 = xv[2 * p]     * rstd * nw[ce];
        float x2 = xv[2 * p + 1] * rstd * nw[ce + 1];
        float cv = cp[de], sv = sp[de + 1];
        out[2 * p]     = x1 * cv - x2 * sv;
        out[2 * p + 1] = x1 * sv + x2 * cv;
    }
    *(float4*)(x + tid * 8)     = make_float4(out[0], out[1], out[2], out[3]);
    *(float4*)(x + tid * 8 + 4) = make_float4(out[4], out[5], out[6], out[7]);
}

// ----------------------------------------------------------------- attention
__device__ __forceinline__ int combined_row(int fi, int j) {
    int hi = j / 48;
    int wi = j - hi * 48;
    int base = (wi < 24) ? 0 : C_SEQ;
    int ww   = (wi < 24) ? wi : wi - 24;
    return base + fi * 576 + hi * 24 + ww;
}

#define AT_STR 65
#define ATTN_SMEM ((128 * AT_STR * 2 + 64 * 128 + 64 * 66 + 192) * 4)

__global__ __launch_bounds__(256) void attn_kernel(
    const float* __restrict__ Q, const float* __restrict__ K,
    const float* __restrict__ V, float* __restrict__ O)
{
    extern __shared__ float sm[];
    float* Qt   = sm;                        // [128][65] d-major, pre-scaled
    float* Kt   = Qt + 128 * AT_STR;         // [128][65] d-major
    float* Vs   = Kt + 128 * AT_STR;         // [64][128]
    float* Sb   = Vs + 64 * 128;             // [64][66]
    float* mrow = Sb + 64 * 66;
    float* lrow = mrow + 64;
    float* arow = lrow + 64;

    const int tid  = threadIdx.x;
    const int fi   = blockIdx.y >> 4;
    const int coloff = (blockIdx.y & 15) * 128;
    const int q0   = blockIdx.x * 64;
    const int ty   = tid >> 4, tx = tid & 15;
    const int r0   = ty * 4, c0 = tx * 4, cv0 = tx * 8;

#pragma unroll
    for (int it = 0; it < 8; ++it) {
        int idx = tid + it * 256;
        int r = idx >> 5, d0 = (idx & 31) << 2;
        int grow = combined_row(fi, q0 + r);
        float4 qv = *(const float4*)&Q[(size_t)grow * C_DIM + coloff + d0];
        Qt[(d0 + 0) * AT_STR + r] = qv.x * C_SCALE;
        Qt[(d0 + 1) * AT_STR + r] = qv.y * C_SCALE;
        Qt[(d0 + 2) * AT_STR + r] = qv.z * C_SCALE;
        Qt[(d0 + 3) * AT_STR + r] = qv.w * C_SCALE;
    }
    if (tid < 64) { mrow[tid] = -1e30f; lrow[tid] = 0.f; }

    float acc[4][8];
#pragma unroll
    for (int i = 0; i < 4; ++i)
#pragma unroll
        for (int j = 0; j < 8; ++j) acc[i][j] = 0.f;

    for (int kc = 0; kc < 18; ++kc) {
        int k0 = kc * 64;
        __syncthreads();
#pragma unroll
        for (int it = 0; it < 8; ++it) {
            int idx = tid + it * 256;
            int r = idx >> 5, d0 = (idx & 31) << 2;
            int grow = combined_row(fi, k0 + r);
            float4 kv = *(const float4*)&K[(size_t)grow * C_DIM + coloff + d0];
            Kt[(d0 + 0) * AT_STR + r] = kv.x;
            Kt[(d0 + 1) * AT_STR + r] = kv.y;
            Kt[(d0 + 2) * AT_STR + r] = kv.z;
            Kt[(d0 + 3) * AT_STR + r] = kv.w;
        }
#pragma unroll
        for (int it = 0; it < 8; ++it) {
            int idx = tid + it * 256;
            int r = idx >> 5, c4 = (idx & 31) << 2;
            int grow = combined_row(fi, k0 + r);
            *(float4*)&Vs[r * 128 + c4] =
                *(const float4*)&V[(size_t)grow * C_DIM + coloff + c4];
        }
        __syncthreads();

        // S = Q K^T (scaled via Q)
        float s[4][4];
#pragma unroll
        for (int i = 0; i < 4; ++i)
#pragma unroll
            for (int j = 0; j < 4; ++j) s[i][j] = 0.f;
        for (int d = 0; d < 128; ++d) {
            const float* qr = &Qt[d * AT_STR + r0];
            const float* kr = &Kt[d * AT_STR + c0];
            float qa = qr[0], qb = qr[1], qc = qr[2], qd = qr[3];
            float ka = kr[0], kb = kr[1], kcv = kr[2], kd = kr[3];
            s[0][0] += qa * ka; s[0][1] += qa * kb; s[0][2] += qa * kcv; s[0][3] += qa * kd;
            s[1][0] += qb * ka; s[1][1] += qb * kb; s[1][2] += qb * kcv; s[1][3] += qb * kd;
            s[2][0] += qc * ka; s[2][1] += qc * kb; s[2][2] += qc * kcv; s[2][3] += qc * kd;
            s[3][0] += qd * ka; s[3][1] += qd * kb; s[3][2] += qd * kcv; s[3][3] += qd * kd;
        }
#pragma unroll
        for (int i = 0; i < 4; ++i)
#pragma unroll
            for (int j = 0; j < 4; ++j)
                Sb[(r0 + i) * 66 + c0 + j] = s[i][j];
        __syncthreads();

        // online softmax, one thread per row
        if (tid < 64) {
            float m = mrow[tid];
            float mx = m;
            float* sr = &Sb[tid * 66];
#pragma unroll 8
            for (int c = 0; c < 64; ++c) mx = fmaxf(mx, sr[c]);
            float fac = __expf(m - mx);
            float l = lrow[tid] * fac;
#pragma unroll 8
            for (int c = 0; c < 64; ++c) {
                float e = __expf(sr[c] - mx);
                sr[c] = e;
                l += e;
            }
            mrow[tid] = mx; lrow[tid] = l; arow[tid] = fac;
        }
        __syncthreads();

        float f0 = arow[r0], f1 = arow[r0 + 1], f2 = arow[r0 + 2], f3 = arow[r0 + 3];
#pragma unroll
        for (int j = 0; j < 8; ++j) {
            acc[0][j] *= f0; acc[1][j] *= f1; acc[2][j] *= f2; acc[3][j] *= f3;
        }
        // PV
        for (int c = 0; c < 64; ++c) {
            float p0 = Sb[(r0 + 0) * 66 + c];
            float p1 = Sb[(r0 + 1) * 66 + c];
            float p2 = Sb[(r0 + 2) * 66 + c];
            float p3 = Sb[(r0 + 3) * 66 + c];
            float4 va = *(const float4*)&Vs[c * 128 + cv0];
            float4 vb = *(const float4*)&Vs[c * 128 + cv0 + 4];
            float vv[8] = {va.x, va.y, va.z, va.w, vb.x, vb.y, vb.z, vb.w};
#pragma unroll
            for (int j = 0; j < 8; ++j) {
                acc[0][j] += p0 * vv[j];
                acc[1][j] += p1 * vv[j];
                acc[2][j] += p2 * vv[j];
                acc[3][j] += p3 * vv[j];
            }
        }
    }
    __syncthreads();
#pragma unroll
    for (int i = 0; i < 4; ++i) {
        float inv = 1.f / lrow[r0 + i];
        int grow = combined_row(fi, q0 + r0 + i);
        float* op = &O[(size_t)grow * C_DIM + coloff + cv0];
        *(float4*)op       = make_float4(acc[i][0] * inv, acc[i][1] * inv,
                                         acc[i][2] * inv, acc[i][3] * inv);
        *(float4*)(op + 4) = make_float4(acc[i][4] * inv, acc[i][5] * inv,
                                         acc[i][6] * inv, acc[i][7] * inv);
    }
}

// ----------------------------------------------------------------- residual gate
__global__ __launch_bounds__(256) void resid_kernel(
    float* __restrict__ st, const float* __restrict__ x, const float* __restrict__ t)
{
    size_t base = (size_t)blockIdx.x * C_DIM + threadIdx.x * 8;
    const float* g = t + 4096 + threadIdx.x * 8;
    float4 s0 = *(float4*)&st[base],     s1 = *(float4*)&st[base + 4];
    float4 x0 = *(const float4*)&x[base], x1 = *(const float4*)&x[base + 4];
    float4 g0 = *(const float4*)&g[0],   g1 = *(const float4*)&g[4];
    s0.x += g0.x * x0.x; s0.y += g0.y * x0.y; s0.z += g0.z * x0.z; s0.w += g0.w * x0.w;
    s1.x += g1.x * x1.x; s1.y += g1.y * x1.y; s1.z += g1.z * x1.z; s1.w += g1.w * x1.w;
    *(float4*)&st[base]     = s0;
    *(float4*)&st[base + 4] = s1;
}

// ----------------------------------------------------------------- launch
extern "C" void kernel_launch(void* const* d_in, const int* in_sizes, int n_in,
                              void* d_out, int out_size)
{
    const float* temb  = (const float*)d_in[2];
    const float* cos_h = (const float*)d_in[3];
    const float* sin_h = (const float*)d_in[4];
    const float* cos_r = (const float*)d_in[5];
    const float* sin_r = (const float*)d_in[6];
    const float* l1lw = (const float*)d_in[7],  *l1lb = (const float*)d_in[8];
    const float* l1nw = (const float*)d_in[9],  *l1nb = (const float*)d_in[10];
    const float* l2lw = (const float*)d_in[11], *l2lb = (const float*)d_in[12];
    const float* l2nw = (const float*)d_in[13], *l2nb = (const float*)d_in[14];
    const float* wq = (const float*)d_in[15], *bq = (const float*)d_in[16];
    const float* wk = (const float*)d_in[17], *bk = (const float*)d_in[18];
    const float* wv = (const float*)d_in[19], *bv = (const float*)d_in[20];
    const float* nqw = (const float*)d_in[21], *nkw = (const float*)d_in[22];
    const float* wo = (const float*)d_in[23], *bo = (const float*)d_in[24];
    const float* fw1 = (const float*)d_in[25], *fb1 = (const float*)d_in[26];
    const float* fw2 = (const float*)d_in[27], *fb2 = (const float*)d_in[28];
    float* st = (float*)d_out;

    float *t1, *t2, *nrm, *q, *k, *v, *ao, *tp, *mid;
    cudaGetSymbolAddress((void**)&t1,  g_t1);
    cudaGetSymbolAddress((void**)&t2,  g_t2);
    cudaGetSymbolAddress((void**)&nrm, g_norm);
    cudaGetSymbolAddress((void**)&q,   g_q);
    cudaGetSymbolAddress((void**)&k,   g_k);
    cudaGetSymbolAddress((void**)&v,   g_v);
    cudaGetSymbolAddress((void**)&ao,  g_ao);
    cudaGetSymbolAddress((void**)&tp,  g_tp);
    cudaGetSymbolAddress((void**)&mid, g_mid);

    size_t half = (size_t)C_SEQ * C_DIM * sizeof(float);
    cudaMemcpyAsync(st, d_in[0], half, cudaMemcpyDeviceToDevice, 0);
    cudaMemcpyAsync(st + (size_t)C_SEQ * C_DIM, d_in[1], half, cudaMemcpyDeviceToDevice, 0);

    cudaFuncSetAttribute(attn_kernel, cudaFuncAttributeMaxDynamicSharedMemorySize, ATTN_SMEM);

    temb_kernel<<<dim3(24, 2), 256>>>(temb, l1lw, l1lb, l2lw, l2lb, t1, t2);
    ln_mod_kernel<<<C_ROWS, 256>>>(st, t1, l1nw, l1nb, nrm);
    gemm_kernel<<<dim3(16, 36), 256>>>(nrm, wq, bq, q, C_ROWS, C_DIM, C_DIM, 0);
    gemm_kernel<<<dim3(16, 36), 256>>>(nrm, wk, bk, k, C_ROWS, C_DIM, C_DIM, 0);
    gemm_kernel<<<dim3(16, 36), 256>>>(nrm, wv, bv, v, C_ROWS, C_DIM, C_DIM, 0);
    rmsrope_kernel<<<dim3(C_ROWS, 2), 256>>>(q, k, nqw, nkw, cos_h, sin_h, cos_r, sin_r);
    attn_kernel<<<dim3(18, 64), 256, ATTN_SMEM>>>(q, k, v, ao);
    gemm_kernel<<<dim3(16, 36), 256>>>(ao, wo, bo, tp, C_ROWS, C_DIM, C_DIM, 0);
    resid_kernel<<<C_ROWS, 256>>>(st, tp, t1);
    ln_mod_kernel<<<C_ROWS, 256>>>(st, t2, l2nw, l2nb, nrm);
    gemm_kernel<<<dim3(64, 36), 256>>>(nrm, fw1, fb1, mid, C_ROWS, C_FFN, C_DIM, 1);
    gemm_kernel<<<dim3(16, 36), 256>>>(mid, fw2, fb2, tp, C_ROWS, C_DIM, C_FFN, 0);
    resid_kernel<<<C_ROWS, 256>>>(st, tp, t2);
}

// round 10
// speedup vs baseline: 2.0537x; 2.0537x over previous
#include <cuda_runtime.h>
#include <cuda_bf16.h>
#include <cstdint>
#include <cstddef>

#define C_SEQ   2304
#define C_DIM   2048
#define C_ROWS  4608
#define C_FFN   8192
#define C_SCALE 0.08838834764831845f   // 1/sqrt(128)

// ----------------------------------------------------------------- scratch
__device__ float g_t1[6144];
__device__ float g_t2[6144];
__device__ __nv_bfloat16 g_nrmH[(size_t)C_ROWS * C_DIM];
__device__ __nv_bfloat16 g_nrmL[(size_t)C_ROWS * C_DIM];
__device__ float g_q [(size_t)C_ROWS * C_DIM];
__device__ float g_k [(size_t)C_ROWS * C_DIM];
__device__ float g_v [(size_t)C_ROWS * C_DIM];
__device__ float g_ao[(size_t)C_ROWS * C_DIM];
__device__ float g_tp[(size_t)C_ROWS * C_DIM];
__device__ __nv_bfloat16 g_aoH[(size_t)C_ROWS * C_DIM];
__device__ __nv_bfloat16 g_aoL[(size_t)C_ROWS * C_DIM];
__device__ __nv_bfloat16 g_midH[(size_t)C_ROWS * C_FFN];
__device__ __nv_bfloat16 g_midL[(size_t)C_ROWS * C_FFN];
// transposed+split weights: [N, K] bf16 hi/lo
__device__ __nv_bfloat16 g_wqH[(size_t)C_DIM * C_DIM];
__device__ __nv_bfloat16 g_wqL[(size_t)C_DIM * C_DIM];
__device__ __nv_bfloat16 g_wkH[(size_t)C_DIM * C_DIM];
__device__ __nv_bfloat16 g_wkL[(size_t)C_DIM * C_DIM];
__device__ __nv_bfloat16 g_wvH[(size_t)C_DIM * C_DIM];
__device__ __nv_bfloat16 g_wvL[(size_t)C_DIM * C_DIM];
__device__ __nv_bfloat16 g_woH[(size_t)C_DIM * C_DIM];
__device__ __nv_bfloat16 g_woL[(size_t)C_DIM * C_DIM];
__device__ __nv_bfloat16 g_f1H[(size_t)C_FFN * C_DIM];
__device__ __nv_bfloat16 g_f1L[(size_t)C_FFN * C_DIM];
__device__ __nv_bfloat16 g_f2H[(size_t)C_DIM * C_FFN];
__device__ __nv_bfloat16 g_f2L[(size_t)C_DIM * C_FFN];

// ----------------------------------------------------------------- helpers
__device__ __forceinline__ uint32_t smem_u32(const void* p) {
    uint32_t a;
    asm("{ .reg .u64 t; cvta.to.shared.u64 t, %1; cvt.u32.u64 %0, t; }" : "=r"(a) : "l"(p));
    return a;
}
#define CP16(dst, src) \
    asm volatile("cp.async.cg.shared.global [%0], [%1], 16;" :: "r"(dst), "l"(src) : "memory")
#define CP_COMMIT() asm volatile("cp.async.commit_group;" ::: "memory")
#define CP_WAIT1()  asm volatile("cp.async.wait_group 1;" ::: "memory")
#define LDSM4(r, p) \
    asm volatile("ldmatrix.sync.aligned.m8n8.x4.shared.b16 {%0,%1,%2,%3}, [%4];" \
        : "=r"((r)[0]), "=r"((r)[1]), "=r"((r)[2]), "=r"((r)[3]) : "r"(p))

__device__ __forceinline__ void mma_bf16(float* d, const uint32_t* a, const uint32_t* b) {
    asm volatile("mma.sync.aligned.m16n8k16.row.col.f32.bf16.bf16.f32 "
        "{%0,%1,%2,%3}, {%4,%5,%6,%7}, {%8,%9}, {%0,%1,%2,%3};"
        : "+f"(d[0]), "+f"(d[1]), "+f"(d[2]), "+f"(d[3])
        : "r"(a[0]), "r"(a[1]), "r"(a[2]), "r"(a[3]), "r"(b[0]), "r"(b[1]));
}
__device__ __forceinline__ void split_bf16(float x, __nv_bfloat16& h, __nv_bfloat16& l) {
    h = __float2bfloat16(x);
    l = __float2bfloat16(x - __bfloat162float(h));
}
__device__ __forceinline__ float gelu_t(float x) {
    float x3 = x * x * x;
    return 0.5f * x * (1.f + tanhf(0.7978845608028654f * (x + 0.044715f * x3)));
}

// ----------------------------------------------------------------- temb -> t1/t2
__global__ __launch_bounds__(256) void temb_kernel(
    const float* __restrict__ temb,
    const float* __restrict__ lw1, const float* __restrict__ lb1,
    const float* __restrict__ lw2, const float* __restrict__ lb2,
    float* __restrict__ t1, float* __restrict__ t2)
{
    __shared__ float s[512];
    int tid = threadIdx.x;
    float a = temb[tid], b = temb[tid + 256];
    s[tid]       = a / (1.f + __expf(-a));
    s[tid + 256] = b / (1.f + __expf(-b));
    __syncthreads();
    const float* lw = blockIdx.y ? lw2 : lw1;
    const float* lb = blockIdx.y ? lb2 : lb1;
    float* t        = blockIdx.y ? t2  : t1;
    int j = blockIdx.x * 256 + tid;
    float acc = lb[j];
#pragma unroll 8
    for (int i = 0; i < 512; ++i) acc += s[i] * lw[(size_t)i * 6144 + j];
    t[j] = acc;
}

// ----------------------------------------------------------------- LN + modulation -> bf16 hi/lo
__global__ __launch_bounds__(256) void ln_mod_kernel(
    const float* __restrict__ st, const float* __restrict__ t,
    const float* __restrict__ nw, const float* __restrict__ nb,
    __nv_bfloat16* __restrict__ H, __nv_bfloat16* __restrict__ L)
{
    int row = blockIdx.x, tid = threadIdx.x;
    const float* x = st + (size_t)row * C_DIM;
    float4 v0 = *(const float4*)(x + tid * 8);
    float4 v1 = *(const float4*)(x + tid * 8 + 4);
    float xv[8] = {v0.x, v0.y, v0.z, v0.w, v1.x, v1.y, v1.z, v1.w};
    float s = 0.f, ss = 0.f;
#pragma unroll
    for (int e = 0; e < 8; ++e) { s += xv[e]; ss += xv[e] * xv[e]; }
#pragma unroll
    for (int o = 16; o > 0; o >>= 1) {
        s  += __shfl_xor_sync(0xffffffffu, s, o);
        ss += __shfl_xor_sync(0xffffffffu, ss, o);
    }
    __shared__ float rs[8], rss[8];
    if ((tid & 31) == 0) { rs[tid >> 5] = s; rss[tid >> 5] = ss; }
    __syncthreads();
    float tot = 0.f, tot2 = 0.f;
#pragma unroll
    for (int w = 0; w < 8; ++w) { tot += rs[w]; tot2 += rss[w]; }
    float mu   = tot * (1.f / 2048.f);
    float var  = tot2 * (1.f / 2048.f) - mu * mu;
    float rstd = rsqrtf(var + 1e-5f);
    size_t ob = (size_t)row * C_DIM + tid * 8;
#pragma unroll
    for (int e = 0; e < 8; e += 2) {
        int c = tid * 8 + e;
        float a0 = ((xv[e]   - mu) * rstd * nw[c]   + nb[c])   * (1.f + t[2048 + c])   + t[c];
        float a1 = ((xv[e+1] - mu) * rstd * nw[c+1] + nb[c+1]) * (1.f + t[2048 + c+1]) + t[c+1];
        __nv_bfloat16 h0, l0, h1, l1;
        split_bf16(a0, h0, l0); split_bf16(a1, h1, l1);
        __nv_bfloat162 hp; hp.x = h0; hp.y = h1;
        __nv_bfloat162 lp; lp.x = l0; lp.y = l1;
        *(__nv_bfloat162*)(H + ob + e) = hp;
        *(__nv_bfloat162*)(L + ob + e) = lp;
    }
}

// ----------------------------------------------------------------- weight transpose + split
__global__ __launch_bounds__(256) void wsplit_kernel(
    const float* __restrict__ W, __nv_bfloat16* __restrict__ Th,
    __nv_bfloat16* __restrict__ Tl, int K, int N)
{
    __shared__ float t[32][33];
    int n0 = blockIdx.x * 32, k0 = blockIdx.y * 32;
    int tx = threadIdx.x & 31, ty = threadIdx.x >> 5;
#pragma unroll
    for (int i = 0; i < 4; ++i)
        t[ty * 4 + i][tx] = W[(size_t)(k0 + ty * 4 + i) * N + n0 + tx];
    __syncthreads();
#pragma unroll
    for (int i = 0; i < 4; ++i) {
        int r = ty * 4 + i;
        float x = t[tx][r];
        __nv_bfloat16 h, l; split_bf16(x, h, l);
        size_t o = (size_t)(n0 + r) * K + k0 + tx;
        Th[o] = h; Tl[o] = l;
    }
}

// ----------------------------------------------------------------- fp32 -> bf16 hi/lo split
__global__ __launch_bounds__(256) void split_kernel(
    const float* __restrict__ X, __nv_bfloat16* __restrict__ H, __nv_bfloat16* __restrict__ L)
{
    size_t i = ((size_t)blockIdx.x * 256 + threadIdx.x) * 4;
    float4 v = *(const float4*)&X[i];
    __nv_bfloat16 h0, l0, h1, l1, h2, l2, h3, l3;
    split_bf16(v.x, h0, l0); split_bf16(v.y, h1, l1);
    split_bf16(v.z, h2, l2); split_bf16(v.w, h3, l3);
    __nv_bfloat162 a, b;
    a.x = h0; a.y = h1; b.x = h2; b.y = h3;
    *(__nv_bfloat162*)(H + i)     = a;
    *(__nv_bfloat162*)(H + i + 2) = b;
    a.x = l0; a.y = l1; b.x = l2; b.y = l3;
    *(__nv_bfloat162*)(L + i)     = a;
    *(__nv_bfloat162*)(L + i + 2) = b;
}

// ----------------------------------------------------------------- mma.sync GEMM (bf16x3)
// D[M,N] = A[M,K] * B[N,K]^T; A/B as bf16 hi/lo, K-contiguous.
#define MG_TILE_B  10240            // 128 rows * 40 halves * 2B
#define MG_STAGE_B (4 * MG_TILE_B)  // Ah, Al, Bh, Bl
#define MG_SMEM    (2 * MG_STAGE_B) // 81920

__global__ __launch_bounds__(256) void mma_gemm(
    const __nv_bfloat16* __restrict__ Ah, const __nv_bfloat16* __restrict__ Al,
    const __nv_bfloat16* __restrict__ Bh, const __nv_bfloat16* __restrict__ Bl,
    const float* __restrict__ bias, float* __restrict__ outF,
    __nv_bfloat16* __restrict__ outH, __nv_bfloat16* __restrict__ outL,
    int N, int K, int act)
{
    extern __shared__ char smc[];
    const uint32_t sb = smem_u32(smc);
    const int tid = threadIdx.x, lane = tid & 31, wid = tid >> 5;
    const int wm = wid & 3, wn = wid >> 2;
    const int m0 = blockIdx.y << 7, n0 = blockIdx.x << 7;

    auto load_chunk = [&](int c, int buf) {
        int k0 = c << 5;
        uint32_t st = sb + buf * MG_STAGE_B;
#pragma unroll
        for (int j = 0; j < 2; ++j) {
            int q = tid + j * 256;
            int r = q >> 2, c4 = q & 3;
            uint32_t d = st + r * 80 + c4 * 16;
            size_t ga = (size_t)(m0 + r) * K + k0 + c4 * 8;
            size_t gb = (size_t)(n0 + r) * K + k0 + c4 * 8;
            CP16(d + 0 * MG_TILE_B, Ah + ga);
            CP16(d + 1 * MG_TILE_B, Al + ga);
            CP16(d + 2 * MG_TILE_B, Bh + gb);
            CP16(d + 3 * MG_TILE_B, Bl + gb);
        }
    };

    // ldmatrix per-lane address components
    const int mrow = (lane & 7) + ((lane >> 3) & 1) * 8;
    const int achk = lane >> 4;
    const int nrow = (lane & 7) + (lane >> 4) * 8;
    const int bchk = (lane >> 3) & 1;
    const uint32_t aoff = (uint32_t)(wm * 32 + mrow) * 80 + achk * 16;
    const uint32_t boff = (uint32_t)(wn * 64 + nrow) * 80 + bchk * 16;

    float acc[2][8][4];
#pragma unroll
    for (int i = 0; i < 2; ++i)
#pragma unroll
        for (int j = 0; j < 8; ++j)
#pragma unroll
            for (int e = 0; e < 4; ++e) acc[i][j][e] = 0.f;

    const int NC = K >> 5;
    load_chunk(0, 0); CP_COMMIT();
    load_chunk(1, 1); CP_COMMIT();

    for (int c = 0; c < NC; ++c) {
        CP_WAIT1();
        __syncthreads();
        uint32_t st = sb + (c & 1) * MG_STAGE_B;
#pragma unroll
        for (int ks = 0; ks < 2; ++ks) {
            uint32_t ah[2][4], al[2][4], bh[4][4], bl[4][4];
#pragma unroll
            for (int mt = 0; mt < 2; ++mt) {
                uint32_t p = st + aoff + mt * (16 * 80) + ks * 32;
                LDSM4(ah[mt], p + 0 * MG_TILE_B);
                LDSM4(al[mt], p + 1 * MG_TILE_B);
            }
#pragma unroll
            for (int g = 0; g < 4; ++g) {
                uint32_t p = st + boff + g * (16 * 80) + ks * 32;
                LDSM4(bh[g], p + 2 * MG_TILE_B);
                LDSM4(bl[g], p + 3 * MG_TILE_B);
            }
#pragma unroll
            for (int mt = 0; mt < 2; ++mt)
#pragma unroll
                for (int g = 0; g < 4; ++g)
#pragma unroll
                    for (int h = 0; h < 2; ++h) {
                        float* d = acc[mt][g * 2 + h];
                        mma_bf16(d, ah[mt], &bh[g][h * 2]);
                        mma_bf16(d, ah[mt], &bl[g][h * 2]);
                        mma_bf16(d, al[mt], &bh[g][h * 2]);
                    }
        }
        __syncthreads();
        if (c + 2 < NC) load_chunk(c + 2, c & 1);
        CP_COMMIT();
    }

    // epilogue
    const int g = lane >> 2, t4 = lane & 3;
#pragma unroll
    for (int mt = 0; mt < 2; ++mt) {
#pragma unroll
        for (int nt = 0; nt < 8; ++nt) {
            float* a = acc[mt][nt];
            int row = m0 + wm * 32 + mt * 16 + g;
            int col = n0 + wn * 64 + nt * 8 + 2 * t4;
            float b0 = bias[col], b1 = bias[col + 1];
            if (act == 0) {
                float2 u0; u0.x = a[0] + b0; u0.y = a[1] + b1;
                float2 u1; u1.x = a[2] + b0; u1.y = a[3] + b1;
                *(float2*)(outF + (size_t)row * N + col)       = u0;
                *(float2*)(outF + (size_t)(row + 8) * N + col) = u1;
            } else {
                float v0 = gelu_t(a[0] + b0), v1 = gelu_t(a[1] + b1);
                float v2 = gelu_t(a[2] + b0), v3 = gelu_t(a[3] + b1);
                __nv_bfloat16 h0, l0, h1, l1, h2, l2, h3, l3;
                split_bf16(v0, h0, l0); split_bf16(v1, h1, l1);
                split_bf16(v2, h2, l2); split_bf16(v3, h3, l3);
                __nv_bfloat162 p;
                p.x = h0; p.y = h1; *(__nv_bfloat162*)(outH + (size_t)row * N + col) = p;
                p.x = l0; p.y = l1; *(__nv_bfloat162*)(outL + (size_t)row * N + col) = p;
                p.x = h2; p.y = h3; *(__nv_bfloat162*)(outH + (size_t)(row + 8) * N + col) = p;
                p.x = l2; p.y = l3; *(__nv_bfloat162*)(outL + (size_t)(row + 8) * N + col) = p;
            }
        }
    }
}

// ----------------------------------------------------------------- RMSNorm + RoPE
__global__ __launch_bounds__(256) void rmsrope_kernel(
    float* __restrict__ Qm, float* __restrict__ Km,
    const float* __restrict__ nq, const float* __restrict__ nk,
    const float* __restrict__ cos_h, const float* __restrict__ sin_h,
    const float* __restrict__ cos_r, const float* __restrict__ sin_r)
{
    int row = blockIdx.x, tid = threadIdx.x;
    float* x = (blockIdx.y ? Km : Qm) + (size_t)row * C_DIM;
    const float* nw = blockIdx.y ? nk : nq;
    int isr = row >= C_SEQ;
    int pos = isr ? row - C_SEQ : row;
    const float* cp = (isr ? cos_r : cos_h) + (size_t)pos * 128;
    const float* sp = (isr ? sin_r : sin_h) + (size_t)pos * 128;
    float4 v0 = *(const float4*)(x + tid * 8);
    float4 v1 = *(const float4*)(x + tid * 8 + 4);
    float xv[8] = {v0.x, v0.y, v0.z, v0.w, v1.x, v1.y, v1.z, v1.w};
    float ss = 0.f;
#pragma unroll
    for (int e = 0; e < 8; ++e) ss += xv[e] * xv[e];
#pragma unroll
    for (int o = 16; o > 0; o >>= 1) ss += __shfl_xor_sync(0xffffffffu, ss, o);
    __shared__ float rss[8];
    if ((tid & 31) == 0) rss[tid >> 5] = ss;
    __syncthreads();
    float tot = 0.f;
#pragma unroll
    for (int w = 0; w < 8; ++w) tot += rss[w];
    float rstd = rsqrtf(tot * (1.f / 2048.f) + 1e-6f);
    float out[8];
#pragma unroll
    for (int p = 0; p < 4; ++p) {
        int ce = tid * 8 + 2 * p;
        int de = ce & 127;
        float x1 = xv[2 * p]     * rstd * nw[ce];
        float x2 = xv[2 * p + 1] * rstd * nw[ce + 1];
        float cv = cp[de], sv = sp[de + 1];
        out[2 * p]     = x1 * cv - x2 * sv;
        out[2 * p + 1] = x1 * sv + x2 * cv;
    }
    *(float4*)(x + tid * 8)     = make_float4(out[0], out[1], out[2], out[3]);
    *(float4*)(x + tid * 8 + 4) = make_float4(out[4], out[5], out[6], out[7]);
}

// ----------------------------------------------------------------- attention
__device__ __forceinline__ int combined_row(int fi, int j) {
    int hi = j / 48;
    int wi = j - hi * 48;
    int base = (wi < 24) ? 0 : C_SEQ;
    int ww   = (wi < 24) ? wi : wi - 24;
    return base + fi * 576 + hi * 24 + ww;
}

#define AT_STR 65
#define ATTN_SMEM ((128 * AT_STR * 2 + 64 * 128 + 64 * 66 + 192) * 4)

__global__ __launch_bounds__(256) void attn_kernel(
    const float* __restrict__ Q, const float* __restrict__ K,
    const float* __restrict__ V, float* __restrict__ O)
{
    extern __shared__ float smf[];
    float* Qt   = smf;
    float* Kt   = Qt + 128 * AT_STR;
    float* Vs   = Kt + 128 * AT_STR;
    float* Sb   = Vs + 64 * 128;
    float* mrow = Sb + 64 * 66;
    float* lrow = mrow + 64;
    float* arow = lrow + 64;

    const int tid  = threadIdx.x;
    const int fi   = blockIdx.y >> 4;
    const int coloff = (blockIdx.y & 15) * 128;
    const int q0   = blockIdx.x * 64;
    const int ty   = tid >> 4, tx = tid & 15;
    const int r0   = ty * 4, c0 = tx * 4, cv0 = tx * 8;

#pragma unroll
    for (int it = 0; it < 8; ++it) {
        int idx = tid + it * 256;
        int rr = idx >> 5, d0 = (idx & 31) << 2;
        int grow = combined_row(fi, q0 + rr);
        float4 qv = *(const float4*)&Q[(size_t)grow * C_DIM + coloff + d0];
        Qt[(d0 + 0) * AT_STR + rr] = qv.x * C_SCALE;
        Qt[(d0 + 1) * AT_STR + rr] = qv.y * C_SCALE;
        Qt[(d0 + 2) * AT_STR + rr] = qv.z * C_SCALE;
        Qt[(d0 + 3) * AT_STR + rr] = qv.w * C_SCALE;
    }
    if (tid < 64) { mrow[tid] = -1e30f; lrow[tid] = 0.f; }

    float acc[4][8];
#pragma unroll
    for (int i = 0; i < 4; ++i)
#pragma unroll
        for (int j = 0; j < 8; ++j) acc[i][j] = 0.f;

    for (int kc = 0; kc < 18; ++kc) {
        int k0 = kc * 64;
        __syncthreads();
#pragma unroll
        for (int it = 0; it < 8; ++it) {
            int idx = tid + it * 256;
            int rr = idx >> 5, d0 = (idx & 31) << 2;
            int grow = combined_row(fi, k0 + rr);
            float4 kv = *(const float4*)&K[(size_t)grow * C_DIM + coloff + d0];
            Kt[(d0 + 0) * AT_STR + rr] = kv.x;
            Kt[(d0 + 1) * AT_STR + rr] = kv.y;
            Kt[(d0 + 2) * AT_STR + rr] = kv.z;
            Kt[(d0 + 3) * AT_STR + rr] = kv.w;
        }
#pragma unroll
        for (int it = 0; it < 8; ++it) {
            int idx = tid + it * 256;
            int rr = idx >> 5, c4 = (idx & 31) << 2;
            int grow = combined_row(fi, k0 + rr);
            *(float4*)&Vs[rr * 128 + c4] =
                *(const float4*)&V[(size_t)grow * C_DIM + coloff + c4];
        }
        __syncthreads();

        float s[4][4];
#pragma unroll
        for (int i = 0; i < 4; ++i)
#pragma unroll
            for (int j = 0; j < 4; ++j) s[i][j] = 0.f;
        for (int d = 0; d < 128; ++d) {
            const float* qr = &Qt[d * AT_STR + r0];
            const float* kr = &Kt[d * AT_STR + c0];
            float qa = qr[0], qb = qr[1], qc = qr[2], qd = qr[3];
            float ka = kr[0], kb = kr[1], kcv = kr[2], kd = kr[3];
            s[0][0] += qa * ka; s[0][1] += qa * kb; s[0][2] += qa * kcv; s[0][3] += qa * kd;
            s[1][0] += qb * ka; s[1][1] += qb * kb; s[1][2] += qb * kcv; s[1][3] += qb * kd;
            s[2][0] += qc * ka; s[2][1] += qc * kb; s[2][2] += qc * kcv; s[2][3] += qc * kd;
            s[3][0] += qd * ka; s[3][1] += qd * kb; s[3][2] += qd * kcv; s[3][3] += qd * kd;
        }
#pragma unroll
        for (int i = 0; i < 4; ++i)
#pragma unroll
            for (int j = 0; j < 4; ++j)
                Sb[(r0 + i) * 66 + c0 + j] = s[i][j];
        __syncthreads();

        if (tid < 64) {
            float m = mrow[tid];
            float mx = m;
            float* sr = &Sb[tid * 66];
#pragma unroll 8
            for (int cc = 0; cc < 64; ++cc) mx = fmaxf(mx, sr[cc]);
            float fac = __expf(m - mx);
            float l = lrow[tid] * fac;
#pragma unroll 8
            for (int cc = 0; cc < 64; ++cc) {
                float e = __expf(sr[cc] - mx);
                sr[cc] = e;
                l += e;
            }
            mrow[tid] = mx; lrow[tid] = l; arow[tid] = fac;
        }
        __syncthreads();

        float f0 = arow[r0], f1 = arow[r0 + 1], f2 = arow[r0 + 2], f3 = arow[r0 + 3];
#pragma unroll
        for (int j = 0; j < 8; ++j) {
            acc[0][j] *= f0; acc[1][j] *= f1; acc[2][j] *= f2; acc[3][j] *= f3;
        }
        for (int cc = 0; cc < 64; ++cc) {
            float p0 = Sb[(r0 + 0) * 66 + cc];
            float p1 = Sb[(r0 + 1) * 66 + cc];
            float p2 = Sb[(r0 + 2) * 66 + cc];
            float p3 = Sb[(r0 + 3) * 66 + cc];
            float4 va = *(const float4*)&Vs[cc * 128 + cv0];
            float4 vb = *(const float4*)&Vs[cc * 128 + cv0 + 4];
            float vv[8] = {va.x, va.y, va.z, va.w, vb.x, vb.y, vb.z, vb.w};
#pragma unroll
            for (int j = 0; j < 8; ++j) {
                acc[0][j] += p0 * vv[j];
                acc[1][j] += p1 * vv[j];
                acc[2][j] += p2 * vv[j];
                acc[3][j] += p3 * vv[j];
            }
        }
    }
    __syncthreads();
#pragma unroll
    for (int i = 0; i < 4; ++i) {
        float inv = 1.f / lrow[r0 + i];
        int grow = combined_row(fi, q0 + r0 + i);
        float* op = &O[(size_t)grow * C_DIM + coloff + cv0];
        *(float4*)op       = make_float4(acc[i][0] * inv, acc[i][1] * inv,
                                         acc[i][2] * inv, acc[i][3] * inv);
        *(float4*)(op + 4) = make_float4(acc[i][4] * inv, acc[i][5] * inv,
                                         acc[i][6] * inv, acc[i][7] * inv);
    }
}

// ----------------------------------------------------------------- residual gate
__global__ __launch_bounds__(256) void resid_kernel(
    float* __restrict__ st, const float* __restrict__ x, const float* __restrict__ t)
{
    size_t base = (size_t)blockIdx.x * C_DIM + threadIdx.x * 8;
    const float* g = t + 4096 + threadIdx.x * 8;
    float4 s0 = *(float4*)&st[base],      s1 = *(float4*)&st[base + 4];
    float4 x0 = *(const float4*)&x[base], x1 = *(const float4*)&x[base + 4];
    float4 g0 = *(const float4*)&g[0],    g1 = *(const float4*)&g[4];
    s0.x += g0.x * x0.x; s0.y += g0.y * x0.y; s0.z += g0.z * x0.z; s0.w += g0.w * x0.w;
    s1.x += g1.x * x1.x; s1.y += g1.y * x1.y; s1.z += g1.z * x1.z; s1.w += g1.w * x1.w;
    *(float4*)&st[base]     = s0;
    *(float4*)&st[base + 4] = s1;
}

// ----------------------------------------------------------------- launch
extern "C" void kernel_launch(void* const* d_in, const int* in_sizes, int n_in,
                              void* d_out, int out_size)
{
    const float* temb  = (const float*)d_in[2];
    const float* cos_h = (const float*)d_in[3];
    const float* sin_h = (const float*)d_in[4];
    const float* cos_r = (const float*)d_in[5];
    const float* sin_r = (const float*)d_in[6];
    const float* l1lw = (const float*)d_in[7],  *l1lb = (const float*)d_in[8];
    const float* l1nw = (const float*)d_in[9],  *l1nb = (const float*)d_in[10];
    const float* l2lw = (const float*)d_in[11], *l2lb = (const float*)d_in[12];
    const float* l2nw = (const float*)d_in[13], *l2nb = (const float*)d_in[14];
    const float* wq = (const float*)d_in[15], *bq = (const float*)d_in[16];
    const float* wk = (const float*)d_in[17], *bk = (const float*)d_in[18];
    const float* wv = (const float*)d_in[19], *bv = (const float*)d_in[20];
    const float* nqw = (const float*)d_in[21], *nkw = (const float*)d_in[22];
    const float* wo = (const float*)d_in[23], *bo = (const float*)d_in[24];
    const float* fw1 = (const float*)d_in[25], *fb1 = (const float*)d_in[26];
    const float* fw2 = (const float*)d_in[27], *fb2 = (const float*)d_in[28];
    float* st = (float*)d_out;

    float *t1, *t2, *q, *k, *v, *ao, *tp;
    __nv_bfloat16 *nrmH, *nrmL, *aoH, *aoL, *midH, *midL;
    __nv_bfloat16 *wqH, *wqL, *wkH, *wkL, *wvH, *wvL, *woH, *woL, *f1H, *f1L, *f2H, *f2L;
    cudaGetSymbolAddress((void**)&t1,  g_t1);
    cudaGetSymbolAddress((void**)&t2,  g_t2);
    cudaGetSymbolAddress((void**)&q,   g_q);
    cudaGetSymbolAddress((void**)&k,   g_k);
    cudaGetSymbolAddress((void**)&v,   g_v);
    cudaGetSymbolAddress((void**)&ao,  g_ao);
    cudaGetSymbolAddress((void**)&tp,  g_tp);
    cudaGetSymbolAddress((void**)&nrmH, g_nrmH);
    cudaGetSymbolAddress((void**)&nrmL, g_nrmL);
    cudaGetSymbolAddress((void**)&aoH,  g_aoH);
    cudaGetSymbolAddress((void**)&aoL,  g_aoL);
    cudaGetSymbolAddress((void**)&midH, g_midH);
    cudaGetSymbolAddress((void**)&midL, g_midL);
    cudaGetSymbolAddress((void**)&wqH, g_wqH); cudaGetSymbolAddress((void**)&wqL, g_wqL);
    cudaGetSymbolAddress((void**)&wkH, g_wkH); cudaGetSymbolAddress((void**)&wkL, g_wkL);
    cudaGetSymbolAddress((void**)&wvH, g_wvH); cudaGetSymbolAddress((void**)&wvL, g_wvL);
    cudaGetSymbolAddress((void**)&woH, g_woH); cudaGetSymbolAddress((void**)&woL, g_woL);
    cudaGetSymbolAddress((void**)&f1H, g_f1H); cudaGetSymbolAddress((void**)&f1L, g_f1L);
    cudaGetSymbolAddress((void**)&f2H, g_f2H); cudaGetSymbolAddress((void**)&f2L, g_f2L);

    size_t half = (size_t)C_SEQ * C_DIM * sizeof(float);
    cudaMemcpyAsync(st, d_in[0], half, cudaMemcpyDeviceToDevice, 0);
    cudaMemcpyAsync(st + (size_t)C_SEQ * C_DIM, d_in[1], half, cudaMemcpyDeviceToDevice, 0);

    cudaFuncSetAttribute(attn_kernel, cudaFuncAttributeMaxDynamicSharedMemorySize, ATTN_SMEM);
    cudaFuncSetAttribute(mma_gemm,    cudaFuncAttributeMaxDynamicSharedMemorySize, MG_SMEM);

    // weight prep
    wsplit_kernel<<<dim3(64, 64),   256>>>(wq,  wqH, wqL, C_DIM, C_DIM);
    wsplit_kernel<<<dim3(64, 64),   256>>>(wk,  wkH, wkL, C_DIM, C_DIM);
    wsplit_kernel<<<dim3(64, 64),   256>>>(wv,  wvH, wvL, C_DIM, C_DIM);
    wsplit_kernel<<<dim3(64, 64),   256>>>(wo,  woH, woL, C_DIM, C_DIM);
    wsplit_kernel<<<dim3(256, 64),  256>>>(fw1, f1H, f1L, C_DIM, C_FFN);
    wsplit_kernel<<<dim3(64, 256),  256>>>(fw2, f2H, f2L, C_FFN, C_DIM);

    temb_kernel<<<dim3(24, 2), 256>>>(temb, l1lw, l1lb, l2lw, l2lb, t1, t2);
    ln_mod_kernel<<<C_ROWS, 256>>>(st, t1, l1nw, l1nb, nrmH, nrmL);
    mma_gemm<<<dim3(16, 36), 256, MG_SMEM>>>(nrmH, nrmL, wqH, wqL, bq, q, 0, 0, C_DIM, C_DIM, 0);
    mma_gemm<<<dim3(16, 36), 256, MG_SMEM>>>(nrmH, nrmL, wkH, wkL, bk, k, 0, 0, C_DIM, C_DIM, 0);
    mma_gemm<<<dim3(16, 36), 256, MG_SMEM>>>(nrmH, nrmL, wvH, wvL, bv, v, 0, 0, C_DIM, C_DIM, 0);
    rmsrope_kernel<<<dim3(C_ROWS, 2), 256>>>(q, k, nqw, nkw, cos_h, sin_h, cos_r, sin_r);
    attn_kernel<<<dim3(18, 64), 256, ATTN_SMEM>>>(q, k, v, ao);
    split_kernel<<<(C_ROWS * C_DIM) / 1024, 256>>>(ao, aoH, aoL);
    mma_gemm<<<dim3(16, 36), 256, MG_SMEM>>>(aoH, aoL, woH, woL, bo, tp, 0, 0, C_DIM, C_DIM, 0);
    resid_kernel<<<C_ROWS, 256>>>(st, tp, t1);
    ln_mod_kernel<<<C_ROWS, 256>>>(st, t2, l2nw, l2nb, nrmH, nrmL);
    mma_gemm<<<dim3(64, 36), 256, MG_SMEM>>>(nrmH, nrmL, f1H, f1L, fb1, 0, midH, midL, C_FFN, C_DIM, 1);
    mma_gemm<<<dim3(16, 36), 256, MG_SMEM>>>(midH, midL, f2H, f2L, fb2, tp, 0, 0, C_DIM, C_FFN, 0);
    resid_kernel<<<C_ROWS, 256>>>(st, tp, t2);
}

// round 11
// speedup vs baseline: 2.5769x; 1.2547x over previous
#include <cuda_runtime.h>
#include <cuda_bf16.h>
#include <cstdint>
#include <cstddef>

#define C_SEQ   2304
#define C_DIM   2048
#define C_ROWS  4608
#define C_FFN   8192
#define C_SCALE 0.08838834764831845f   // 1/sqrt(128)

// ----------------------------------------------------------------- scratch
__device__ float g_t1[6144];
__device__ float g_t2[6144];
__device__ __nv_bfloat16 g_nrmH[(size_t)C_ROWS * C_DIM];
__device__ __nv_bfloat16 g_nrmL[(size_t)C_ROWS * C_DIM];
__device__ float g_q [(size_t)C_ROWS * C_DIM];
__device__ float g_k [(size_t)C_ROWS * C_DIM];
__device__ float g_tp[(size_t)C_ROWS * C_DIM];
__device__ __nv_bfloat16 g_qH[(size_t)C_ROWS * C_DIM];
__device__ __nv_bfloat16 g_qL[(size_t)C_ROWS * C_DIM];
__device__ __nv_bfloat16 g_kH[(size_t)C_ROWS * C_DIM];
__device__ __nv_bfloat16 g_kL[(size_t)C_ROWS * C_DIM];
__device__ __nv_bfloat16 g_vH[(size_t)C_ROWS * C_DIM];
__device__ __nv_bfloat16 g_vL[(size_t)C_ROWS * C_DIM];
__device__ __nv_bfloat16 g_aoH[(size_t)C_ROWS * C_DIM];
__device__ __nv_bfloat16 g_aoL[(size_t)C_ROWS * C_DIM];
__device__ __nv_bfloat16 g_midH[(size_t)C_ROWS * C_FFN];
__device__ __nv_bfloat16 g_midL[(size_t)C_ROWS * C_FFN];
// transposed+split weights: [N, K] bf16 hi/lo
__device__ __nv_bfloat16 g_wqH[(size_t)C_DIM * C_DIM];
__device__ __nv_bfloat16 g_wqL[(size_t)C_DIM * C_DIM];
__device__ __nv_bfloat16 g_wkH[(size_t)C_DIM * C_DIM];
__device__ __nv_bfloat16 g_wkL[(size_t)C_DIM * C_DIM];
__device__ __nv_bfloat16 g_wvH[(size_t)C_DIM * C_DIM];
__device__ __nv_bfloat16 g_wvL[(size_t)C_DIM * C_DIM];
__device__ __nv_bfloat16 g_woH[(size_t)C_DIM * C_DIM];
__device__ __nv_bfloat16 g_woL[(size_t)C_DIM * C_DIM];
__device__ __nv_bfloat16 g_f1H[(size_t)C_FFN * C_DIM];
__device__ __nv_bfloat16 g_f1L[(size_t)C_FFN * C_DIM];
__device__ __nv_bfloat16 g_f2H[(size_t)C_DIM * C_FFN];
__device__ __nv_bfloat16 g_f2L[(size_t)C_DIM * C_FFN];

// ----------------------------------------------------------------- helpers
__device__ __forceinline__ uint32_t smem_u32(const void* p) {
    uint32_t a;
    asm("{ .reg .u64 t; cvta.to.shared.u64 t, %1; cvt.u32.u64 %0, t; }" : "=r"(a) : "l"(p));
    return a;
}
#define CP16(dst, src) \
    asm volatile("cp.async.cg.shared.global [%0], [%1], 16;" :: "r"(dst), "l"(src) : "memory")
#define CP_COMMIT() asm volatile("cp.async.commit_group;" ::: "memory")
#define CP_WAIT1()  asm volatile("cp.async.wait_group 1;" ::: "memory")
#define LDSM4(r, p) \
    asm volatile("ldmatrix.sync.aligned.m8n8.x4.shared.b16 {%0,%1,%2,%3}, [%4];" \
        : "=r"((r)[0]), "=r"((r)[1]), "=r"((r)[2]), "=r"((r)[3]) : "r"(p))
#define LDSM4T(r, p) \
    asm volatile("ldmatrix.sync.aligned.m8n8.x4.trans.shared.b16 {%0,%1,%2,%3}, [%4];" \
        : "=r"((r)[0]), "=r"((r)[1]), "=r"((r)[2]), "=r"((r)[3]) : "r"(p))

__device__ __forceinline__ void mma_bf16(float* d, const uint32_t* a, const uint32_t* b) {
    asm volatile("mma.sync.aligned.m16n8k16.row.col.f32.bf16.bf16.f32 "
        "{%0,%1,%2,%3}, {%4,%5,%6,%7}, {%8,%9}, {%0,%1,%2,%3};"
        : "+f"(d[0]), "+f"(d[1]), "+f"(d[2]), "+f"(d[3])
        : "r"(a[0]), "r"(a[1]), "r"(a[2]), "r"(a[3]), "r"(b[0]), "r"(b[1]));
}
__device__ __forceinline__ void split_bf16(float x, __nv_bfloat16& h, __nv_bfloat16& l) {
    h = __float2bfloat16(x);
    l = __float2bfloat16(x - __bfloat162float(h));
}
__device__ __forceinline__ float gelu_t(float x) {
    float x3 = x * x * x;
    return 0.5f * x * (1.f + tanhf(0.7978845608028654f * (x + 0.044715f * x3)));
}

// ----------------------------------------------------------------- temb -> t1/t2
__global__ __launch_bounds__(256) void temb_kernel(
    const float* __restrict__ temb,
    const float* __restrict__ lw1, const float* __restrict__ lb1,
    const float* __restrict__ lw2, const float* __restrict__ lb2,
    float* __restrict__ t1, float* __restrict__ t2)
{
    __shared__ float s[512];
    int tid = threadIdx.x;
    float a = temb[tid], b = temb[tid + 256];
    s[tid]       = a / (1.f + __expf(-a));
    s[tid + 256] = b / (1.f + __expf(-b));
    __syncthreads();
    const float* lw = blockIdx.y ? lw2 : lw1;
    const float* lb = blockIdx.y ? lb2 : lb1;
    float* t        = blockIdx.y ? t2  : t1;
    int j = blockIdx.x * 256 + tid;
    float acc = lb[j];
#pragma unroll 8
    for (int i = 0; i < 512; ++i) acc += s[i] * lw[(size_t)i * 6144 + j];
    t[j] = acc;
}

// ----------------------------------------------------------------- LN + modulation -> bf16 hi/lo
__global__ __launch_bounds__(256) void ln_mod_kernel(
    const float* __restrict__ st, const float* __restrict__ t,
    const float* __restrict__ nw, const float* __restrict__ nb,
    __nv_bfloat16* __restrict__ H, __nv_bfloat16* __restrict__ L)
{
    int row = blockIdx.x, tid = threadIdx.x;
    const float* x = st + (size_t)row * C_DIM;
    float4 v0 = *(const float4*)(x + tid * 8);
    float4 v1 = *(const float4*)(x + tid * 8 + 4);
    float xv[8] = {v0.x, v0.y, v0.z, v0.w, v1.x, v1.y, v1.z, v1.w};
    float s = 0.f, ss = 0.f;
#pragma unroll
    for (int e = 0; e < 8; ++e) { s += xv[e]; ss += xv[e] * xv[e]; }
#pragma unroll
    for (int o = 16; o > 0; o >>= 1) {
        s  += __shfl_xor_sync(0xffffffffu, s, o);
        ss += __shfl_xor_sync(0xffffffffu, ss, o);
    }
    __shared__ float rs[8], rss[8];
    if ((tid & 31) == 0) { rs[tid >> 5] = s; rss[tid >> 5] = ss; }
    __syncthreads();
    float tot = 0.f, tot2 = 0.f;
#pragma unroll
    for (int w = 0; w < 8; ++w) { tot += rs[w]; tot2 += rss[w]; }
    float mu   = tot * (1.f / 2048.f);
    float var  = tot2 * (1.f / 2048.f) - mu * mu;
    float rstd = rsqrtf(var + 1e-5f);
    size_t ob = (size_t)row * C_DIM + tid * 8;
#pragma unroll
    for (int e = 0; e < 8; e += 2) {
        int c = tid * 8 + e;
        float a0 = ((xv[e]   - mu) * rstd * nw[c]   + nb[c])   * (1.f + t[2048 + c])   + t[c];
        float a1 = ((xv[e+1] - mu) * rstd * nw[c+1] + nb[c+1]) * (1.f + t[2048 + c+1]) + t[c+1];
        __nv_bfloat16 h0, l0, h1, l1;
        split_bf16(a0, h0, l0); split_bf16(a1, h1, l1);
        __nv_bfloat162 hp; hp.x = h0; hp.y = h1;
        __nv_bfloat162 lp; lp.x = l0; lp.y = l1;
        *(__nv_bfloat162*)(H + ob + e) = hp;
        *(__nv_bfloat162*)(L + ob + e) = lp;
    }
}

// ----------------------------------------------------------------- weight transpose + split
__global__ __launch_bounds__(256) void wsplit_kernel(
    const float* __restrict__ W, __nv_bfloat16* __restrict__ Th,
    __nv_bfloat16* __restrict__ Tl, int K, int N)
{
    __shared__ float t[32][33];
    int n0 = blockIdx.x * 32, k0 = blockIdx.y * 32;
    int tx = threadIdx.x & 31, ty = threadIdx.x >> 5;
#pragma unroll
    for (int i = 0; i < 4; ++i)
        t[ty * 4 + i][tx] = W[(size_t)(k0 + ty * 4 + i) * N + n0 + tx];
    __syncthreads();
#pragma unroll
    for (int i = 0; i < 4; ++i) {
        int r = ty * 4 + i;
        float x = t[tx][r];
        __nv_bfloat16 h, l; split_bf16(x, h, l);
        size_t o = (size_t)(n0 + r) * K + k0 + tx;
        Th[o] = h; Tl[o] = l;
    }
}

// ----------------------------------------------------------------- mma.sync GEMM (bf16x3)
// D[M,N] = A[M,K] * B[N,K]^T; A/B as bf16 hi/lo, K-contiguous.
// act: 0 = fp32 + bias; 1 = gelu(bias) -> bf16 split; 2 = bias -> bf16 split
#define MG_TILE_B  10240
#define MG_STAGE_B (4 * MG_TILE_B)
#define MG_SMEM    (2 * MG_STAGE_B)

__global__ __launch_bounds__(256) void mma_gemm(
    const __nv_bfloat16* __restrict__ Ah, const __nv_bfloat16* __restrict__ Al,
    const __nv_bfloat16* __restrict__ Bh, const __nv_bfloat16* __restrict__ Bl,
    const float* __restrict__ bias, float* __restrict__ outF,
    __nv_bfloat16* __restrict__ outH, __nv_bfloat16* __restrict__ outL,
    int N, int K, int act)
{
    extern __shared__ char smc[];
    const uint32_t sb = smem_u32(smc);
    const int tid = threadIdx.x, lane = tid & 31, wid = tid >> 5;
    const int wm = wid & 3, wn = wid >> 2;
    const int m0 = blockIdx.y << 7, n0 = blockIdx.x << 7;

    auto load_chunk = [&](int c, int buf) {
        int k0 = c << 5;
        uint32_t st = sb + buf * MG_STAGE_B;
#pragma unroll
        for (int j = 0; j < 2; ++j) {
            int q = tid + j * 256;
            int r = q >> 2, c4 = q & 3;
            uint32_t d = st + r * 80 + c4 * 16;
            size_t ga = (size_t)(m0 + r) * K + k0 + c4 * 8;
            size_t gb = (size_t)(n0 + r) * K + k0 + c4 * 8;
            CP16(d + 0 * MG_TILE_B, Ah + ga);
            CP16(d + 1 * MG_TILE_B, Al + ga);
            CP16(d + 2 * MG_TILE_B, Bh + gb);
            CP16(d + 3 * MG_TILE_B, Bl + gb);
        }
    };

    const int mrow = (lane & 7) + ((lane >> 3) & 1) * 8;
    const int achk = lane >> 4;
    const int nrow = (lane & 7) + (lane >> 4) * 8;
    const int bchk = (lane >> 3) & 1;
    const uint32_t aoff = (uint32_t)(wm * 32 + mrow) * 80 + achk * 16;
    const uint32_t boff = (uint32_t)(wn * 64 + nrow) * 80 + bchk * 16;

    float acc[2][8][4];
#pragma unroll
    for (int i = 0; i < 2; ++i)
#pragma unroll
        for (int j = 0; j < 8; ++j)
#pragma unroll
            for (int e = 0; e < 4; ++e) acc[i][j][e] = 0.f;

    const int NC = K >> 5;
    load_chunk(0, 0); CP_COMMIT();
    load_chunk(1, 1); CP_COMMIT();

    for (int c = 0; c < NC; ++c) {
        CP_WAIT1();
        __syncthreads();
        uint32_t st = sb + (c & 1) * MG_STAGE_B;
#pragma unroll
        for (int ks = 0; ks < 2; ++ks) {
            uint32_t ah[2][4], al[2][4], bh[4][4], bl[4][4];
#pragma unroll
            for (int mt = 0; mt < 2; ++mt) {
                uint32_t p = st + aoff + mt * (16 * 80) + ks * 32;
                LDSM4(ah[mt], p + 0 * MG_TILE_B);
                LDSM4(al[mt], p + 1 * MG_TILE_B);
            }
#pragma unroll
            for (int g = 0; g < 4; ++g) {
                uint32_t p = st + boff + g * (16 * 80) + ks * 32;
                LDSM4(bh[g], p + 2 * MG_TILE_B);
                LDSM4(bl[g], p + 3 * MG_TILE_B);
            }
#pragma unroll
            for (int mt = 0; mt < 2; ++mt)
#pragma unroll
                for (int g = 0; g < 4; ++g)
#pragma unroll
                    for (int h = 0; h < 2; ++h) {
                        float* d = acc[mt][g * 2 + h];
                        mma_bf16(d, ah[mt], &bh[g][h * 2]);
                        mma_bf16(d, ah[mt], &bl[g][h * 2]);
                        mma_bf16(d, al[mt], &bh[g][h * 2]);
                    }
        }
        __syncthreads();
        if (c + 2 < NC) load_chunk(c + 2, c & 1);
        CP_COMMIT();
    }

    const int g = lane >> 2, t4 = lane & 3;
#pragma unroll
    for (int mt = 0; mt < 2; ++mt) {
#pragma unroll
        for (int nt = 0; nt < 8; ++nt) {
            float* a = acc[mt][nt];
            int row = m0 + wm * 32 + mt * 16 + g;
            int col = n0 + wn * 64 + nt * 8 + 2 * t4;
            float b0 = bias[col], b1 = bias[col + 1];
            if (act == 0) {
                float2 u0; u0.x = a[0] + b0; u0.y = a[1] + b1;
                float2 u1; u1.x = a[2] + b0; u1.y = a[3] + b1;
                *(float2*)(outF + (size_t)row * N + col)       = u0;
                *(float2*)(outF + (size_t)(row + 8) * N + col) = u1;
            } else {
                float v0 = a[0] + b0, v1 = a[1] + b1;
                float v2 = a[2] + b0, v3 = a[3] + b1;
                if (act == 1) { v0 = gelu_t(v0); v1 = gelu_t(v1); v2 = gelu_t(v2); v3 = gelu_t(v3); }
                __nv_bfloat16 h0, l0, h1, l1, h2, l2, h3, l3;
                split_bf16(v0, h0, l0); split_bf16(v1, h1, l1);
                split_bf16(v2, h2, l2); split_bf16(v3, h3, l3);
                __nv_bfloat162 p;
                p.x = h0; p.y = h1; *(__nv_bfloat162*)(outH + (size_t)row * N + col) = p;
                p.x = l0; p.y = l1; *(__nv_bfloat162*)(outL + (size_t)row * N + col) = p;
                p.x = h2; p.y = h3; *(__nv_bfloat162*)(outH + (size_t)(row + 8) * N + col) = p;
                p.x = l2; p.y = l3; *(__nv_bfloat162*)(outL + (size_t)(row + 8) * N + col) = p;
            }
        }
    }
}

// ----------------------------------------------------------------- RMSNorm + RoPE -> bf16 hi/lo
__global__ __launch_bounds__(256) void rmsrope_kernel(
    const float* __restrict__ Qf, const float* __restrict__ Kf,
    const float* __restrict__ nq, const float* __restrict__ nk,
    const float* __restrict__ cos_h, const float* __restrict__ sin_h,
    const float* __restrict__ cos_r, const float* __restrict__ sin_r,
    __nv_bfloat16* __restrict__ qH, __nv_bfloat16* __restrict__ qL,
    __nv_bfloat16* __restrict__ kH, __nv_bfloat16* __restrict__ kL)
{
    int row = blockIdx.x, tid = threadIdx.x;
    int isk = blockIdx.y;
    const float* x = (isk ? Kf : Qf) + (size_t)row * C_DIM;
    const float* nw = isk ? nk : nq;
    float oscale = isk ? 1.f : C_SCALE;
    __nv_bfloat16* H = isk ? kH : qH;
    __nv_bfloat16* L = isk ? kL : qL;
    int isr = row >= C_SEQ;
    int pos = isr ? row - C_SEQ : row;
    const float* cp = (isr ? cos_r : cos_h) + (size_t)pos * 128;
    const float* sp = (isr ? sin_r : sin_h) + (size_t)pos * 128;
    float4 v0 = *(const float4*)(x + tid * 8);
    float4 v1 = *(const float4*)(x + tid * 8 + 4);
    float xv[8] = {v0.x, v0.y, v0.z, v0.w, v1.x, v1.y, v1.z, v1.w};
    float ss = 0.f;
#pragma unroll
    for (int e = 0; e < 8; ++e) ss += xv[e] * xv[e];
#pragma unroll
    for (int o = 16; o > 0; o >>= 1) ss += __shfl_xor_sync(0xffffffffu, ss, o);
    __shared__ float rss[8];
    if ((tid & 31) == 0) rss[tid >> 5] = ss;
    __syncthreads();
    float tot = 0.f;
#pragma unroll
    for (int w = 0; w < 8; ++w) tot += rss[w];
    float rstd = rsqrtf(tot * (1.f / 2048.f) + 1e-6f);
    size_t ob = (size_t)row * C_DIM + tid * 8;
#pragma unroll
    for (int p = 0; p < 4; ++p) {
        int ce = tid * 8 + 2 * p;
        int de = ce & 127;
        float x1 = xv[2 * p]     * rstd * nw[ce];
        float x2 = xv[2 * p + 1] * rstd * nw[ce + 1];
        float cv = cp[de], sv = sp[de + 1];
        float e0 = (x1 * cv - x2 * sv) * oscale;
        float e1 = (x1 * sv + x2 * cv) * oscale;
        __nv_bfloat16 h0, l0, h1, l1;
        split_bf16(e0, h0, l0); split_bf16(e1, h1, l1);
        __nv_bfloat162 hp; hp.x = h0; hp.y = h1;
        __nv_bfloat162 lp; lp.x = l0; lp.y = l1;
        *(__nv_bfloat162*)(H + ob + 2 * p) = hp;
        *(__nv_bfloat162*)(L + ob + 2 * p) = lp;
    }
}

// ----------------------------------------------------------------- attention (bf16x3 mma flash)
__device__ __forceinline__ int combined_row(int fi, int j) {
    int hi = j / 48;
    int wi = j - hi * 48;
    int base = (wi < 24) ? 0 : C_SEQ;
    int ww   = (wi < 24) ? wi : wi - 24;
    return base + fi * 576 + hi * 24 + ww;
}

#define AQ_STR 136   // halves per row (128 + 8 pad)
#define AP_STR 72
#define A_TILE  17408                 // 64*136*2 bytes
#define AO_Q    0
#define AO_K(b) (34816 + (b) * 34816) // H at off, L at off+A_TILE
#define AO_V(b) (104448 + (b) * 34816)
#define AO_S    174080                // fp32 [64][66]
#define AO_PH   190976
#define AO_PL   200192
#define AO_M    209408
#define AO_LR   209664
#define AO_A    209920
#define ATTN_SMEM 210176

__global__ __launch_bounds__(256) void attn_kernel(
    const __nv_bfloat16* __restrict__ QhG, const __nv_bfloat16* __restrict__ QlG,
    const __nv_bfloat16* __restrict__ KhG, const __nv_bfloat16* __restrict__ KlG,
    const __nv_bfloat16* __restrict__ VhG, const __nv_bfloat16* __restrict__ VlG,
    __nv_bfloat16* __restrict__ OH, __nv_bfloat16* __restrict__ OL)
{
    extern __shared__ char smc[];
    const uint32_t sb = smem_u32(smc);
    float* Sb   = (float*)(smc + AO_S);
    float* mrow = (float*)(smc + AO_M);
    float* lrow = (float*)(smc + AO_LR);
    float* arow = (float*)(smc + AO_A);

    const int tid  = threadIdx.x, lane = tid & 31, wid = tid >> 5;
    const int wm = wid & 3, wn = wid >> 2;
    const int fi = blockIdx.y >> 4;
    const int coloff = (blockIdx.y & 15) * 128;
    const int q0 = blockIdx.x * 64;

    // ldmatrix lane address components
    const int mrow_a = (lane & 7) + ((lane >> 3) & 1) * 8;
    const int achk   = lane >> 4;          // A: k halves +0/+8
    const int nrow_b = (lane & 7) + (lane >> 4) * 8;
    const int bchk   = (lane >> 3) & 1;
    const int vrow   = mrow_a;             // trans B rows (kv)
    const int vc8    = (lane >> 4) * 8;    // trans B col (d) +0/+8

    // ---- prologue: Q tile + KV chunk 0
#pragma unroll
    for (int i = 0; i < 4; ++i) {
        int c = tid + i * 256;
        int r = c >> 4, ch8 = (c & 15) * 8;
        int grow = combined_row(fi, q0 + r);
        size_t g = (size_t)grow * C_DIM + coloff + ch8;
        uint32_t d = (uint32_t)(r * AQ_STR + ch8) * 2;
        CP16(sb + AO_Q + d, QhG + g);
        CP16(sb + AO_Q + A_TILE + d, QlG + g);
    }
    auto load_kv = [&](int kc, int buf) {
        int k0 = kc * 64;
#pragma unroll
        for (int i = 0; i < 4; ++i) {
            int c = tid + i * 256;
            int r = c >> 4, ch8 = (c & 15) * 8;
            int grow = combined_row(fi, k0 + r);
            size_t g = (size_t)grow * C_DIM + coloff + ch8;
            uint32_t d = (uint32_t)(r * AQ_STR + ch8) * 2;
            CP16(sb + AO_K(buf) + d, KhG + g);
            CP16(sb + AO_K(buf) + A_TILE + d, KlG + g);
            CP16(sb + AO_V(buf) + d, VhG + g);
            CP16(sb + AO_V(buf) + A_TILE + d, VlG + g);
        }
    };
    load_kv(0, 0);
    CP_COMMIT();
    if (tid < 64) { mrow[tid] = -1e30f; lrow[tid] = 0.f; }

    float oacc[8][4];
#pragma unroll
    for (int f = 0; f < 8; ++f)
#pragma unroll
        for (int e = 0; e < 4; ++e) oacc[f][e] = 0.f;

    const uint32_t qoff = (uint32_t)((wm * 16 + mrow_a) * AQ_STR + achk * 8) * 2;
    const uint32_t poff = (uint32_t)((wm * 16 + mrow_a) * AP_STR + achk * 8) * 2;

    for (int kc = 0; kc < 18; ++kc) {
        if (kc + 1 < 18) load_kv(kc + 1, (kc + 1) & 1);
        CP_COMMIT();
        CP_WAIT1();
        __syncthreads();
        const int buf = kc & 1;
        const uint32_t kb = sb + AO_K(buf), vb = sb + AO_V(buf);

        // ---- S = Q K^T (warp tile m16 x n32), bf16x3
        float sacc[4][4];
#pragma unroll
        for (int f = 0; f < 4; ++f)
#pragma unroll
            for (int e = 0; e < 4; ++e) sacc[f][e] = 0.f;
        const uint32_t koff = (uint32_t)((wn * 32 + nrow_b) * AQ_STR + bchk * 8) * 2;
#pragma unroll
        for (int ks = 0; ks < 8; ++ks) {
            uint32_t ah[4], al[4];
            LDSM4(ah, sb + AO_Q + qoff + ks * 32);
            LDSM4(al, sb + AO_Q + A_TILE + qoff + ks * 32);
#pragma unroll
            for (int g2 = 0; g2 < 2; ++g2) {
                uint32_t bh[4], bl[4];
                uint32_t p = koff + g2 * (16 * AQ_STR * 2) + ks * 32;
                LDSM4(bh, kb + p);
                LDSM4(bl, kb + A_TILE + p);
#pragma unroll
                for (int h = 0; h < 2; ++h) {
                    float* d = sacc[g2 * 2 + h];
                    mma_bf16(d, ah, &bh[h * 2]);
                    mma_bf16(d, ah, &bl[h * 2]);
                    mma_bf16(d, al, &bh[h * 2]);
                }
            }
        }
        {
            int r = wm * 16 + (lane >> 2);
#pragma unroll
            for (int f = 0; f < 4; ++f) {
                int cc = wn * 32 + f * 8 + 2 * (lane & 3);
                Sb[r * 66 + cc]           = sacc[f][0];
                Sb[r * 66 + cc + 1]       = sacc[f][1];
                Sb[(r + 8) * 66 + cc]     = sacc[f][2];
                Sb[(r + 8) * 66 + cc + 1] = sacc[f][3];
            }
        }
        __syncthreads();

        // ---- online softmax (row per thread)
        if (tid < 64) {
            float m = mrow[tid];
            float mx = m;
            float* sr = &Sb[tid * 66];
#pragma unroll 8
            for (int cc = 0; cc < 64; ++cc) mx = fmaxf(mx, sr[cc]);
            float fac = __expf(m - mx);
            float l = lrow[tid] * fac;
#pragma unroll 8
            for (int cc = 0; cc < 64; ++cc) {
                float e = __expf(sr[cc] - mx);
                sr[cc] = e;
                l += e;
            }
            mrow[tid] = mx; lrow[tid] = l; arow[tid] = fac;
        }
        __syncthreads();

        // ---- split P to bf16 hi/lo + rescale accumulators
        {
            int pr = tid >> 2, pc0 = (tid & 3) * 16;
            const float* srow = &Sb[pr * 66 + pc0];
            __nv_bfloat16* ph = (__nv_bfloat16*)(smc + AO_PH) + pr * AP_STR + pc0;
            __nv_bfloat16* pl = (__nv_bfloat16*)(smc + AO_PL) + pr * AP_STR + pc0;
#pragma unroll
            for (int j = 0; j < 16; j += 2) {
                __nv_bfloat16 h0, l0, h1, l1;
                split_bf16(srow[j], h0, l0);
                split_bf16(srow[j + 1], h1, l1);
                __nv_bfloat162 hp; hp.x = h0; hp.y = h1;
                __nv_bfloat162 lp; lp.x = l0; lp.y = l1;
                *(__nv_bfloat162*)(ph + j) = hp;
                *(__nv_bfloat162*)(pl + j) = lp;
            }
        }
        {
            float f0 = arow[wm * 16 + (lane >> 2)];
            float f1 = arow[wm * 16 + (lane >> 2) + 8];
#pragma unroll
            for (int f = 0; f < 8; ++f) {
                oacc[f][0] *= f0; oacc[f][1] *= f0;
                oacc[f][2] *= f1; oacc[f][3] *= f1;
            }
        }
        __syncthreads();

        // ---- O += P V (warp tile m16 x n64), bf16x3, V via ldmatrix.trans
#pragma unroll
        for (int ks = 0; ks < 4; ++ks) {
            uint32_t ph[4], pl[4];
            LDSM4(ph, sb + AO_PH - AO_Q + poff + ks * 32);
            LDSM4(pl, sb + AO_PL - AO_Q + poff + ks * 32);
#pragma unroll
            for (int g2 = 0; g2 < 4; ++g2) {
                uint32_t vh[4], vl[4];
                uint32_t p = (uint32_t)((ks * 16 + vrow) * AQ_STR + wn * 64 + g2 * 16 + vc8) * 2;
                LDSM4T(vh, vb + p);
                LDSM4T(vl, vb + A_TILE + p);
#pragma unroll
                for (int h = 0; h < 2; ++h) {
                    float* d = oacc[g2 * 2 + h];
                    mma_bf16(d, ph, &vh[h * 2]);
                    mma_bf16(d, ph, &vl[h * 2]);
                    mma_bf16(d, pl, &vh[h * 2]);
                }
            }
        }
        __syncthreads();
    }

    // ---- epilogue: normalize + split to bf16 hi/lo
    {
        int r1 = wm * 16 + (lane >> 2), r2 = r1 + 8;
        float i1 = 1.f / lrow[r1], i2 = 1.f / lrow[r2];
        int g1 = combined_row(fi, q0 + r1), g2r = combined_row(fi, q0 + r2);
#pragma unroll
        for (int f = 0; f < 8; ++f) {
            int col = coloff + wn * 64 + f * 8 + 2 * (lane & 3);
            float v0 = oacc[f][0] * i1, v1 = oacc[f][1] * i1;
            float v2 = oacc[f][2] * i2, v3 = oacc[f][3] * i2;
            __nv_bfloat16 h0, l0, h1, l1, h2, l2, h3, l3;
            split_bf16(v0, h0, l0); split_bf16(v1, h1, l1);
            split_bf16(v2, h2, l2); split_bf16(v3, h3, l3);
            __nv_bfloat162 p;
            p.x = h0; p.y = h1; *(__nv_bfloat162*)(OH + (size_t)g1 * C_DIM + col) = p;
            p.x = l0; p.y = l1; *(__nv_bfloat162*)(OL + (size_t)g1 * C_DIM + col) = p;
            p.x = h2; p.y = h3; *(__nv_bfloat162*)(OH + (size_t)g2r * C_DIM + col) = p;
            p.x = l2; p.y = l3; *(__nv_bfloat162*)(OL + (size_t)g2r * C_DIM + col) = p;
        }
    }
}

// ----------------------------------------------------------------- residual gate
__global__ __launch_bounds__(256) void resid_kernel(
    float* __restrict__ st, const float* __restrict__ x, const float* __restrict__ t)
{
    size_t base = (size_t)blockIdx.x * C_DIM + threadIdx.x * 8;
    const float* g = t + 4096 + threadIdx.x * 8;
    float4 s0 = *(float4*)&st[base],      s1 = *(float4*)&st[base + 4];
    float4 x0 = *(const float4*)&x[base], x1 = *(const float4*)&x[base + 4];
    float4 g0 = *(const float4*)&g[0],    g1 = *(const float4*)&g[4];
    s0.x += g0.x * x0.x; s0.y += g0.y * x0.y; s0.z += g0.z * x0.z; s0.w += g0.w * x0.w;
    s1.x += g1.x * x1.x; s1.y += g1.y * x1.y; s1.z += g1.z * x1.z; s1.w += g1.w * x1.w;
    *(float4*)&st[base]     = s0;
    *(float4*)&st[base + 4] = s1;
}

// ----------------------------------------------------------------- launch
extern "C" void kernel_launch(void* const* d_in, const int* in_sizes, int n_in,
                              void* d_out, int out_size)
{
    const float* temb  = (const float*)d_in[2];
    const float* cos_h = (const float*)d_in[3];
    const float* sin_h = (const float*)d_in[4];
    const float* cos_r = (const float*)d_in[5];
    const float* sin_r = (const float*)d_in[6];
    const float* l1lw = (const float*)d_in[7],  *l1lb = (const float*)d_in[8];
    const float* l1nw = (const float*)d_in[9],  *l1nb = (const float*)d_in[10];
    const float* l2lw = (const float*)d_in[11], *l2lb = (const float*)d_in[12];
    const float* l2nw = (const float*)d_in[13], *l2nb = (const float*)d_in[14];
    const float* wq = (const float*)d_in[15], *bq = (const float*)d_in[16];
    const float* wk = (const float*)d_in[17], *bk = (const float*)d_in[18];
    const float* wv = (const float*)d_in[19], *bv = (const float*)d_in[20];
    const float* nqw = (const float*)d_in[21], *nkw = (const float*)d_in[22];
    const float* wo = (const float*)d_in[23], *bo = (const float*)d_in[24];
    const float* fw1 = (const float*)d_in[25], *fb1 = (const float*)d_in[26];
    const float* fw2 = (const float*)d_in[27], *fb2 = (const float*)d_in[28];
    float* st = (float*)d_out;

    float *t1, *t2, *q, *k, *tp;
    __nv_bfloat16 *nrmH, *nrmL, *qH, *qL, *kH, *kL, *vH, *vL, *aoH, *aoL, *midH, *midL;
    __nv_bfloat16 *wqH, *wqL, *wkH, *wkL, *wvH, *wvL, *woH, *woL, *f1H, *f1L, *f2H, *f2L;
    cudaGetSymbolAddress((void**)&t1,  g_t1);
    cudaGetSymbolAddress((void**)&t2,  g_t2);
    cudaGetSymbolAddress((void**)&q,   g_q);
    cudaGetSymbolAddress((void**)&k,   g_k);
    cudaGetSymbolAddress((void**)&tp,  g_tp);
    cudaGetSymbolAddress((void**)&nrmH, g_nrmH);
    cudaGetSymbolAddress((void**)&nrmL, g_nrmL);
    cudaGetSymbolAddress((void**)&qH, g_qH); cudaGetSymbolAddress((void**)&qL, g_qL);
    cudaGetSymbolAddress((void**)&kH, g_kH); cudaGetSymbolAddress((void**)&kL, g_kL);
    cudaGetSymbolAddress((void**)&vH, g_vH); cudaGetSymbolAddress((void**)&vL, g_vL);
    cudaGetSymbolAddress((void**)&aoH, g_aoH); cudaGetSymbolAddress((void**)&aoL, g_aoL);
    cudaGetSymbolAddress((void**)&midH, g_midH); cudaGetSymbolAddress((void**)&midL, g_midL);
    cudaGetSymbolAddress((void**)&wqH, g_wqH); cudaGetSymbolAddress((void**)&wqL, g_wqL);
    cudaGetSymbolAddress((void**)&wkH, g_wkH); cudaGetSymbolAddress((void**)&wkL, g_wkL);
    cudaGetSymbolAddress((void**)&wvH, g_wvH); cudaGetSymbolAddress((void**)&wvL, g_wvL);
    cudaGetSymbolAddress((void**)&woH, g_woH); cudaGetSymbolAddress((void**)&woL, g_woL);
    cudaGetSymbolAddress((void**)&f1H, g_f1H); cudaGetSymbolAddress((void**)&f1L, g_f1L);
    cudaGetSymbolAddress((void**)&f2H, g_f2H); cudaGetSymbolAddress((void**)&f2L, g_f2L);

    size_t half = (size_t)C_SEQ * C_DIM * sizeof(float);
    cudaMemcpyAsync(st, d_in[0], half, cudaMemcpyDeviceToDevice, 0);
    cudaMemcpyAsync(st + (size_t)C_SEQ * C_DIM, d_in[1], half, cudaMemcpyDeviceToDevice, 0);

    cudaFuncSetAttribute(attn_kernel, cudaFuncAttributeMaxDynamicSharedMemorySize, ATTN_SMEM);
    cudaFuncSetAttribute(mma_gemm,    cudaFuncAttributeMaxDynamicSharedMemorySize, MG_SMEM);

    wsplit_kernel<<<dim3(64, 64),   256>>>(wq,  wqH, wqL, C_DIM, C_DIM);
    wsplit_kernel<<<dim3(64, 64),   256>>>(wk,  wkH, wkL, C_DIM, C_DIM);
    wsplit_kernel<<<dim3(64, 64),   256>>>(wv,  wvH, wvL, C_DIM, C_DIM);
    wsplit_kernel<<<dim3(64, 64),   256>>>(wo,  woH, woL, C_DIM, C_DIM);
    wsplit_kernel<<<dim3(256, 64),  256>>>(fw1, f1H, f1L, C_DIM, C_FFN);
    wsplit_kernel<<<dim3(64, 256),  256>>>(fw2, f2H, f2L, C_FFN, C_DIM);

    temb_kernel<<<dim3(24, 2), 256>>>(temb, l1lw, l1lb, l2lw, l2lb, t1, t2);
    ln_mod_kernel<<<C_ROWS, 256>>>(st, t1, l1nw, l1nb, nrmH, nrmL);
    mma_gemm<<<dim3(16, 36), 256, MG_SMEM>>>(nrmH, nrmL, wqH, wqL, bq, q, 0, 0, C_DIM, C_DIM, 0);
    mma_gemm<<<dim3(16, 36), 256, MG_SMEM>>>(nrmH, nrmL, wkH, wkL, bk, k, 0, 0, C_DIM, C_DIM, 0);
    mma_gemm<<<dim3(16, 36), 256, MG_SMEM>>>(nrmH, nrmL, wvH, wvL, bv, 0, vH, vL, C_DIM, C_DIM, 2);
    rmsrope_kernel<<<dim3(C_ROWS, 2), 256>>>(q, k, nqw, nkw, cos_h, sin_h, cos_r, sin_r,
                                             qH, qL, kH, kL);
    attn_kernel<<<dim3(18, 64), 256, ATTN_SMEM>>>(qH, qL, kH, kL, vH, vL, aoH, aoL);
    mma_gemm<<<dim3(16, 36), 256, MG_SMEM>>>(aoH, aoL, woH, woL, bo, tp, 0, 0, C_DIM, C_DIM, 0);
    resid_kernel<<<C_ROWS, 256>>>(st, tp, t1);
    ln_mod_kernel<<<C_ROWS, 256>>>(st, t2, l2nw, l2nb, nrmH, nrmL);
    mma_gemm<<<dim3(64, 36), 256, MG_SMEM>>>(nrmH, nrmL, f1H, f1L, fb1, 0, midH, midL, C_FFN, C_DIM, 1);
    mma_gemm<<<dim3(16, 36), 256, MG_SMEM>>>(midH, midL, f2H, f2L, fb2, tp, 0, 0, C_DIM, C_FFN, 0);
    resid_kernel<<<C_ROWS, 256>>>(st, tp, t2);
}

// round 12
// speedup vs baseline: 3.7245x; 1.4453x over previous
#include <cuda_runtime.h>
#include <cuda_fp16.h>
#include <cstdint>
#include <cstddef>

#define C_SEQ   2304
#define C_DIM   2048
#define C_ROWS  4608
#define C_FFN   8192
#define C_SCALE 0.08838834764831845f   // 1/sqrt(128)

// ----------------------------------------------------------------- scratch
__device__ float g_t1[6144];
__device__ float g_t2[6144];
__device__ __half g_nrmH[(size_t)C_ROWS * C_DIM];
__device__ __half g_nrmL[(size_t)C_ROWS * C_DIM];
__device__ float g_q [(size_t)C_ROWS * C_DIM];
__device__ float g_k [(size_t)C_ROWS * C_DIM];
__device__ float g_tp[(size_t)C_ROWS * C_DIM];
__device__ __half g_qH[(size_t)C_ROWS * C_DIM];
__device__ __half g_qL[(size_t)C_ROWS * C_DIM];
__device__ __half g_kH[(size_t)C_ROWS * C_DIM];
__device__ __half g_vH[(size_t)C_ROWS * C_DIM];
__device__ __half g_aoH[(size_t)C_ROWS * C_DIM];
__device__ __half g_aoL[(size_t)C_ROWS * C_DIM];
__device__ __half g_midH[(size_t)C_ROWS * C_FFN];
__device__ __half g_midL[(size_t)C_ROWS * C_FFN];
// transposed fp16 weights: [N, K]
__device__ __half g_wq[(size_t)C_DIM * C_DIM];
__device__ __half g_wk[(size_t)C_DIM * C_DIM];
__device__ __half g_wv[(size_t)C_DIM * C_DIM];
__device__ __half g_wo[(size_t)C_DIM * C_DIM];
__device__ __half g_f1[(size_t)C_FFN * C_DIM];
__device__ __half g_f2[(size_t)C_DIM * C_FFN];

// ----------------------------------------------------------------- helpers
__device__ __forceinline__ uint32_t smem_u32(const void* p) {
    uint32_t a;
    asm("{ .reg .u64 t; cvta.to.shared.u64 t, %1; cvt.u32.u64 %0, t; }" : "=r"(a) : "l"(p));
    return a;
}
#define CP16(dst, src) \
    asm volatile("cp.async.cg.shared.global [%0], [%1], 16;" :: "r"(dst), "l"(src) : "memory")
#define CP_COMMIT() asm volatile("cp.async.commit_group;" ::: "memory")
#define CP_WAIT1()  asm volatile("cp.async.wait_group 1;" ::: "memory")
#define LDSM4(r, p) \
    asm volatile("ldmatrix.sync.aligned.m8n8.x4.shared.b16 {%0,%1,%2,%3}, [%4];" \
        : "=r"((r)[0]), "=r"((r)[1]), "=r"((r)[2]), "=r"((r)[3]) : "r"(p))
#define LDSM4T(r, p) \
    asm volatile("ldmatrix.sync.aligned.m8n8.x4.trans.shared.b16 {%0,%1,%2,%3}, [%4];" \
        : "=r"((r)[0]), "=r"((r)[1]), "=r"((r)[2]), "=r"((r)[3]) : "r"(p))

__device__ __forceinline__ void mma_f16(float* d, const uint32_t* a, const uint32_t* b) {
    asm volatile("mma.sync.aligned.m16n8k16.row.col.f32.f16.f16.f32 "
        "{%0,%1,%2,%3}, {%4,%5,%6,%7}, {%8,%9}, {%0,%1,%2,%3};"
        : "+f"(d[0]), "+f"(d[1]), "+f"(d[2]), "+f"(d[3])
        : "r"(a[0]), "r"(a[1]), "r"(a[2]), "r"(a[3]), "r"(b[0]), "r"(b[1]));
}
__device__ __forceinline__ void split_f16(float x, __half& h, __half& l) {
    h = __float2half(x);
    l = __float2half(x - __half2float(h));
}
__device__ __forceinline__ float gelu_t(float x) {
    float x3 = x * x * x;
    return 0.5f * x * (1.f + tanhf(0.7978845608028654f * (x + 0.044715f * x3)));
}

// ----------------------------------------------------------------- temb -> t1/t2
__global__ __launch_bounds__(256) void temb_kernel(
    const float* __restrict__ temb,
    const float* __restrict__ lw1, const float* __restrict__ lb1,
    const float* __restrict__ lw2, const float* __restrict__ lb2,
    float* __restrict__ t1, float* __restrict__ t2)
{
    __shared__ float s[512];
    int tid = threadIdx.x;
    float a = temb[tid], b = temb[tid + 256];
    s[tid]       = a / (1.f + __expf(-a));
    s[tid + 256] = b / (1.f + __expf(-b));
    __syncthreads();
    const float* lw = blockIdx.y ? lw2 : lw1;
    const float* lb = blockIdx.y ? lb2 : lb1;
    float* t        = blockIdx.y ? t2  : t1;
    int j = blockIdx.x * 256 + tid;
    float acc = lb[j];
#pragma unroll 8
    for (int i = 0; i < 512; ++i) acc += s[i] * lw[(size_t)i * 6144 + j];
    t[j] = acc;
}

// ----------------------------------------------------------------- LN + modulation -> fp16 hi/lo
__global__ __launch_bounds__(256) void ln_mod_kernel(
    const float* __restrict__ st, const float* __restrict__ t,
    const float* __restrict__ nw, const float* __restrict__ nb,
    __half* __restrict__ H, __half* __restrict__ L)
{
    int row = blockIdx.x, tid = threadIdx.x;
    const float* x = st + (size_t)row * C_DIM;
    float4 v0 = *(const float4*)(x + tid * 8);
    float4 v1 = *(const float4*)(x + tid * 8 + 4);
    float xv[8] = {v0.x, v0.y, v0.z, v0.w, v1.x, v1.y, v1.z, v1.w};
    float s = 0.f, ss = 0.f;
#pragma unroll
    for (int e = 0; e < 8; ++e) { s += xv[e]; ss += xv[e] * xv[e]; }
#pragma unroll
    for (int o = 16; o > 0; o >>= 1) {
        s  += __shfl_xor_sync(0xffffffffu, s, o);
        ss += __shfl_xor_sync(0xffffffffu, ss, o);
    }
    __shared__ float rs[8], rss[8];
    if ((tid & 31) == 0) { rs[tid >> 5] = s; rss[tid >> 5] = ss; }
    __syncthreads();
    float tot = 0.f, tot2 = 0.f;
#pragma unroll
    for (int w = 0; w < 8; ++w) { tot += rs[w]; tot2 += rss[w]; }
    float mu   = tot * (1.f / 2048.f);
    float var  = tot2 * (1.f / 2048.f) - mu * mu;
    float rstd = rsqrtf(var + 1e-5f);
    size_t ob = (size_t)row * C_DIM + tid * 8;
#pragma unroll
    for (int e = 0; e < 8; e += 2) {
        int c = tid * 8 + e;
        float a0 = ((xv[e]   - mu) * rstd * nw[c]   + nb[c])   * (1.f + t[2048 + c])   + t[c];
        float a1 = ((xv[e+1] - mu) * rstd * nw[c+1] + nb[c+1]) * (1.f + t[2048 + c+1]) + t[c+1];
        __half h0, l0, h1, l1;
        split_f16(a0, h0, l0); split_f16(a1, h1, l1);
        __half2 hp; hp.x = h0; hp.y = h1;
        __half2 lp; lp.x = l0; lp.y = l1;
        *(__half2*)(H + ob + e) = hp;
        *(__half2*)(L + ob + e) = lp;
    }
}

// ----------------------------------------------------------------- weight transpose -> fp16
__global__ __launch_bounds__(256) void wconv_kernel(
    const float* __restrict__ W, __half* __restrict__ T, int K, int N)
{
    __shared__ float t[32][33];
    int n0 = blockIdx.x * 32, k0 = blockIdx.y * 32;
    int tx = threadIdx.x & 31, ty = threadIdx.x >> 5;
#pragma unroll
    for (int i = 0; i < 4; ++i)
        t[ty * 4 + i][tx] = W[(size_t)(k0 + ty * 4 + i) * N + n0 + tx];
    __syncthreads();
#pragma unroll
    for (int i = 0; i < 4; ++i) {
        int r = ty * 4 + i;
        T[(size_t)(n0 + r) * K + k0 + tx] = __float2half(t[tx][r]);
    }
}

// ----------------------------------------------------------------- mma.sync GEMM (fp16 A-split x2)
// D[M,N] = A[M,K] * B[N,K]^T; A as fp16 hi/lo, B single fp16, K-contiguous.
// act: 0 = fp32 + bias; 1 = gelu(bias) -> fp16 split; 2 = bias -> single fp16
#define MG_TILE_B  10240
#define MG_STAGE_B (3 * MG_TILE_B)
#define MG_SMEM    (2 * MG_STAGE_B)

__global__ __launch_bounds__(256) void mma_gemm(
    const __half* __restrict__ Ah, const __half* __restrict__ Al,
    const __half* __restrict__ B,
    const float* __restrict__ bias, float* __restrict__ outF,
    __half* __restrict__ outH, __half* __restrict__ outL,
    int N, int K, int act)
{
    extern __shared__ char smc[];
    const uint32_t sb = smem_u32(smc);
    const int tid = threadIdx.x, lane = tid & 31, wid = tid >> 5;
    const int wm = wid & 3, wn = wid >> 2;
    const int m0 = blockIdx.y << 7, n0 = blockIdx.x << 7;

    auto load_chunk = [&](int c, int buf) {
        int k0 = c << 5;
        uint32_t st = sb + buf * MG_STAGE_B;
#pragma unroll
        for (int j = 0; j < 2; ++j) {
            int q = tid + j * 256;
            int r = q >> 2, c4 = q & 3;
            uint32_t d = st + r * 80 + c4 * 16;
            size_t ga = (size_t)(m0 + r) * K + k0 + c4 * 8;
            size_t gb = (size_t)(n0 + r) * K + k0 + c4 * 8;
            CP16(d + 0 * MG_TILE_B, Ah + ga);
            CP16(d + 1 * MG_TILE_B, Al + ga);
            CP16(d + 2 * MG_TILE_B, B  + gb);
        }
    };

    const int mrow = (lane & 7) + ((lane >> 3) & 1) * 8;
    const int achk = lane >> 4;
    const int nrow = (lane & 7) + (lane >> 4) * 8;
    const int bchk = (lane >> 3) & 1;
    const uint32_t aoff = (uint32_t)(wm * 32 + mrow) * 80 + achk * 16;
    const uint32_t boff = (uint32_t)(wn * 64 + nrow) * 80 + bchk * 16;

    float acc[2][8][4];
#pragma unroll
    for (int i = 0; i < 2; ++i)
#pragma unroll
        for (int j = 0; j < 8; ++j)
#pragma unroll
            for (int e = 0; e < 4; ++e) acc[i][j][e] = 0.f;

    const int NC = K >> 5;
    load_chunk(0, 0); CP_COMMIT();
    load_chunk(1, 1); CP_COMMIT();

    for (int c = 0; c < NC; ++c) {
        CP_WAIT1();
        __syncthreads();
        uint32_t st = sb + (c & 1) * MG_STAGE_B;
#pragma unroll
        for (int ks = 0; ks < 2; ++ks) {
            uint32_t ah[2][4], al[2][4], bh[4][4];
#pragma unroll
            for (int mt = 0; mt < 2; ++mt) {
                uint32_t p = st + aoff + mt * (16 * 80) + ks * 32;
                LDSM4(ah[mt], p + 0 * MG_TILE_B);
                LDSM4(al[mt], p + 1 * MG_TILE_B);
            }
#pragma unroll
            for (int g = 0; g < 4; ++g) {
                uint32_t p = st + boff + g * (16 * 80) + ks * 32;
                LDSM4(bh[g], p + 2 * MG_TILE_B);
            }
#pragma unroll
            for (int mt = 0; mt < 2; ++mt)
#pragma unroll
                for (int g = 0; g < 4; ++g)
#pragma unroll
                    for (int h = 0; h < 2; ++h) {
                        float* d = acc[mt][g * 2 + h];
                        mma_f16(d, ah[mt], &bh[g][h * 2]);
                        mma_f16(d, al[mt], &bh[g][h * 2]);
                    }
        }
        __syncthreads();
        if (c + 2 < NC) load_chunk(c + 2, c & 1);
        CP_COMMIT();
    }

    const int g = lane >> 2, t4 = lane & 3;
#pragma unroll
    for (int mt = 0; mt < 2; ++mt) {
#pragma unroll
        for (int nt = 0; nt < 8; ++nt) {
            float* a = acc[mt][nt];
            int row = m0 + wm * 32 + mt * 16 + g;
            int col = n0 + wn * 64 + nt * 8 + 2 * t4;
            float b0 = bias[col], b1 = bias[col + 1];
            float v0 = a[0] + b0, v1 = a[1] + b1;
            float v2 = a[2] + b0, v3 = a[3] + b1;
            if (act == 0) {
                float2 u0; u0.x = v0; u0.y = v1;
                float2 u1; u1.x = v2; u1.y = v3;
                *(float2*)(outF + (size_t)row * N + col)       = u0;
                *(float2*)(outF + (size_t)(row + 8) * N + col) = u1;
            } else if (act == 2) {
                __half2 p;
                p.x = __float2half(v0); p.y = __float2half(v1);
                *(__half2*)(outH + (size_t)row * N + col) = p;
                p.x = __float2half(v2); p.y = __float2half(v3);
                *(__half2*)(outH + (size_t)(row + 8) * N + col) = p;
            } else {
                v0 = gelu_t(v0); v1 = gelu_t(v1); v2 = gelu_t(v2); v3 = gelu_t(v3);
                __half h0, l0, h1, l1, h2, l2, h3, l3;
                split_f16(v0, h0, l0); split_f16(v1, h1, l1);
                split_f16(v2, h2, l2); split_f16(v3, h3, l3);
                __half2 p;
                p.x = h0; p.y = h1; *(__half2*)(outH + (size_t)row * N + col) = p;
                p.x = l0; p.y = l1; *(__half2*)(outL + (size_t)row * N + col) = p;
                p.x = h2; p.y = h3; *(__half2*)(outH + (size_t)(row + 8) * N + col) = p;
                p.x = l2; p.y = l3; *(__half2*)(outL + (size_t)(row + 8) * N + col) = p;
            }
        }
    }
}

// ----------------------------------------------------------------- RMSNorm + RoPE -> fp16
__global__ __launch_bounds__(256) void rmsrope_kernel(
    const float* __restrict__ Qf, const float* __restrict__ Kf,
    const float* __restrict__ nq, const float* __restrict__ nk,
    const float* __restrict__ cos_h, const float* __restrict__ sin_h,
    const float* __restrict__ cos_r, const float* __restrict__ sin_r,
    __half* __restrict__ qH, __half* __restrict__ qL, __half* __restrict__ kH)
{
    int row = blockIdx.x, tid = threadIdx.x;
    int isk = blockIdx.y;
    const float* x = (isk ? Kf : Qf) + (size_t)row * C_DIM;
    const float* nw = isk ? nk : nq;
    float oscale = isk ? 1.f : C_SCALE;
    int isr = row >= C_SEQ;
    int pos = isr ? row - C_SEQ : row;
    const float* cp = (isr ? cos_r : cos_h) + (size_t)pos * 128;
    const float* sp = (isr ? sin_r : sin_h) + (size_t)pos * 128;
    float4 v0 = *(const float4*)(x + tid * 8);
    float4 v1 = *(const float4*)(x + tid * 8 + 4);
    float xv[8] = {v0.x, v0.y, v0.z, v0.w, v1.x, v1.y, v1.z, v1.w};
    float ss = 0.f;
#pragma unroll
    for (int e = 0; e < 8; ++e) ss += xv[e] * xv[e];
#pragma unroll
    for (int o = 16; o > 0; o >>= 1) ss += __shfl_xor_sync(0xffffffffu, ss, o);
    __shared__ float rss[8];
    if ((tid & 31) == 0) rss[tid >> 5] = ss;
    __syncthreads();
    float tot = 0.f;
#pragma unroll
    for (int w = 0; w < 8; ++w) tot += rss[w];
    float rstd = rsqrtf(tot * (1.f / 2048.f) + 1e-6f);
    size_t ob = (size_t)row * C_DIM + tid * 8;
#pragma unroll
    for (int p = 0; p < 4; ++p) {
        int ce = tid * 8 + 2 * p;
        int de = ce & 127;
        float x1 = xv[2 * p]     * rstd * nw[ce];
        float x2 = xv[2 * p + 1] * rstd * nw[ce + 1];
        float cv = cp[de], sv = sp[de + 1];
        float e0 = (x1 * cv - x2 * sv) * oscale;
        float e1 = (x1 * sv + x2 * cv) * oscale;
        if (isk) {
            __half2 hp; hp.x = __float2half(e0); hp.y = __float2half(e1);
            *(__half2*)(kH + ob + 2 * p) = hp;
        } else {
            __half h0, l0, h1, l1;
            split_f16(e0, h0, l0); split_f16(e1, h1, l1);
            __half2 hp; hp.x = h0; hp.y = h1;
            __half2 lp; lp.x = l0; lp.y = l1;
            *(__half2*)(qH + ob + 2 * p) = hp;
            *(__half2*)(qL + ob + 2 * p) = lp;
        }
    }
}

// ----------------------------------------------------------------- attention (fp16 mma flash)
__device__ __forceinline__ int combined_row(int fi, int j) {
    int hi = j / 48;
    int wi = j - hi * 48;
    int base = (wi < 24) ? 0 : C_SEQ;
    int ww   = (wi < 24) ? wi : wi - 24;
    return base + fi * 576 + hi * 24 + ww;
}

#define AQ_STR 136
#define AP_STR 72
#define A_TILE  17408                 // 64*136*2 bytes
#define AO_Q    0                     // Qh ; Ql at +A_TILE
#define AO_K(b) (34816 + (b) * A_TILE)
#define AO_V(b) (69632 + (b) * A_TILE)
#define AO_S    104448                // fp32 [64][66]
#define AO_PH   121344
#define AO_PL   130560
#define AO_M    139776
#define AO_LR   140032
#define AO_A    140288
#define ATTN_SMEM 140544

__global__ __launch_bounds__(256) void attn_kernel(
    const __half* __restrict__ QhG, const __half* __restrict__ QlG,
    const __half* __restrict__ KhG, const __half* __restrict__ VhG,
    __half* __restrict__ OH, __half* __restrict__ OL)
{
    extern __shared__ char smc[];
    const uint32_t sb = smem_u32(smc);
    float* Sb   = (float*)(smc + AO_S);
    float* mrow = (float*)(smc + AO_M);
    float* lrow = (float*)(smc + AO_LR);
    float* arow = (float*)(smc + AO_A);

    const int tid  = threadIdx.x, lane = tid & 31, wid = tid >> 5;
    const int wm = wid & 3, wn = wid >> 2;
    const int fi = blockIdx.y >> 4;
    const int coloff = (blockIdx.y & 15) * 128;
    const int q0 = blockIdx.x * 64;

    const int mrow_a = (lane & 7) + ((lane >> 3) & 1) * 8;
    const int achk   = lane >> 4;
    const int nrow_b = (lane & 7) + (lane >> 4) * 8;
    const int bchk   = (lane >> 3) & 1;
    const int vrow   = mrow_a;
    const int vc8    = (lane >> 4) * 8;

#pragma unroll
    for (int i = 0; i < 4; ++i) {
        int c = tid + i * 256;
        int r = c >> 4, ch8 = (c & 15) * 8;
        int grow = combined_row(fi, q0 + r);
        size_t g = (size_t)grow * C_DIM + coloff + ch8;
        uint32_t d = (uint32_t)(r * AQ_STR + ch8) * 2;
        CP16(sb + AO_Q + d, QhG + g);
        CP16(sb + AO_Q + A_TILE + d, QlG + g);
    }
    auto load_kv = [&](int kc, int buf) {
        int k0 = kc * 64;
#pragma unroll
        for (int i = 0; i < 4; ++i) {
            int c = tid + i * 256;
            int r = c >> 4, ch8 = (c & 15) * 8;
            int grow = combined_row(fi, k0 + r);
            size_t g = (size_t)grow * C_DIM + coloff + ch8;
            uint32_t d = (uint32_t)(r * AQ_STR + ch8) * 2;
            CP16(sb + AO_K(buf) + d, KhG + g);
            CP16(sb + AO_V(buf) + d, VhG + g);
        }
    };
    load_kv(0, 0);
    CP_COMMIT();
    if (tid < 64) { mrow[tid] = -1e30f; lrow[tid] = 0.f; }

    float oacc[8][4];
#pragma unroll
    for (int f = 0; f < 8; ++f)
#pragma unroll
        for (int e = 0; e < 4; ++e) oacc[f][e] = 0.f;

    const uint32_t qoff = (uint32_t)((wm * 16 + mrow_a) * AQ_STR + achk * 8) * 2;
    const uint32_t poff = (uint32_t)((wm * 16 + mrow_a) * AP_STR + achk * 8) * 2;

    for (int kc = 0; kc < 18; ++kc) {
        if (kc + 1 < 18) load_kv(kc + 1, (kc + 1) & 1);
        CP_COMMIT();
        CP_WAIT1();
        __syncthreads();
        const int buf = kc & 1;
        const uint32_t kb = sb + AO_K(buf), vb = sb + AO_V(buf);

        // ---- S = Q K^T
        float sacc[4][4];
#pragma unroll
        for (int f = 0; f < 4; ++f)
#pragma unroll
            for (int e = 0; e < 4; ++e) sacc[f][e] = 0.f;
        const uint32_t koff = (uint32_t)((wn * 32 + nrow_b) * AQ_STR + bchk * 8) * 2;
#pragma unroll
        for (int ks = 0; ks < 8; ++ks) {
            uint32_t ah[4], al[4];
            LDSM4(ah, sb + AO_Q + qoff + ks * 32);
            LDSM4(al, sb + AO_Q + A_TILE + qoff + ks * 32);
#pragma unroll
            for (int g2 = 0; g2 < 2; ++g2) {
                uint32_t bh[4];
                LDSM4(bh, kb + koff + g2 * (16 * AQ_STR * 2) + ks * 32);
#pragma unroll
                for (int h = 0; h < 2; ++h) {
                    float* d = sacc[g2 * 2 + h];
                    mma_f16(d, ah, &bh[h * 2]);
                    mma_f16(d, al, &bh[h * 2]);
                }
            }
        }
        {
            int r = wm * 16 + (lane >> 2);
#pragma unroll
            for (int f = 0; f < 4; ++f) {
                int cc = wn * 32 + f * 8 + 2 * (lane & 3);
                Sb[r * 66 + cc]           = sacc[f][0];
                Sb[r * 66 + cc + 1]       = sacc[f][1];
                Sb[(r + 8) * 66 + cc]     = sacc[f][2];
                Sb[(r + 8) * 66 + cc + 1] = sacc[f][3];
            }
        }
        __syncthreads();

        // ---- online softmax
        if (tid < 64) {
            float m = mrow[tid];
            float mx = m;
            float* sr = &Sb[tid * 66];
#pragma unroll 8
            for (int cc = 0; cc < 64; ++cc) mx = fmaxf(mx, sr[cc]);
            float fac = __expf(m - mx);
            float l = lrow[tid] * fac;
#pragma unroll 8
            for (int cc = 0; cc < 64; ++cc) {
                float e = __expf(sr[cc] - mx);
                sr[cc] = e;
                l += e;
            }
            mrow[tid] = mx; lrow[tid] = l; arow[tid] = fac;
        }
        __syncthreads();

        // ---- split P + rescale accumulators
        {
            int pr = tid >> 2, pc0 = (tid & 3) * 16;
            const float* srow = &Sb[pr * 66 + pc0];
            __half* ph = (__half*)(smc + AO_PH) + pr * AP_STR + pc0;
            __half* pl = (__half*)(smc + AO_PL) + pr * AP_STR + pc0;
#pragma unroll
            for (int j = 0; j < 16; j += 2) {
                __half h0, l0, h1, l1;
                split_f16(srow[j], h0, l0);
                split_f16(srow[j + 1], h1, l1);
                __half2 hp; hp.x = h0; hp.y = h1;
                __half2 lp; lp.x = l0; lp.y = l1;
                *(__half2*)(ph + j) = hp;
                *(__half2*)(pl + j) = lp;
            }
        }
        {
            float f0 = arow[wm * 16 + (lane >> 2)];
            float f1 = arow[wm * 16 + (lane >> 2) + 8];
#pragma unroll
            for (int f = 0; f < 8; ++f) {
                oacc[f][0] *= f0; oacc[f][1] *= f0;
                oacc[f][2] *= f1; oacc[f][3] *= f1;
            }
        }
        __syncthreads();

        // ---- O += P V
#pragma unroll
        for (int ks = 0; ks < 4; ++ks) {
            uint32_t ph[4], pl[4];
            LDSM4(ph, sb + AO_PH + poff + ks * 32);
            LDSM4(pl, sb + AO_PL + poff + ks * 32);
#pragma unroll
            for (int g2 = 0; g2 < 4; ++g2) {
                uint32_t vh[4];
                uint32_t p = (uint32_t)((ks * 16 + vrow) * AQ_STR + wn * 64 + g2 * 16 + vc8) * 2;
                LDSM4T(vh, vb + p);
#pragma unroll
                for (int h = 0; h < 2; ++h) {
                    float* d = oacc[g2 * 2 + h];
                    mma_f16(d, ph, &vh[h * 2]);
                    mma_f16(d, pl, &vh[h * 2]);
                }
            }
        }
        __syncthreads();
    }

    // ---- epilogue
    {
        int r1 = wm * 16 + (lane >> 2), r2 = r1 + 8;
        float i1 = 1.f / lrow[r1], i2 = 1.f / lrow[r2];
        int g1 = combined_row(fi, q0 + r1), g2r = combined_row(fi, q0 + r2);
#pragma unroll
        for (int f = 0; f < 8; ++f) {
            int col = coloff + wn * 64 + f * 8 + 2 * (lane & 3);
            float v0 = oacc[f][0] * i1, v1 = oacc[f][1] * i1;
            float v2 = oacc[f][2] * i2, v3 = oacc[f][3] * i2;
            __half h0, l0, h1, l1, h2, l2, h3, l3;
            split_f16(v0, h0, l0); split_f16(v1, h1, l1);
            split_f16(v2, h2, l2); split_f16(v3, h3, l3);
            __half2 p;
            p.x = h0; p.y = h1; *(__half2*)(OH + (size_t)g1 * C_DIM + col) = p;
            p.x = l0; p.y = l1; *(__half2*)(OL + (size_t)g1 * C_DIM + col) = p;
            p.x = h2; p.y = h3; *(__half2*)(OH + (size_t)g2r * C_DIM + col) = p;
            p.x = l2; p.y = l3; *(__half2*)(OL + (size_t)g2r * C_DIM + col) = p;
        }
    }
}

// ----------------------------------------------------------------- residual gate
__global__ __launch_bounds__(256) void resid_kernel(
    float* __restrict__ st, const float* __restrict__ x, const float* __restrict__ t)
{
    size_t base = (size_t)blockIdx.x * C_DIM + threadIdx.x * 8;
    const float* g = t + 4096 + threadIdx.x * 8;
    float4 s0 = *(float4*)&st[base],      s1 = *(float4*)&st[base + 4];
    float4 x0 = *(const float4*)&x[base], x1 = *(const float4*)&x[base + 4];
    float4 g0 = *(const float4*)&g[0],    g1 = *(const float4*)&g[4];
    s0.x += g0.x * x0.x; s0.y += g0.y * x0.y; s0.z += g0.z * x0.z; s0.w += g0.w * x0.w;
    s1.x += g1.x * x1.x; s1.y += g1.y * x1.y; s1.z += g1.z * x1.z; s1.w += g1.w * x1.w;
    *(float4*)&st[base]     = s0;
    *(float4*)&st[base + 4] = s1;
}

// ----------------------------------------------------------------- launch
extern "C" void kernel_launch(void* const* d_in, const int* in_sizes, int n_in,
                              void* d_out, int out_size)
{
    const float* temb  = (const float*)d_in[2];
    const float* cos_h = (const float*)d_in[3];
    const float* sin_h = (const float*)d_in[4];
    const float* cos_r = (const float*)d_in[5];
    const float* sin_r = (const float*)d_in[6];
    const float* l1lw = (const float*)d_in[7],  *l1lb = (const float*)d_in[8];
    const float* l1nw = (const float*)d_in[9],  *l1nb = (const float*)d_in[10];
    const float* l2lw = (const float*)d_in[11], *l2lb = (const float*)d_in[12];
    const float* l2nw = (const float*)d_in[13], *l2nb = (const float*)d_in[14];
    const float* wq = (const float*)d_in[15], *bq = (const float*)d_in[16];
    const float* wk = (const float*)d_in[17], *bk = (const float*)d_in[18];
    const float* wv = (const float*)d_in[19], *bv = (const float*)d_in[20];
    const float* nqw = (const float*)d_in[21], *nkw = (const float*)d_in[22];
    const float* wo = (const float*)d_in[23], *bo = (const float*)d_in[24];
    const float* fw1 = (const float*)d_in[25], *fb1 = (const float*)d_in[26];
    const float* fw2 = (const float*)d_in[27], *fb2 = (const float*)d_in[28];
    float* st = (float*)d_out;

    float *t1, *t2, *q, *k, *tp;
    __half *nrmH, *nrmL, *qH, *qL, *kH, *vH, *aoH, *aoL, *midH, *midL;
    __half *wqh, *wkh, *wvh, *woh, *f1h, *f2h;
    cudaGetSymbolAddress((void**)&t1,  g_t1);
    cudaGetSymbolAddress((void**)&t2,  g_t2);
    cudaGetSymbolAddress((void**)&q,   g_q);
    cudaGetSymbolAddress((void**)&k,   g_k);
    cudaGetSymbolAddress((void**)&tp,  g_tp);
    cudaGetSymbolAddress((void**)&nrmH, g_nrmH);
    cudaGetSymbolAddress((void**)&nrmL, g_nrmL);
    cudaGetSymbolAddress((void**)&qH, g_qH); cudaGetSymbolAddress((void**)&qL, g_qL);
    cudaGetSymbolAddress((void**)&kH, g_kH);
    cudaGetSymbolAddress((void**)&vH, g_vH);
    cudaGetSymbolAddress((void**)&aoH, g_aoH); cudaGetSymbolAddress((void**)&aoL, g_aoL);
    cudaGetSymbolAddress((void**)&midH, g_midH); cudaGetSymbolAddress((void**)&midL, g_midL);
    cudaGetSymbolAddress((void**)&wqh, g_wq);
    cudaGetSymbolAddress((void**)&wkh, g_wk);
    cudaGetSymbolAddress((void**)&wvh, g_wv);
    cudaGetSymbolAddress((void**)&woh, g_wo);
    cudaGetSymbolAddress((void**)&f1h, g_f1);
    cudaGetSymbolAddress((void**)&f2h, g_f2);

    size_t half_b = (size_t)C_SEQ * C_DIM * sizeof(float);
    cudaMemcpyAsync(st, d_in[0], half_b, cudaMemcpyDeviceToDevice, 0);
    cudaMemcpyAsync(st + (size_t)C_SEQ * C_DIM, d_in[1], half_b, cudaMemcpyDeviceToDevice, 0);

    cudaFuncSetAttribute(attn_kernel, cudaFuncAttributeMaxDynamicSharedMemorySize, ATTN_SMEM);
    cudaFuncSetAttribute(mma_gemm,    cudaFuncAttributeMaxDynamicSharedMemorySize, MG_SMEM);

    wconv_kernel<<<dim3(64, 64),   256>>>(wq,  wqh, C_DIM, C_DIM);
    wconv_kernel<<<dim3(64, 64),   256>>>(wk,  wkh, C_DIM, C_DIM);
    wconv_kernel<<<dim3(64, 64),   256>>>(wv,  wvh, C_DIM, C_DIM);
    wconv_kernel<<<dim3(64, 64),   256>>>(wo,  woh, C_DIM, C_DIM);
    wconv_kernel<<<dim3(256, 64),  256>>>(fw1, f1h, C_DIM, C_FFN);
    wconv_kernel<<<dim3(64, 256),  256>>>(fw2, f2h, C_FFN, C_DIM);

    temb_kernel<<<dim3(24, 2), 256>>>(temb, l1lw, l1lb, l2lw, l2lb, t1, t2);
    ln_mod_kernel<<<C_ROWS, 256>>>(st, t1, l1nw, l1nb, nrmH, nrmL);
    mma_gemm<<<dim3(16, 36), 256, MG_SMEM>>>(nrmH, nrmL, wqh, bq, q, 0, 0, C_DIM, C_DIM, 0);
    mma_gemm<<<dim3(16, 36), 256, MG_SMEM>>>(nrmH, nrmL, wkh, bk, k, 0, 0, C_DIM, C_DIM, 0);
    mma_gemm<<<dim3(16, 36), 256, MG_SMEM>>>(nrmH, nrmL, wvh, bv, 0, vH, 0, C_DIM, C_DIM, 2);
    rmsrope_kernel<<<dim3(C_ROWS, 2), 256>>>(q, k, nqw, nkw, cos_h, sin_h, cos_r, sin_r,
                                             qH, qL, kH);
    attn_kernel<<<dim3(18, 64), 256, ATTN_SMEM>>>(qH, qL, kH, vH, aoH, aoL);
    mma_gemm<<<dim3(16, 36), 256, MG_SMEM>>>(aoH, aoL, woh, bo, tp, 0, 0, C_DIM, C_DIM, 0);
    resid_kernel<<<C_ROWS, 256>>>(st, tp, t1);
    ln_mod_kernel<<<C_ROWS, 256>>>(st, t2, l2nw, l2nb, nrmH, nrmL);
    mma_gemm<<<dim3(64, 36), 256, MG_SMEM>>>(nrmH, nrmL, f1h, fb1, 0, midH, midL, C_FFN, C_DIM, 1);
    mma_gemm<<<dim3(16, 36), 256, MG_SMEM>>>(midH, midL, f2h, fb2, tp, 0, 0, C_DIM, C_FFN, 0);
    resid_kernel<<<C_ROWS, 256>>>(st, tp, t2);
}

// round 13
// speedup vs baseline: 5.7646x; 1.5477x over previous
#include <cuda_runtime.h>
#include <cuda_fp16.h>
#include <cstdint>
#include <cstddef>

#define C_SEQ   2304
#define C_DIM   2048
#define C_ROWS  4608
#define C_FFN   8192
#define C_SCALE 0.08838834764831845f   // 1/sqrt(128)

// ----------------------------------------------------------------- scratch
__device__ float g_t1[6144];
__device__ float g_t2[6144];
__device__ __half g_nrm[(size_t)C_ROWS * C_DIM];
__device__ float g_q [(size_t)C_ROWS * C_DIM];
__device__ float g_k [(size_t)C_ROWS * C_DIM];
__device__ float g_tp[(size_t)C_ROWS * C_DIM];
__device__ __half g_qH[(size_t)C_ROWS * C_DIM];
__device__ __half g_kH[(size_t)C_ROWS * C_DIM];
__device__ __half g_vH[(size_t)C_ROWS * C_DIM];
__device__ __half g_aoH[(size_t)C_ROWS * C_DIM];
__device__ __half g_mid[(size_t)C_ROWS * C_FFN];
// transposed fp16 weights: [N, K]
__device__ __half g_wq[(size_t)C_DIM * C_DIM];
__device__ __half g_wk[(size_t)C_DIM * C_DIM];
__device__ __half g_wv[(size_t)C_DIM * C_DIM];
__device__ __half g_wo[(size_t)C_DIM * C_DIM];
__device__ __half g_f1[(size_t)C_FFN * C_DIM];
__device__ __half g_f2[(size_t)C_DIM * C_FFN];

// ----------------------------------------------------------------- helpers
__device__ __forceinline__ uint32_t smem_u32(const void* p) {
    uint32_t a;
    asm("{ .reg .u64 t; cvta.to.shared.u64 t, %1; cvt.u32.u64 %0, t; }" : "=r"(a) : "l"(p));
    return a;
}
#define CP16(dst, src) \
    asm volatile("cp.async.cg.shared.global [%0], [%1], 16;" :: "r"(dst), "l"(src) : "memory")
#define CP_COMMIT() asm volatile("cp.async.commit_group;" ::: "memory")
#define CP_WAIT1()  asm volatile("cp.async.wait_group 1;" ::: "memory")
#define CP_WAIT2()  asm volatile("cp.async.wait_group 2;" ::: "memory")
#define LDSM4(r, p) \
    asm volatile("ldmatrix.sync.aligned.m8n8.x4.shared.b16 {%0,%1,%2,%3}, [%4];" \
        : "=r"((r)[0]), "=r"((r)[1]), "=r"((r)[2]), "=r"((r)[3]) : "r"(p))
#define LDSM4T(r, p) \
    asm volatile("ldmatrix.sync.aligned.m8n8.x4.trans.shared.b16 {%0,%1,%2,%3}, [%4];" \
        : "=r"((r)[0]), "=r"((r)[1]), "=r"((r)[2]), "=r"((r)[3]) : "r"(p))

__device__ __forceinline__ void mma_f16(float* d, const uint32_t* a, const uint32_t* b) {
    asm volatile("mma.sync.aligned.m16n8k16.row.col.f32.f16.f16.f32 "
        "{%0,%1,%2,%3}, {%4,%5,%6,%7}, {%8,%9}, {%0,%1,%2,%3};"
        : "+f"(d[0]), "+f"(d[1]), "+f"(d[2]), "+f"(d[3])
        : "r"(a[0]), "r"(a[1]), "r"(a[2]), "r"(a[3]), "r"(b[0]), "r"(b[1]));
}
__device__ __forceinline__ float gelu_t(float x) {
    float x3 = x * x * x;
    return 0.5f * x * (1.f + tanhf(0.7978845608028654f * (x + 0.044715f * x3)));
}

// ----------------------------------------------------------------- temb -> t1/t2
__global__ __launch_bounds__(256) void temb_kernel(
    const float* __restrict__ temb,
    const float* __restrict__ lw1, const float* __restrict__ lb1,
    const float* __restrict__ lw2, const float* __restrict__ lb2,
    float* __restrict__ t1, float* __restrict__ t2)
{
    __shared__ float s[512];
    int tid = threadIdx.x;
    float a = temb[tid], b = temb[tid + 256];
    s[tid]       = a / (1.f + __expf(-a));
    s[tid + 256] = b / (1.f + __expf(-b));
    __syncthreads();
    const float* lw = blockIdx.y ? lw2 : lw1;
    const float* lb = blockIdx.y ? lb2 : lb1;
    float* t        = blockIdx.y ? t2  : t1;
    int j = blockIdx.x * 256 + tid;
    float acc = lb[j];
#pragma unroll 8
    for (int i = 0; i < 512; ++i) acc += s[i] * lw[(size_t)i * 6144 + j];
    t[j] = acc;
}

// ----------------------------------------------------------------- LN + modulation -> fp16
__global__ __launch_bounds__(256) void ln_mod_kernel(
    const float* __restrict__ st, const float* __restrict__ t,
    const float* __restrict__ nw, const float* __restrict__ nb,
    __half* __restrict__ H)
{
    int row = blockIdx.x, tid = threadIdx.x;
    const float* x = st + (size_t)row * C_DIM;
    float4 v0 = *(const float4*)(x + tid * 8);
    float4 v1 = *(const float4*)(x + tid * 8 + 4);
    float xv[8] = {v0.x, v0.y, v0.z, v0.w, v1.x, v1.y, v1.z, v1.w};
    float s = 0.f, ss = 0.f;
#pragma unroll
    for (int e = 0; e < 8; ++e) { s += xv[e]; ss += xv[e] * xv[e]; }
#pragma unroll
    for (int o = 16; o > 0; o >>= 1) {
        s  += __shfl_xor_sync(0xffffffffu, s, o);
        ss += __shfl_xor_sync(0xffffffffu, ss, o);
    }
    __shared__ float rs[8], rss[8];
    if ((tid & 31) == 0) { rs[tid >> 5] = s; rss[tid >> 5] = ss; }
    __syncthreads();
    float tot = 0.f, tot2 = 0.f;
#pragma unroll
    for (int w = 0; w < 8; ++w) { tot += rs[w]; tot2 += rss[w]; }
    float mu   = tot * (1.f / 2048.f);
    float var  = tot2 * (1.f / 2048.f) - mu * mu;
    float rstd = rsqrtf(var + 1e-5f);
    size_t ob = (size_t)row * C_DIM + tid * 8;
#pragma unroll
    for (int e = 0; e < 8; e += 2) {
        int c = tid * 8 + e;
        float a0 = ((xv[e]   - mu) * rstd * nw[c]   + nb[c])   * (1.f + t[2048 + c])   + t[c];
        float a1 = ((xv[e+1] - mu) * rstd * nw[c+1] + nb[c+1]) * (1.f + t[2048 + c+1]) + t[c+1];
        __half2 hp; hp.x = __float2half(a0); hp.y = __float2half(a1);
        *(__half2*)(H + ob + e) = hp;
    }
}

// ----------------------------------------------------------------- weight transpose -> fp16
__global__ __launch_bounds__(256) void wconv_kernel(
    const float* __restrict__ W, __half* __restrict__ T, int K, int N)
{
    __shared__ float t[32][33];
    int n0 = blockIdx.x * 32, k0 = blockIdx.y * 32;
    int tx = threadIdx.x & 31, ty = threadIdx.x >> 5;
#pragma unroll
    for (int i = 0; i < 4; ++i)
        t[ty * 4 + i][tx] = W[(size_t)(k0 + ty * 4 + i) * N + n0 + tx];
    __syncthreads();
#pragma unroll
    for (int i = 0; i < 4; ++i) {
        int r = ty * 4 + i;
        T[(size_t)(n0 + r) * K + k0 + tx] = __float2half(t[tx][r]);
    }
}

// ----------------------------------------------------------------- mma.sync HGEMM (fp32 accum)
// D[M,N] = A[M,K] * B[N,K]^T; K-contiguous fp16. act: 0=fp32+bias; 1=gelu->fp16; 2=bias->fp16
#define MG_TILE_B  10240
#define MG_STAGE_B (2 * MG_TILE_B)
#define MG_SMEM    (3 * MG_STAGE_B)

__global__ __launch_bounds__(256) void mma_gemm(
    const __half* __restrict__ A, const __half* __restrict__ B,
    const float* __restrict__ bias, float* __restrict__ outF,
    __half* __restrict__ outH, int N, int K, int act)
{
    extern __shared__ char smc[];
    const uint32_t sb = smem_u32(smc);
    const int tid = threadIdx.x, lane = tid & 31, wid = tid >> 5;
    const int wm = wid & 3, wn = wid >> 2;
    const int m0 = blockIdx.y << 7, n0 = blockIdx.x << 7;

    auto load_chunk = [&](int c, int buf) {
        int k0 = c << 5;
        uint32_t st = sb + buf * MG_STAGE_B;
#pragma unroll
        for (int j = 0; j < 2; ++j) {
            int q = tid + j * 256;
            int r = q >> 2, c4 = q & 3;
            uint32_t d = st + r * 80 + c4 * 16;
            CP16(d,             A + (size_t)(m0 + r) * K + k0 + c4 * 8);
            CP16(d + MG_TILE_B, B + (size_t)(n0 + r) * K + k0 + c4 * 8);
        }
    };

    const int mrow = (lane & 7) + ((lane >> 3) & 1) * 8;
    const int achk = lane >> 4;
    const int nrow = (lane & 7) + (lane >> 4) * 8;
    const int bchk = (lane >> 3) & 1;
    const uint32_t aoff = (uint32_t)(wm * 32 + mrow) * 80 + achk * 16;
    const uint32_t boff = (uint32_t)(wn * 64 + nrow) * 80 + bchk * 16;

    float acc[2][8][4];
#pragma unroll
    for (int i = 0; i < 2; ++i)
#pragma unroll
        for (int j = 0; j < 8; ++j)
#pragma unroll
            for (int e = 0; e < 4; ++e) acc[i][j][e] = 0.f;

    const int NC = K >> 5;
    load_chunk(0, 0); CP_COMMIT();
    load_chunk(1, 1); CP_COMMIT();
    load_chunk(2, 2); CP_COMMIT();

    int buf = 0;
    for (int c = 0; c < NC; ++c) {
        CP_WAIT2();
        __syncthreads();
        uint32_t st = sb + buf * MG_STAGE_B;
#pragma unroll
        for (int ks = 0; ks < 2; ++ks) {
            uint32_t ah[2][4], bh[4][4];
#pragma unroll
            for (int mt = 0; mt < 2; ++mt)
                LDSM4(ah[mt], st + aoff + mt * (16 * 80) + ks * 32);
#pragma unroll
            for (int g = 0; g < 4; ++g)
                LDSM4(bh[g], st + MG_TILE_B + boff + g * (16 * 80) + ks * 32);
#pragma unroll
            for (int mt = 0; mt < 2; ++mt)
#pragma unroll
                for (int g = 0; g < 4; ++g)
#pragma unroll
                    for (int h = 0; h < 2; ++h)
                        mma_f16(acc[mt][g * 2 + h], ah[mt], &bh[g][h * 2]);
        }
        __syncthreads();
        if (c + 3 < NC) load_chunk(c + 3, buf);
        CP_COMMIT();
        buf = (buf == 2) ? 0 : buf + 1;
    }

    const int g = lane >> 2, t4 = lane & 3;
#pragma unroll
    for (int mt = 0; mt < 2; ++mt) {
#pragma unroll
        for (int nt = 0; nt < 8; ++nt) {
            float* a = acc[mt][nt];
            int row = m0 + wm * 32 + mt * 16 + g;
            int col = n0 + wn * 64 + nt * 8 + 2 * t4;
            float b0 = bias[col], b1 = bias[col + 1];
            float v0 = a[0] + b0, v1 = a[1] + b1;
            float v2 = a[2] + b0, v3 = a[3] + b1;
            if (act == 0) {
                float2 u0; u0.x = v0; u0.y = v1;
                float2 u1; u1.x = v2; u1.y = v3;
                *(float2*)(outF + (size_t)row * N + col)       = u0;
                *(float2*)(outF + (size_t)(row + 8) * N + col) = u1;
            } else {
                if (act == 1) { v0 = gelu_t(v0); v1 = gelu_t(v1); v2 = gelu_t(v2); v3 = gelu_t(v3); }
                __half2 p;
                p.x = __float2half(v0); p.y = __float2half(v1);
                *(__half2*)(outH + (size_t)row * N + col) = p;
                p.x = __float2half(v2); p.y = __float2half(v3);
                *(__half2*)(outH + (size_t)(row + 8) * N + col) = p;
            }
        }
    }
}

// ----------------------------------------------------------------- RMSNorm + RoPE -> fp16
__global__ __launch_bounds__(256) void rmsrope_kernel(
    const float* __restrict__ Qf, const float* __restrict__ Kf,
    const float* __restrict__ nq, const float* __restrict__ nk,
    const float* __restrict__ cos_h, const float* __restrict__ sin_h,
    const float* __restrict__ cos_r, const float* __restrict__ sin_r,
    __half* __restrict__ qH, __half* __restrict__ kH)
{
    int row = blockIdx.x, tid = threadIdx.x;
    int isk = blockIdx.y;
    const float* x = (isk ? Kf : Qf) + (size_t)row * C_DIM;
    const float* nw = isk ? nk : nq;
    float oscale = isk ? 1.f : C_SCALE;
    __half* H = isk ? kH : qH;
    int isr = row >= C_SEQ;
    int pos = isr ? row - C_SEQ : row;
    const float* cp = (isr ? cos_r : cos_h) + (size_t)pos * 128;
    const float* sp = (isr ? sin_r : sin_h) + (size_t)pos * 128;
    float4 v0 = *(const float4*)(x + tid * 8);
    float4 v1 = *(const float4*)(x + tid * 8 + 4);
    float xv[8] = {v0.x, v0.y, v0.z, v0.w, v1.x, v1.y, v1.z, v1.w};
    float ss = 0.f;
#pragma unroll
    for (int e = 0; e < 8; ++e) ss += xv[e] * xv[e];
#pragma unroll
    for (int o = 16; o > 0; o >>= 1) ss += __shfl_xor_sync(0xffffffffu, ss, o);
    __shared__ float rss[8];
    if ((tid & 31) == 0) rss[tid >> 5] = ss;
    __syncthreads();
    float tot = 0.f;
#pragma unroll
    for (int w = 0; w < 8; ++w) tot += rss[w];
    float rstd = rsqrtf(tot * (1.f / 2048.f) + 1e-6f);
    size_t ob = (size_t)row * C_DIM + tid * 8;
#pragma unroll
    for (int p = 0; p < 4; ++p) {
        int ce = tid * 8 + 2 * p;
        int de = ce & 127;
        float x1 = xv[2 * p]     * rstd * nw[ce];
        float x2 = xv[2 * p + 1] * rstd * nw[ce + 1];
        float cv = cp[de], sv = sp[de + 1];
        float e0 = (x1 * cv - x2 * sv) * oscale;
        float e1 = (x1 * sv + x2 * cv) * oscale;
        __half2 hp; hp.x = __float2half(e0); hp.y = __float2half(e1);
        *(__half2*)(H + ob + 2 * p) = hp;
    }
}

// ----------------------------------------------------------------- attention (fp16 mma flash)
__device__ __forceinline__ int combined_row(int fi, int j) {
    int hi = j / 48;
    int wi = j - hi * 48;
    int base = (wi < 24) ? 0 : C_SEQ;
    int ww   = (wi < 24) ? wi : wi - 24;
    return base + fi * 576 + hi * 24 + ww;
}

#define AQ_STR 136
#define AP_STR 72
#define A_TILE  17408                 // 64*136*2 bytes
#define AO_Q    0
#define AO_K(b) (17408 + (b) * A_TILE)
#define AO_V(b) (52224 + (b) * A_TILE)
#define AO_S    87040                 // fp32 [64][66]
#define AO_PH   103936                // fp16 [64][72]
#define AO_M    113152
#define AO_LR   113408
#define AO_A    113664
#define ATTN_SMEM 113920

__global__ __launch_bounds__(256) void attn_kernel(
    const __half* __restrict__ QhG, const __half* __restrict__ KhG,
    const __half* __restrict__ VhG, __half* __restrict__ OH)
{
    extern __shared__ char smc[];
    const uint32_t sb = smem_u32(smc);
    float* Sb   = (float*)(smc + AO_S);
    float* mrow = (float*)(smc + AO_M);
    float* lrow = (float*)(smc + AO_LR);
    float* arow = (float*)(smc + AO_A);

    const int tid  = threadIdx.x, lane = tid & 31, wid = tid >> 5;
    const int wm = wid & 3, wn = wid >> 2;
    const int fi = blockIdx.y >> 4;
    const int coloff = (blockIdx.y & 15) * 128;
    const int q0 = blockIdx.x * 64;

    const int mrow_a = (lane & 7) + ((lane >> 3) & 1) * 8;
    const int achk   = lane >> 4;
    const int nrow_b = (lane & 7) + (lane >> 4) * 8;
    const int bchk   = (lane >> 3) & 1;
    const int vrow   = mrow_a;
    const int vc8    = (lane >> 4) * 8;

#pragma unroll
    for (int i = 0; i < 4; ++i) {
        int c = tid + i * 256;
        int r = c >> 4, ch8 = (c & 15) * 8;
        int grow = combined_row(fi, q0 + r);
        uint32_t d = (uint32_t)(r * AQ_STR + ch8) * 2;
        CP16(sb + AO_Q + d, QhG + (size_t)grow * C_DIM + coloff + ch8);
    }
    auto load_kv = [&](int kc, int buf) {
        int k0 = kc * 64;
#pragma unroll
        for (int i = 0; i < 4; ++i) {
            int c = tid + i * 256;
            int r = c >> 4, ch8 = (c & 15) * 8;
            int grow = combined_row(fi, k0 + r);
            size_t g = (size_t)grow * C_DIM + coloff + ch8;
            uint32_t d = (uint32_t)(r * AQ_STR + ch8) * 2;
            CP16(sb + AO_K(buf) + d, KhG + g);
            CP16(sb + AO_V(buf) + d, VhG + g);
        }
    };
    load_kv(0, 0);
    CP_COMMIT();
    if (tid < 64) { mrow[tid] = -1e30f; lrow[tid] = 0.f; }

    float oacc[8][4];
#pragma unroll
    for (int f = 0; f < 8; ++f)
#pragma unroll
        for (int e = 0; e < 4; ++e) oacc[f][e] = 0.f;

    const uint32_t qoff = (uint32_t)((wm * 16 + mrow_a) * AQ_STR + achk * 8) * 2;
    const uint32_t poff = (uint32_t)((wm * 16 + mrow_a) * AP_STR + achk * 8) * 2;

    for (int kc = 0; kc < 18; ++kc) {
        if (kc + 1 < 18) load_kv(kc + 1, (kc + 1) & 1);
        CP_COMMIT();
        CP_WAIT1();
        __syncthreads();
        const int buf = kc & 1;
        const uint32_t kb = sb + AO_K(buf), vb = sb + AO_V(buf);

        // ---- S = Q K^T
        float sacc[4][4];
#pragma unroll
        for (int f = 0; f < 4; ++f)
#pragma unroll
            for (int e = 0; e < 4; ++e) sacc[f][e] = 0.f;
        const uint32_t koff = (uint32_t)((wn * 32 + nrow_b) * AQ_STR + bchk * 8) * 2;
#pragma unroll
        for (int ks = 0; ks < 8; ++ks) {
            uint32_t ah[4];
            LDSM4(ah, sb + AO_Q + qoff + ks * 32);
#pragma unroll
            for (int g2 = 0; g2 < 2; ++g2) {
                uint32_t bh[4];
                LDSM4(bh, kb + koff + g2 * (16 * AQ_STR * 2) + ks * 32);
#pragma unroll
                for (int h = 0; h < 2; ++h)
                    mma_f16(sacc[g2 * 2 + h], ah, &bh[h * 2]);
            }
        }
        {
            int r = wm * 16 + (lane >> 2);
#pragma unroll
            for (int f = 0; f < 4; ++f) {
                int cc = wn * 32 + f * 8 + 2 * (lane & 3);
                Sb[r * 66 + cc]           = sacc[f][0];
                Sb[r * 66 + cc + 1]       = sacc[f][1];
                Sb[(r + 8) * 66 + cc]     = sacc[f][2];
                Sb[(r + 8) * 66 + cc + 1] = sacc[f][3];
            }
        }
        __syncthreads();

        // ---- online softmax
        if (tid < 64) {
            float m = mrow[tid];
            float mx = m;
            float* sr = &Sb[tid * 66];
#pragma unroll 8
            for (int cc = 0; cc < 64; ++cc) mx = fmaxf(mx, sr[cc]);
            float fac = __expf(m - mx);
            float l = lrow[tid] * fac;
#pragma unroll 8
            for (int cc = 0; cc < 64; ++cc) {
                float e = __expf(sr[cc] - mx);
                sr[cc] = e;
                l += e;
            }
            mrow[tid] = mx; lrow[tid] = l; arow[tid] = fac;
        }
        __syncthreads();

        // ---- P -> fp16 + rescale accumulators
        {
            int pr = tid >> 2, pc0 = (tid & 3) * 16;
            const float* srow = &Sb[pr * 66 + pc0];
            __half* ph = (__half*)(smc + AO_PH) + pr * AP_STR + pc0;
#pragma unroll
            for (int j = 0; j < 16; j += 2) {
                __half2 hp;
                hp.x = __float2half(srow[j]);
                hp.y = __float2half(srow[j + 1]);
                *(__half2*)(ph + j) = hp;
            }
        }
        {
            float f0 = arow[wm * 16 + (lane >> 2)];
            float f1 = arow[wm * 16 + (lane >> 2) + 8];
#pragma unroll
            for (int f = 0; f < 8; ++f) {
                oacc[f][0] *= f0; oacc[f][1] *= f0;
                oacc[f][2] *= f1; oacc[f][3] *= f1;
            }
        }
        __syncthreads();

        // ---- O += P V
#pragma unroll
        for (int ks = 0; ks < 4; ++ks) {
            uint32_t ph[4];
            LDSM4(ph, sb + AO_PH + poff + ks * 32);
#pragma unroll
            for (int g2 = 0; g2 < 4; ++g2) {
                uint32_t vh[4];
                uint32_t p = (uint32_t)((ks * 16 + vrow) * AQ_STR + wn * 64 + g2 * 16 + vc8) * 2;
                LDSM4T(vh, vb + p);
#pragma unroll
                for (int h = 0; h < 2; ++h)
                    mma_f16(oacc[g2 * 2 + h], ph, &vh[h * 2]);
            }
        }
        __syncthreads();
    }

    // ---- epilogue
    {
        int r1 = wm * 16 + (lane >> 2), r2 = r1 + 8;
        float i1 = 1.f / lrow[r1], i2 = 1.f / lrow[r2];
        int g1 = combined_row(fi, q0 + r1), g2r = combined_row(fi, q0 + r2);
#pragma unroll
        for (int f = 0; f < 8; ++f) {
            int col = coloff + wn * 64 + f * 8 + 2 * (lane & 3);
            __half2 p;
            p.x = __float2half(oacc[f][0] * i1); p.y = __float2half(oacc[f][1] * i1);
            *(__half2*)(OH + (size_t)g1 * C_DIM + col) = p;
            p.x = __float2half(oacc[f][2] * i2); p.y = __float2half(oacc[f][3] * i2);
            *(__half2*)(OH + (size_t)g2r * C_DIM + col) = p;
        }
    }
}

// ----------------------------------------------------------------- residual gate
__global__ __launch_bounds__(256) void resid_kernel(
    float* __restrict__ st, const float* __restrict__ x, const float* __restrict__ t)
{
    size_t base = (size_t)blockIdx.x * C_DIM + threadIdx.x * 8;
    const float* g = t + 4096 + threadIdx.x * 8;
    float4 s0 = *(float4*)&st[base],      s1 = *(float4*)&st[base + 4];
    float4 x0 = *(const float4*)&x[base], x1 = *(const float4*)&x[base + 4];
    float4 g0 = *(const float4*)&g[0],    g1 = *(const float4*)&g[4];
    s0.x += g0.x * x0.x; s0.y += g0.y * x0.y; s0.z += g0.z * x0.z; s0.w += g0.w * x0.w;
    s1.x += g1.x * x1.x; s1.y += g1.y * x1.y; s1.z += g1.z * x1.z; s1.w += g1.w * x1.w;
    *(float4*)&st[base]     = s0;
    *(float4*)&st[base + 4] = s1;
}

// ----------------------------------------------------------------- launch
extern "C" void kernel_launch(void* const* d_in, const int* in_sizes, int n_in,
                              void* d_out, int out_size)
{
    const float* temb  = (const float*)d_in[2];
    const float* cos_h = (const float*)d_in[3];
    const float* sin_h = (const float*)d_in[4];
    const float* cos_r = (const float*)d_in[5];
    const float* sin_r = (const float*)d_in[6];
    const float* l1lw = (const float*)d_in[7],  *l1lb = (const float*)d_in[8];
    const float* l1nw = (const float*)d_in[9],  *l1nb = (const float*)d_in[10];
    const float* l2lw = (const float*)d_in[11], *l2lb = (const float*)d_in[12];
    const float* l2nw = (const float*)d_in[13], *l2nb = (const float*)d_in[14];
    const float* wq = (const float*)d_in[15], *bq = (const float*)d_in[16];
    const float* wk = (const float*)d_in[17], *bk = (const float*)d_in[18];
    const float* wv = (const float*)d_in[19], *bv = (const float*)d_in[20];
    const float* nqw = (const float*)d_in[21], *nkw = (const float*)d_in[22];
    const float* wo = (const float*)d_in[23], *bo = (const float*)d_in[24];
    const float* fw1 = (const float*)d_in[25], *fb1 = (const float*)d_in[26];
    const float* fw2 = (const float*)d_in[27], *fb2 = (const float*)d_in[28];
    float* st = (float*)d_out;

    float *t1, *t2, *q, *k, *tp;
    __half *nrm, *qH, *kH, *vH, *aoH, *mid;
    __half *wqh, *wkh, *wvh, *woh, *f1h, *f2h;
    cudaGetSymbolAddress((void**)&t1,  g_t1);
    cudaGetSymbolAddress((void**)&t2,  g_t2);
    cudaGetSymbolAddress((void**)&q,   g_q);
    cudaGetSymbolAddress((void**)&k,   g_k);
    cudaGetSymbolAddress((void**)&tp,  g_tp);
    cudaGetSymbolAddress((void**)&nrm, g_nrm);
    cudaGetSymbolAddress((void**)&qH, g_qH);
    cudaGetSymbolAddress((void**)&kH, g_kH);
    cudaGetSymbolAddress((void**)&vH, g_vH);
    cudaGetSymbolAddress((void**)&aoH, g_aoH);
    cudaGetSymbolAddress((void**)&mid, g_mid);
    cudaGetSymbolAddress((void**)&wqh, g_wq);
    cudaGetSymbolAddress((void**)&wkh, g_wk);
    cudaGetSymbolAddress((void**)&wvh, g_wv);
    cudaGetSymbolAddress((void**)&woh, g_wo);
    cudaGetSymbolAddress((void**)&f1h, g_f1);
    cudaGetSymbolAddress((void**)&f2h, g_f2);

    size_t half_b = (size_t)C_SEQ * C_DIM * sizeof(float);
    cudaMemcpyAsync(st, d_in[0], half_b, cudaMemcpyDeviceToDevice, 0);
    cudaMemcpyAsync(st + (size_t)C_SEQ * C_DIM, d_in[1], half_b, cudaMemcpyDeviceToDevice, 0);

    cudaFuncSetAttribute(attn_kernel, cudaFuncAttributeMaxDynamicSharedMemorySize, ATTN_SMEM);
    cudaFuncSetAttribute(mma_gemm,    cudaFuncAttributeMaxDynamicSharedMemorySize, MG_SMEM);

    wconv_kernel<<<dim3(64, 64),   256>>>(wq,  wqh, C_DIM, C_DIM);
    wconv_kernel<<<dim3(64, 64),   256>>>(wk,  wkh, C_DIM, C_DIM);
    wconv_kernel<<<dim3(64, 64),   256>>>(wv,  wvh, C_DIM, C_DIM);
    wconv_kernel<<<dim3(64, 64),   256>>>(wo,  woh, C_DIM, C_DIM);
    wconv_kernel<<<dim3(256, 64),  256>>>(fw1, f1h, C_DIM, C_FFN);
    wconv_kernel<<<dim3(64, 256),  256>>>(fw2, f2h, C_FFN, C_DIM);

    temb_kernel<<<dim3(24, 2), 256>>>(temb, l1lw, l1lb, l2lw, l2lb, t1, t2);
    ln_mod_kernel<<<C_ROWS, 256>>>(st, t1, l1nw, l1nb, nrm);
    mma_gemm<<<dim3(16, 36), 256, MG_SMEM>>>(nrm, wqh, bq, q, 0, C_DIM, C_DIM, 0);
    mma_gemm<<<dim3(16, 36), 256, MG_SMEM>>>(nrm, wkh, bk, k, 0, C_DIM, C_DIM, 0);
    mma_gemm<<<dim3(16, 36), 256, MG_SMEM>>>(nrm, wvh, bv, 0, vH, C_DIM, C_DIM, 2);
    rmsrope_kernel<<<dim3(C_ROWS, 2), 256>>>(q, k, nqw, nkw, cos_h, sin_h, cos_r, sin_r, qH, kH);
    attn_kernel<<<dim3(18, 64), 256, ATTN_SMEM>>>(qH, kH, vH, aoH);
    mma_gemm<<<dim3(16, 36), 256, MG_SMEM>>>(aoH, woh, bo, tp, 0, C_DIM, C_DIM, 0);
    resid_kernel<<<C_ROWS, 256>>>(st, tp, t1);
    ln_mod_kernel<<<C_ROWS, 256>>>(st, t2, l2nw, l2nb, nrm);
    mma_gemm<<<dim3(64, 36), 256, MG_SMEM>>>(nrm, f1h, fb1, 0, mid, C_FFN, C_DIM, 1);
    mma_gemm<<<dim3(16, 36), 256, MG_SMEM>>>(mid, f2h, fb2, tp, 0, C_DIM, C_FFN, 0);
    resid_kernel<<<C_ROWS, 256>>>(st, tp, t2);
}

// round 14
// speedup vs baseline: 7.2788x; 1.2627x over previous
#include <cuda_runtime.h>
#include <cuda_fp16.h>
#include <cstdint>
#include <cstddef>

#define C_SEQ   2304
#define C_DIM   2048
#define C_ROWS  4608
#define C_FFN   8192
#define C_SCALE 0.08838834764831845f   // 1/sqrt(128)

// ----------------------------------------------------------------- scratch
__device__ float g_t1[6144];
__device__ float g_t2[6144];
__device__ __half g_nrm[(size_t)C_ROWS * C_DIM];
__device__ float g_q [(size_t)C_ROWS * C_DIM];
__device__ float g_k [(size_t)C_ROWS * C_DIM];
__device__ float g_tp[(size_t)C_ROWS * C_DIM];
__device__ __half g_qH[(size_t)C_ROWS * C_DIM];
__device__ __half g_kH[(size_t)C_ROWS * C_DIM];
__device__ __half g_vH[(size_t)C_ROWS * C_DIM];
__device__ __half g_aoH[(size_t)C_ROWS * C_DIM];
__device__ __half g_mid[(size_t)C_ROWS * C_FFN];
// transposed fp16 weights: [N, K]
__device__ __half g_wq[(size_t)C_DIM * C_DIM];
__device__ __half g_wk[(size_t)C_DIM * C_DIM];
__device__ __half g_wv[(size_t)C_DIM * C_DIM];
__device__ __half g_wo[(size_t)C_DIM * C_DIM];
__device__ __half g_f1[(size_t)C_FFN * C_DIM];
__device__ __half g_f2[(size_t)C_DIM * C_FFN];

// ----------------------------------------------------------------- helpers
__device__ __forceinline__ uint32_t smem_u32(const void* p) {
    uint32_t a;
    asm("{ .reg .u64 t; cvta.to.shared.u64 t, %1; cvt.u32.u64 %0, t; }" : "=r"(a) : "l"(p));
    return a;
}
#define CP16(dst, src) \
    asm volatile("cp.async.cg.shared.global [%0], [%1], 16;" :: "r"(dst), "l"(src) : "memory")
#define CP_COMMIT() asm volatile("cp.async.commit_group;" ::: "memory")
#define CP_WAIT1()  asm volatile("cp.async.wait_group 1;" ::: "memory")
#define LDSM4(r, p) \
    asm volatile("ldmatrix.sync.aligned.m8n8.x4.shared.b16 {%0,%1,%2,%3}, [%4];" \
        : "=r"((r)[0]), "=r"((r)[1]), "=r"((r)[2]), "=r"((r)[3]) : "r"(p))
#define LDSM4T(r, p) \
    asm volatile("ldmatrix.sync.aligned.m8n8.x4.trans.shared.b16 {%0,%1,%2,%3}, [%4];" \
        : "=r"((r)[0]), "=r"((r)[1]), "=r"((r)[2]), "=r"((r)[3]) : "r"(p))

__device__ __forceinline__ void mma_f16(float* d, const uint32_t* a, const uint32_t* b) {
    asm volatile("mma.sync.aligned.m16n8k16.row.col.f32.f16.f16.f32 "
        "{%0,%1,%2,%3}, {%4,%5,%6,%7}, {%8,%9}, {%0,%1,%2,%3};"
        : "+f"(d[0]), "+f"(d[1]), "+f"(d[2]), "+f"(d[3])
        : "r"(a[0]), "r"(a[1]), "r"(a[2]), "r"(a[3]), "r"(b[0]), "r"(b[1]));
}
__device__ __forceinline__ float gelu_t(float x) {
    float x3 = x * x * x;
    return 0.5f * x * (1.f + tanhf(0.7978845608028654f * (x + 0.044715f * x3)));
}

// ----------------------------------------------------------------- temb -> t1/t2
__global__ __launch_bounds__(256) void temb_kernel(
    const float* __restrict__ temb,
    const float* __restrict__ lw1, const float* __restrict__ lb1,
    const float* __restrict__ lw2, const float* __restrict__ lb2,
    float* __restrict__ t1, float* __restrict__ t2)
{
    __shared__ float s[512];
    int tid = threadIdx.x;
    float a = temb[tid], b = temb[tid + 256];
    s[tid]       = a / (1.f + __expf(-a));
    s[tid + 256] = b / (1.f + __expf(-b));
    __syncthreads();
    const float* lw = blockIdx.y ? lw2 : lw1;
    const float* lb = blockIdx.y ? lb2 : lb1;
    float* t        = blockIdx.y ? t2  : t1;
    int j = blockIdx.x * 256 + tid;
    float acc = lb[j];
#pragma unroll 8
    for (int i = 0; i < 512; ++i) acc += s[i] * lw[(size_t)i * 6144 + j];
    t[j] = acc;
}

// ----------------------------------------------------------------- LN helpers
__device__ __forceinline__ void ln_store(
    const float* xv, float mu, float rstd, const float* __restrict__ t,
    const float* __restrict__ nw, const float* __restrict__ nb,
    __half* __restrict__ H, size_t ob, int tid)
{
#pragma unroll
    for (int e = 0; e < 8; e += 2) {
        int c = tid * 8 + e;
        float a0 = ((xv[e]   - mu) * rstd * nw[c]   + nb[c])   * (1.f + t[2048 + c])   + t[c];
        float a1 = ((xv[e+1] - mu) * rstd * nw[c+1] + nb[c+1]) * (1.f + t[2048 + c+1]) + t[c+1];
        __half2 hp; hp.x = __float2half(a0); hp.y = __float2half(a1);
        *(__half2*)(H + ob + e) = hp;
    }
}

// ----------------------------------------------------------------- LN + modulation -> fp16
__global__ __launch_bounds__(256) void ln_mod_kernel(
    const float* __restrict__ st, const float* __restrict__ t,
    const float* __restrict__ nw, const float* __restrict__ nb,
    __half* __restrict__ H)
{
    int row = blockIdx.x, tid = threadIdx.x;
    const float* x = st + (size_t)row * C_DIM;
    float4 v0 = *(const float4*)(x + tid * 8);
    float4 v1 = *(const float4*)(x + tid * 8 + 4);
    float xv[8] = {v0.x, v0.y, v0.z, v0.w, v1.x, v1.y, v1.z, v1.w};
    float s = 0.f, ss = 0.f;
#pragma unroll
    for (int e = 0; e < 8; ++e) { s += xv[e]; ss += xv[e] * xv[e]; }
#pragma unroll
    for (int o = 16; o > 0; o >>= 1) {
        s  += __shfl_xor_sync(0xffffffffu, s, o);
        ss += __shfl_xor_sync(0xffffffffu, ss, o);
    }
    __shared__ float rs[8], rss[8];
    if ((tid & 31) == 0) { rs[tid >> 5] = s; rss[tid >> 5] = ss; }
    __syncthreads();
    float tot = 0.f, tot2 = 0.f;
#pragma unroll
    for (int w = 0; w < 8; ++w) { tot += rs[w]; tot2 += rss[w]; }
    float mu   = tot * (1.f / 2048.f);
    float var  = tot2 * (1.f / 2048.f) - mu * mu;
    float rstd = rsqrtf(var + 1e-5f);
    ln_store(xv, mu, rstd, t, nw, nb, H, (size_t)row * C_DIM + tid * 8, tid);
}

// ----------------------------------------------------------------- resid + LN fused
__global__ __launch_bounds__(256) void resid_ln_kernel(
    float* __restrict__ st, const float* __restrict__ x, const float* __restrict__ tg,
    const float* __restrict__ t, const float* __restrict__ nw, const float* __restrict__ nb,
    __half* __restrict__ H)
{
    int row = blockIdx.x, tid = threadIdx.x;
    size_t base = (size_t)row * C_DIM + tid * 8;
    const float* g = tg + 4096 + tid * 8;
    float4 s0 = *(float4*)&st[base],      s1 = *(float4*)&st[base + 4];
    float4 x0 = *(const float4*)&x[base], x1 = *(const float4*)&x[base + 4];
    float4 g0 = *(const float4*)&g[0],    g1 = *(const float4*)&g[4];
    float xv[8];
    xv[0] = s0.x + g0.x * x0.x; xv[1] = s0.y + g0.y * x0.y;
    xv[2] = s0.z + g0.z * x0.z; xv[3] = s0.w + g0.w * x0.w;
    xv[4] = s1.x + g1.x * x1.x; xv[5] = s1.y + g1.y * x1.y;
    xv[6] = s1.z + g1.z * x1.z; xv[7] = s1.w + g1.w * x1.w;
    *(float4*)&st[base]     = make_float4(xv[0], xv[1], xv[2], xv[3]);
    *(float4*)&st[base + 4] = make_float4(xv[4], xv[5], xv[6], xv[7]);
    float s = 0.f, ss = 0.f;
#pragma unroll
    for (int e = 0; e < 8; ++e) { s += xv[e]; ss += xv[e] * xv[e]; }
#pragma unroll
    for (int o = 16; o > 0; o >>= 1) {
        s  += __shfl_xor_sync(0xffffffffu, s, o);
        ss += __shfl_xor_sync(0xffffffffu, ss, o);
    }
    __shared__ float rs[8], rss[8];
    if ((tid & 31) == 0) { rs[tid >> 5] = s; rss[tid >> 5] = ss; }
    __syncthreads();
    float tot = 0.f, tot2 = 0.f;
#pragma unroll
    for (int w = 0; w < 8; ++w) { tot += rs[w]; tot2 += rss[w]; }
    float mu   = tot * (1.f / 2048.f);
    float var  = tot2 * (1.f / 2048.f) - mu * mu;
    float rstd = rsqrtf(var + 1e-5f);
    ln_store(xv, mu, rstd, t, nw, nb, H, base, tid);
}

// ----------------------------------------------------------------- weight transpose -> fp16
__global__ __launch_bounds__(256) void wconv_kernel(
    const float* __restrict__ W, __half* __restrict__ T, int K, int N)
{
    __shared__ float t[32][33];
    int n0 = blockIdx.x * 32, k0 = blockIdx.y * 32;
    int tx = threadIdx.x & 31, ty = threadIdx.x >> 5;
#pragma unroll
    for (int i = 0; i < 4; ++i)
        t[ty * 4 + i][tx] = W[(size_t)(k0 + ty * 4 + i) * N + n0 + tx];
    __syncthreads();
#pragma unroll
    for (int i = 0; i < 4; ++i) {
        int r = ty * 4 + i;
        T[(size_t)(n0 + r) * K + k0 + tx] = __float2half(t[tx][r]);
    }
}

// ----------------------------------------------------------------- mma.sync HGEMM (fp32 accum)
// D[M,N] = A[M,K] * B[N,K]^T; K-contiguous fp16. BK=64, 3-stage, 1 bar/iter.
// act: 0=fp32+bias; 1=gelu->fp16; 2=bias->fp16
#define MG_TILE_B  18432            // 128 rows * 72 halves * 2B
#define MG_STAGE_B (2 * MG_TILE_B)
#define MG_SMEM    (3 * MG_STAGE_B) // 110592

__global__ __launch_bounds__(256) void mma_gemm(
    const __half* __restrict__ A, const __half* __restrict__ B,
    const float* __restrict__ bias, float* __restrict__ outF,
    __half* __restrict__ outH, int N, int K, int act)
{
    extern __shared__ char smc[];
    const uint32_t sb = smem_u32(smc);
    const int tid = threadIdx.x, lane = tid & 31, wid = tid >> 5;
    const int wm = wid & 3, wn = wid >> 2;
    const int m0 = blockIdx.y << 7, n0 = blockIdx.x << 7;

    auto load_chunk = [&](int c, int buf) {
        int k0 = c << 6;
        uint32_t st = sb + buf * MG_STAGE_B;
#pragma unroll
        for (int j = 0; j < 4; ++j) {
            int q = tid + j * 256;          // 0..1023
            int r = q >> 3, c8 = q & 7;
            uint32_t d = st + r * 144 + c8 * 16;
            CP16(d,             A + (size_t)(m0 + r) * K + k0 + c8 * 8);
            CP16(d + MG_TILE_B, B + (size_t)(n0 + r) * K + k0 + c8 * 8);
        }
    };

    const int mrow = (lane & 7) + ((lane >> 3) & 1) * 8;
    const int achk = lane >> 4;
    const int nrow = (lane & 7) + (lane >> 4) * 8;
    const int bchk = (lane >> 3) & 1;
    const uint32_t aoff = (uint32_t)(wm * 32 + mrow) * 144 + achk * 16;
    const uint32_t boff = (uint32_t)(wn * 64 + nrow) * 144 + bchk * 16;

    float acc[2][8][4];
#pragma unroll
    for (int i = 0; i < 2; ++i)
#pragma unroll
        for (int j = 0; j < 8; ++j)
#pragma unroll
            for (int e = 0; e < 4; ++e) acc[i][j][e] = 0.f;

    const int NC = K >> 6;
    load_chunk(0, 0); CP_COMMIT();
    load_chunk(1, 1); CP_COMMIT();

    int buf = 0, pbuf = 2;
    for (int c = 0; c < NC; ++c) {
        CP_WAIT1();
        __syncthreads();
        uint32_t st = sb + buf * MG_STAGE_B;
#pragma unroll
        for (int ks = 0; ks < 4; ++ks) {
            uint32_t ah[2][4], bh[4][4];
#pragma unroll
            for (int mt = 0; mt < 2; ++mt)
                LDSM4(ah[mt], st + aoff + mt * (16 * 144) + ks * 32);
#pragma unroll
            for (int g = 0; g < 4; ++g)
                LDSM4(bh[g], st + MG_TILE_B + boff + g * (16 * 144) + ks * 32);
#pragma unroll
            for (int mt = 0; mt < 2; ++mt)
#pragma unroll
                for (int g = 0; g < 4; ++g)
#pragma unroll
                    for (int h = 0; h < 2; ++h)
                        mma_f16(acc[mt][g * 2 + h], ah[mt], &bh[g][h * 2]);
        }
        if (c + 2 < NC) load_chunk(c + 2, pbuf);
        CP_COMMIT();
        buf  = (buf  == 2) ? 0 : buf  + 1;
        pbuf = (pbuf == 2) ? 0 : pbuf + 1;
    }

    const int g = lane >> 2, t4 = lane & 3;
#pragma unroll
    for (int mt = 0; mt < 2; ++mt) {
#pragma unroll
        for (int nt = 0; nt < 8; ++nt) {
            float* a = acc[mt][nt];
            int row = m0 + wm * 32 + mt * 16 + g;
            int col = n0 + wn * 64 + nt * 8 + 2 * t4;
            float b0 = bias[col], b1 = bias[col + 1];
            float v0 = a[0] + b0, v1 = a[1] + b1;
            float v2 = a[2] + b0, v3 = a[3] + b1;
            if (act == 0) {
                float2 u0; u0.x = v0; u0.y = v1;
                float2 u1; u1.x = v2; u1.y = v3;
                *(float2*)(outF + (size_t)row * N + col)       = u0;
                *(float2*)(outF + (size_t)(row + 8) * N + col) = u1;
            } else {
                if (act == 1) { v0 = gelu_t(v0); v1 = gelu_t(v1); v2 = gelu_t(v2); v3 = gelu_t(v3); }
                __half2 p;
                p.x = __float2half(v0); p.y = __float2half(v1);
                *(__half2*)(outH + (size_t)row * N + col) = p;
                p.x = __float2half(v2); p.y = __float2half(v3);
                *(__half2*)(outH + (size_t)(row + 8) * N + col) = p;
            }
        }
    }
}

// ----------------------------------------------------------------- RMSNorm + RoPE -> fp16
__global__ __launch_bounds__(256) void rmsrope_kernel(
    const float* __restrict__ Qf, const float* __restrict__ Kf,
    const float* __restrict__ nq, const float* __restrict__ nk,
    const float* __restrict__ cos_h, const float* __restrict__ sin_h,
    const float* __restrict__ cos_r, const float* __restrict__ sin_r,
    __half* __restrict__ qH, __half* __restrict__ kH)
{
    int row = blockIdx.x, tid = threadIdx.x;
    int isk = blockIdx.y;
    const float* x = (isk ? Kf : Qf) + (size_t)row * C_DIM;
    const float* nw = isk ? nk : nq;
    float oscale = isk ? 1.f : C_SCALE;
    __half* H = isk ? kH : qH;
    int isr = row >= C_SEQ;
    int pos = isr ? row - C_SEQ : row;
    const float* cp = (isr ? cos_r : cos_h) + (size_t)pos * 128;
    const float* sp = (isr ? sin_r : sin_h) + (size_t)pos * 128;
    float4 v0 = *(const float4*)(x + tid * 8);
    float4 v1 = *(const float4*)(x + tid * 8 + 4);
    float xv[8] = {v0.x, v0.y, v0.z, v0.w, v1.x, v1.y, v1.z, v1.w};
    float ss = 0.f;
#pragma unroll
    for (int e = 0; e < 8; ++e) ss += xv[e] * xv[e];
#pragma unroll
    for (int o = 16; o > 0; o >>= 1) ss += __shfl_xor_sync(0xffffffffu, ss, o);
    __shared__ float rss[8];
    if ((tid & 31) == 0) rss[tid >> 5] = ss;
    __syncthreads();
    float tot = 0.f;
#pragma unroll
    for (int w = 0; w < 8; ++w) tot += rss[w];
    float rstd = rsqrtf(tot * (1.f / 2048.f) + 1e-6f);
    size_t ob = (size_t)row * C_DIM + tid * 8;
#pragma unroll
    for (int p = 0; p < 4; ++p) {
        int ce = tid * 8 + 2 * p;
        int de = ce & 127;
        float x1 = xv[2 * p]     * rstd * nw[ce];
        float x2 = xv[2 * p + 1] * rstd * nw[ce + 1];
        float cv = cp[de], sv = sp[de + 1];
        float e0 = (x1 * cv - x2 * sv) * oscale;
        float e1 = (x1 * sv + x2 * cv) * oscale;
        __half2 hp; hp.x = __float2half(e0); hp.y = __float2half(e1);
        *(__half2*)(H + ob + 2 * p) = hp;
    }
}

// ----------------------------------------------------------------- attention (fp16 mma flash)
__device__ __forceinline__ int combined_row(int fi, int j) {
    int hi = j / 48;
    int wi = j - hi * 48;
    int base = (wi < 24) ? 0 : C_SEQ;
    int ww   = (wi < 24) ? wi : wi - 24;
    return base + fi * 576 + hi * 24 + ww;
}

#define AQ_STR 136
#define AP_STR 72
#define A_TILE  17408                 // 64*136*2 bytes
#define AO_Q    0
#define AO_K(b) (17408 + (b) * A_TILE)
#define AO_V(b) (52224 + (b) * A_TILE)
#define AO_S    87040                 // fp32 [64][66]
#define AO_PH   103936                // fp16 [64][72]
#define AO_M    113152
#define AO_LR   113408
#define AO_A    113664
#define ATTN_SMEM 113920

__global__ __launch_bounds__(256) void attn_kernel(
    const __half* __restrict__ QhG, const __half* __restrict__ KhG,
    const __half* __restrict__ VhG, __half* __restrict__ OH)
{
    extern __shared__ char smc[];
    const uint32_t sb = smem_u32(smc);
    float* Sb   = (float*)(smc + AO_S);
    float* mrow = (float*)(smc + AO_M);
    float* lrow = (float*)(smc + AO_LR);
    float* arow = (float*)(smc + AO_A);

    const int tid  = threadIdx.x, lane = tid & 31, wid = tid >> 5;
    const int wm = wid & 3, wn = wid >> 2;
    const int fi = blockIdx.y >> 4;
    const int coloff = (blockIdx.y & 15) * 128;
    const int q0 = blockIdx.x * 64;

    const int mrow_a = (lane & 7) + ((lane >> 3) & 1) * 8;
    const int achk   = lane >> 4;
    const int nrow_b = (lane & 7) + (lane >> 4) * 8;
    const int bchk   = (lane >> 3) & 1;
    const int vrow   = mrow_a;
    const int vc8    = (lane >> 4) * 8;

#pragma unroll
    for (int i = 0; i < 4; ++i) {
        int c = tid + i * 256;
        int r = c >> 4, ch8 = (c & 15) * 8;
        int grow = combined_row(fi, q0 + r);
        uint32_t d = (uint32_t)(r * AQ_STR + ch8) * 2;
        CP16(sb + AO_Q + d, QhG + (size_t)grow * C_DIM + coloff + ch8);
    }
    auto load_kv = [&](int kc, int buf) {
        int k0 = kc * 64;
#pragma unroll
        for (int i = 0; i < 4; ++i) {
            int c = tid + i * 256;
            int r = c >> 4, ch8 = (c & 15) * 8;
            int grow = combined_row(fi, k0 + r);
            size_t g = (size_t)grow * C_DIM + coloff + ch8;
            uint32_t d = (uint32_t)(r * AQ_STR + ch8) * 2;
            CP16(sb + AO_K(buf) + d, KhG + g);
            CP16(sb + AO_V(buf) + d, VhG + g);
        }
    };
    load_kv(0, 0);
    CP_COMMIT();
    if (tid < 64) { mrow[tid] = -1e30f; lrow[tid] = 0.f; }

    float oacc[8][4];
#pragma unroll
    for (int f = 0; f < 8; ++f)
#pragma unroll
        for (int e = 0; e < 4; ++e) oacc[f][e] = 0.f;

    const uint32_t qoff = (uint32_t)((wm * 16 + mrow_a) * AQ_STR + achk * 8) * 2;
    const uint32_t poff = (uint32_t)((wm * 16 + mrow_a) * AP_STR + achk * 8) * 2;

    for (int kc = 0; kc < 18; ++kc) {
        if (kc + 1 < 18) load_kv(kc + 1, (kc + 1) & 1);
        CP_COMMIT();
        CP_WAIT1();
        __syncthreads();                          // B1: KV visible
        const int buf = kc & 1;
        const uint32_t kb = sb + AO_K(buf), vb = sb + AO_V(buf);

        // ---- S = Q K^T
        float sacc[4][4];
#pragma unroll
        for (int f = 0; f < 4; ++f)
#pragma unroll
            for (int e = 0; e < 4; ++e) sacc[f][e] = 0.f;
        const uint32_t koff = (uint32_t)((wn * 32 + nrow_b) * AQ_STR + bchk * 8) * 2;
#pragma unroll
        for (int ks = 0; ks < 8; ++ks) {
            uint32_t ah[4];
            LDSM4(ah, sb + AO_Q + qoff + ks * 32);
#pragma unroll
            for (int g2 = 0; g2 < 2; ++g2) {
                uint32_t bh[4];
                LDSM4(bh, kb + koff + g2 * (16 * AQ_STR * 2) + ks * 32);
#pragma unroll
                for (int h = 0; h < 2; ++h)
                    mma_f16(sacc[g2 * 2 + h], ah, &bh[h * 2]);
            }
        }
        {
            int r = wm * 16 + (lane >> 2);
#pragma unroll
            for (int f = 0; f < 4; ++f) {
                int cc = wn * 32 + f * 8 + 2 * (lane & 3);
                Sb[r * 66 + cc]           = sacc[f][0];
                Sb[r * 66 + cc + 1]       = sacc[f][1];
                Sb[(r + 8) * 66 + cc]     = sacc[f][2];
                Sb[(r + 8) * 66 + cc + 1] = sacc[f][3];
            }
        }
        __syncthreads();                          // B2: S complete

        // ---- parallel online softmax: 4 lanes per row, fused P-split
        {
            int pr = tid >> 2;
            int seg = (tid & 3) * 16;
            const float* sr = &Sb[pr * 66 + seg];
            float v[16];
            float lm = -1e30f;
#pragma unroll
            for (int j = 0; j < 16; ++j) { v[j] = sr[j]; lm = fmaxf(lm, v[j]); }
            lm = fmaxf(lm, __shfl_xor_sync(0xffffffffu, lm, 1));
            lm = fmaxf(lm, __shfl_xor_sync(0xffffffffu, lm, 2));
            float m_old = mrow[pr];
            float mx = fmaxf(m_old, lm);
            float ls = 0.f;
            __half* ph = (__half*)(smc + AO_PH) + pr * AP_STR + seg;
#pragma unroll
            for (int j = 0; j < 16; j += 2) {
                float e0 = __expf(v[j]     - mx);
                float e1 = __expf(v[j + 1] - mx);
                ls += e0 + e1;
                __half2 hp; hp.x = __float2half(e0); hp.y = __float2half(e1);
                *(__half2*)(ph + j) = hp;
            }
            ls += __shfl_xor_sync(0xffffffffu, ls, 1);
            ls += __shfl_xor_sync(0xffffffffu, ls, 2);
            if ((tid & 3) == 0) {
                float fac = __expf(m_old - mx);
                mrow[pr] = mx;
                lrow[pr] = lrow[pr] * fac + ls;
                arow[pr] = fac;
            }
        }
        __syncthreads();                          // B3: P, arow ready

        {
            float f0 = arow[wm * 16 + (lane >> 2)];
            float f1 = arow[wm * 16 + (lane >> 2) + 8];
#pragma unroll
            for (int f = 0; f < 8; ++f) {
                oacc[f][0] *= f0; oacc[f][1] *= f0;
                oacc[f][2] *= f1; oacc[f][3] *= f1;
            }
        }

        // ---- O += P V
#pragma unroll
        for (int ks = 0; ks < 4; ++ks) {
            uint32_t ph[4];
            LDSM4(ph, sb + AO_PH + poff + ks * 32);
#pragma unroll
            for (int g2 = 0; g2 < 4; ++g2) {
                uint32_t vh[4];
                uint32_t p = (uint32_t)((ks * 16 + vrow) * AQ_STR + wn * 64 + g2 * 16 + vc8) * 2;
                LDSM4T(vh, vb + p);
#pragma unroll
                for (int h = 0; h < 2; ++h)
                    mma_f16(oacc[g2 * 2 + h], ph, &vh[h * 2]);
            }
        }
        __syncthreads();                          // B4: V buf / PH reusable
    }

    // ---- epilogue
    {
        int r1 = wm * 16 + (lane >> 2), r2 = r1 + 8;
        float i1 = 1.f / lrow[r1], i2 = 1.f / lrow[r2];
        int g1 = combined_row(fi, q0 + r1), g2r = combined_row(fi, q0 + r2);
#pragma unroll
        for (int f = 0; f < 8; ++f) {
            int col = coloff + wn * 64 + f * 8 + 2 * (lane & 3);
            __half2 p;
            p.x = __float2half(oacc[f][0] * i1); p.y = __float2half(oacc[f][1] * i1);
            *(__half2*)(OH + (size_t)g1 * C_DIM + col) = p;
            p.x = __float2half(oacc[f][2] * i2); p.y = __float2half(oacc[f][3] * i2);
            *(__half2*)(OH + (size_t)g2r * C_DIM + col) = p;
        }
    }
}

// ----------------------------------------------------------------- residual gate
__global__ __launch_bounds__(256) void resid_kernel(
    float* __restrict__ st, const float* __restrict__ x, const float* __restrict__ t)
{
    size_t base = (size_t)blockIdx.x * C_DIM + threadIdx.x * 8;
    const float* g = t + 4096 + threadIdx.x * 8;
    float4 s0 = *(float4*)&st[base],      s1 = *(float4*)&st[base + 4];
    float4 x0 = *(const float4*)&x[base], x1 = *(const float4*)&x[base + 4];
    float4 g0 = *(const float4*)&g[0],    g1 = *(const float4*)&g[4];
    s0.x += g0.x * x0.x; s0.y += g0.y * x0.y; s0.z += g0.z * x0.z; s0.w += g0.w * x0.w;
    s1.x += g1.x * x1.x; s1.y += g1.y * x1.y; s1.z += g1.z * x1.z; s1.w += g1.w * x1.w;
    *(float4*)&st[base]     = s0;
    *(float4*)&st[base + 4] = s1;
}

// ----------------------------------------------------------------- launch
extern "C" void kernel_launch(void* const* d_in, const int* in_sizes, int n_in,
                              void* d_out, int out_size)
{
    const float* temb  = (const float*)d_in[2];
    const float* cos_h = (const float*)d_in[3];
    const float* sin_h = (const float*)d_in[4];
    const float* cos_r = (const float*)d_in[5];
    const float* sin_r = (const float*)d_in[6];
    const float* l1lw = (const float*)d_in[7],  *l1lb = (const float*)d_in[8];
    const float* l1nw = (const float*)d_in[9],  *l1nb = (const float*)d_in[10];
    const float* l2lw = (const float*)d_in[11], *l2lb = (const float*)d_in[12];
    const float* l2nw = (const float*)d_in[13], *l2nb = (const float*)d_in[14];
    const float* wq = (const float*)d_in[15], *bq = (const float*)d_in[16];
    const float* wk = (const float*)d_in[17], *bk = (const float*)d_in[18];
    const float* wv = (const float*)d_in[19], *bv = (const float*)d_in[20];
    const float* nqw = (const float*)d_in[21], *nkw = (const float*)d_in[22];
    const float* wo = (const float*)d_in[23], *bo = (const float*)d_in[24];
    const float* fw1 = (const float*)d_in[25], *fb1 = (const float*)d_in[26];
    const float* fw2 = (const float*)d_in[27], *fb2 = (const float*)d_in[28];
    float* st = (float*)d_out;

    float *t1, *t2, *q, *k, *tp;
    __half *nrm, *qH, *kH, *vH, *aoH, *mid;
    __half *wqh, *wkh, *wvh, *woh, *f1h, *f2h;
    cudaGetSymbolAddress((void**)&t1,  g_t1);
    cudaGetSymbolAddress((void**)&t2,  g_t2);
    cudaGetSymbolAddress((void**)&q,   g_q);
    cudaGetSymbolAddress((void**)&k,   g_k);
    cudaGetSymbolAddress((void**)&tp,  g_tp);
    cudaGetSymbolAddress((void**)&nrm, g_nrm);
    cudaGetSymbolAddress((void**)&qH, g_qH);
    cudaGetSymbolAddress((void**)&kH, g_kH);
    cudaGetSymbolAddress((void**)&vH, g_vH);
    cudaGetSymbolAddress((void**)&aoH, g_aoH);
    cudaGetSymbolAddress((void**)&mid, g_mid);
    cudaGetSymbolAddress((void**)&wqh, g_wq);
    cudaGetSymbolAddress((void**)&wkh, g_wk);
    cudaGetSymbolAddress((void**)&wvh, g_wv);
    cudaGetSymbolAddress((void**)&woh, g_wo);
    cudaGetSymbolAddress((void**)&f1h, g_f1);
    cudaGetSymbolAddress((void**)&f2h, g_f2);

    size_t half_b = (size_t)C_SEQ * C_DIM * sizeof(float);
    cudaMemcpyAsync(st, d_in[0], half_b, cudaMemcpyDeviceToDevice, 0);
    cudaMemcpyAsync(st + (size_t)C_SEQ * C_DIM, d_in[1], half_b, cudaMemcpyDeviceToDevice, 0);

    cudaFuncSetAttribute(attn_kernel, cudaFuncAttributeMaxDynamicSharedMemorySize, ATTN_SMEM);
    cudaFuncSetAttribute(mma_gemm,    cudaFuncAttributeMaxDynamicSharedMemorySize, MG_SMEM);

    wconv_kernel<<<dim3(64, 64),   256>>>(wq,  wqh, C_DIM, C_DIM);
    wconv_kernel<<<dim3(64, 64),   256>>>(wk,  wkh, C_DIM, C_DIM);
    wconv_kernel<<<dim3(64, 64),   256>>>(wv,  wvh, C_DIM, C_DIM);
    wconv_kernel<<<dim3(64, 64),   256>>>(wo,  woh, C_DIM, C_DIM);
    wconv_kernel<<<dim3(256, 64),  256>>>(fw1, f1h, C_DIM, C_FFN);
    wconv_kernel<<<dim3(64, 256),  256>>>(fw2, f2h, C_FFN, C_DIM);

    temb_kernel<<<dim3(24, 2), 256>>>(temb, l1lw, l1lb, l2lw, l2lb, t1, t2);
    ln_mod_kernel<<<C_ROWS, 256>>>(st, t1, l1nw, l1nb, nrm);
    mma_gemm<<<dim3(16, 36), 256, MG_SMEM>>>(nrm, wqh, bq, q, 0, C_DIM, C_DIM, 0);
    mma_gemm<<<dim3(16, 36), 256, MG_SMEM>>>(nrm, wkh, bk, k, 0, C_DIM, C_DIM, 0);
    mma_gemm<<<dim3(16, 36), 256, MG_SMEM>>>(nrm, wvh, bv, 0, vH, C_DIM, C_DIM, 2);
    rmsrope_kernel<<<dim3(C_ROWS, 2), 256>>>(q, k, nqw, nkw, cos_h, sin_h, cos_r, sin_r, qH, kH);
    attn_kernel<<<dim3(18, 64), 256, ATTN_SMEM>>>(qH, kH, vH, aoH);
    mma_gemm<<<dim3(16, 36), 256, MG_SMEM>>>(aoH, woh, bo, tp, 0, C_DIM, C_DIM, 0);
    resid_ln_kernel<<<C_ROWS, 256>>>(st, tp, t1, t2, l2nw, l2nb, nrm);
    mma_gemm<<<dim3(64, 36), 256, MG_SMEM>>>(nrm, f1h, fb1, 0, mid, C_FFN, C_DIM, 1);
    mma_gemm<<<dim3(16, 36), 256, MG_SMEM>>>(mid, f2h, fb2, tp, 0, C_DIM, C_FFN, 0);
    resid_kernel<<<C_ROWS, 256>>>(st, tp, t2);
}

// round 15
// speedup vs baseline: 7.5468x; 1.0368x over previous
#include <cuda_runtime.h>
#include <cuda_fp16.h>
#include <cstdint>
#include <cstddef>

#define C_SEQ   2304
#define C_DIM   2048
#define C_ROWS  4608
#define C_FFN   8192
#define C_SCALE 0.08838834764831845f   // 1/sqrt(128)

// ----------------------------------------------------------------- scratch
__device__ float g_t1[6144];
__device__ float g_t2[6144];
__device__ __half g_nrm[(size_t)C_ROWS * C_DIM];
__device__ float g_tp[(size_t)C_ROWS * C_DIM];
__device__ __half g_qH[(size_t)C_ROWS * C_DIM];
__device__ __half g_kH[(size_t)C_ROWS * C_DIM];
__device__ __half g_vH[(size_t)C_ROWS * C_DIM];
__device__ __half g_aoH[(size_t)C_ROWS * C_DIM];
__device__ __half g_mid[(size_t)C_ROWS * C_FFN];
// transposed fp16 weights: [N, K]
__device__ __half g_wq[(size_t)C_DIM * C_DIM];
__device__ __half g_wk[(size_t)C_DIM * C_DIM];
__device__ __half g_wv[(size_t)C_DIM * C_DIM];
__device__ __half g_wo[(size_t)C_DIM * C_DIM];
__device__ __half g_f1[(size_t)C_FFN * C_DIM];
__device__ __half g_f2[(size_t)C_DIM * C_FFN];

// ----------------------------------------------------------------- helpers
__device__ __forceinline__ uint32_t smem_u32(const void* p) {
    uint32_t a;
    asm("{ .reg .u64 t; cvta.to.shared.u64 t, %1; cvt.u32.u64 %0, t; }" : "=r"(a) : "l"(p));
    return a;
}
#define CP16(dst, src) \
    asm volatile("cp.async.cg.shared.global [%0], [%1], 16;" :: "r"(dst), "l"(src) : "memory")
#define CP_COMMIT() asm volatile("cp.async.commit_group;" ::: "memory")
#define CP_WAIT1()  asm volatile("cp.async.wait_group 1;" ::: "memory")
#define LDSM4(r, p) \
    asm volatile("ldmatrix.sync.aligned.m8n8.x4.shared.b16 {%0,%1,%2,%3}, [%4];" \
        : "=r"((r)[0]), "=r"((r)[1]), "=r"((r)[2]), "=r"((r)[3]) : "r"(p))
#define LDSM4T(r, p) \
    asm volatile("ldmatrix.sync.aligned.m8n8.x4.trans.shared.b16 {%0,%1,%2,%3}, [%4];" \
        : "=r"((r)[0]), "=r"((r)[1]), "=r"((r)[2]), "=r"((r)[3]) : "r"(p))

__device__ __forceinline__ void mma_f16(float* d, const uint32_t* a, const uint32_t* b) {
    asm volatile("mma.sync.aligned.m16n8k16.row.col.f32.f16.f16.f32 "
        "{%0,%1,%2,%3}, {%4,%5,%6,%7}, {%8,%9}, {%0,%1,%2,%3};"
        : "+f"(d[0]), "+f"(d[1]), "+f"(d[2]), "+f"(d[3])
        : "r"(a[0]), "r"(a[1]), "r"(a[2]), "r"(a[3]), "r"(b[0]), "r"(b[1]));
}
__device__ __forceinline__ float gelu_t(float x) {
    // 0.5x(1+tanh(u)) == x * sigmoid(2u)
    float u2 = 1.5957691216057308f * (x + 0.044715f * x * x * x);
    return __fdividef(x, 1.f + __expf(-u2));
}

// ----------------------------------------------------------------- temb -> t1/t2
__global__ __launch_bounds__(256) void temb_kernel(
    const float* __restrict__ temb,
    const float* __restrict__ lw1, const float* __restrict__ lb1,
    const float* __restrict__ lw2, const float* __restrict__ lb2,
    float* __restrict__ t1, float* __restrict__ t2)
{
    __shared__ float s[512];
    int tid = threadIdx.x;
    float a = temb[tid], b = temb[tid + 256];
    s[tid]       = a / (1.f + __expf(-a));
    s[tid + 256] = b / (1.f + __expf(-b));
    __syncthreads();
    const float* lw = blockIdx.y ? lw2 : lw1;
    const float* lb = blockIdx.y ? lb2 : lb1;
    float* t        = blockIdx.y ? t2  : t1;
    int j = blockIdx.x * 256 + tid;
    float acc = lb[j];
#pragma unroll 8
    for (int i = 0; i < 512; ++i) acc += s[i] * lw[(size_t)i * 6144 + j];
    t[j] = acc;
}

// ----------------------------------------------------------------- LN store helper
__device__ __forceinline__ void ln_store(
    const float* xv, float mu, float rstd, const float* __restrict__ t,
    const float* __restrict__ nw, const float* __restrict__ nb,
    __half* __restrict__ H, size_t ob, int tid)
{
#pragma unroll
    for (int e = 0; e < 8; e += 2) {
        int c = tid * 8 + e;
        float a0 = ((xv[e]   - mu) * rstd * nw[c]   + nb[c])   * (1.f + t[2048 + c])   + t[c];
        float a1 = ((xv[e+1] - mu) * rstd * nw[c+1] + nb[c+1]) * (1.f + t[2048 + c+1]) + t[c+1];
        __half2 hp; hp.x = __float2half(a0); hp.y = __float2half(a1);
        *(__half2*)(H + ob + e) = hp;
    }
}

// ----------------------------------------------------------------- first LN: reads inputs, writes st + nrm
__global__ __launch_bounds__(256) void ln_mod_first(
    const float* __restrict__ src0, const float* __restrict__ src1,
    const float* __restrict__ t,
    const float* __restrict__ nw, const float* __restrict__ nb,
    __half* __restrict__ H, float* __restrict__ st)
{
    int row = blockIdx.x, tid = threadIdx.x;
    const float* x = (row < C_SEQ) ? src0 + (size_t)row * C_DIM
                                   : src1 + (size_t)(row - C_SEQ) * C_DIM;
    float4 v0 = *(const float4*)(x + tid * 8);
    float4 v1 = *(const float4*)(x + tid * 8 + 4);
    size_t base = (size_t)row * C_DIM + tid * 8;
    *(float4*)&st[base]     = v0;
    *(float4*)&st[base + 4] = v1;
    float xv[8] = {v0.x, v0.y, v0.z, v0.w, v1.x, v1.y, v1.z, v1.w};
    float s = 0.f, ss = 0.f;
#pragma unroll
    for (int e = 0; e < 8; ++e) { s += xv[e]; ss += xv[e] * xv[e]; }
#pragma unroll
    for (int o = 16; o > 0; o >>= 1) {
        s  += __shfl_xor_sync(0xffffffffu, s, o);
        ss += __shfl_xor_sync(0xffffffffu, ss, o);
    }
    __shared__ float rs[8], rss[8];
    if ((tid & 31) == 0) { rs[tid >> 5] = s; rss[tid >> 5] = ss; }
    __syncthreads();
    float tot = 0.f, tot2 = 0.f;
#pragma unroll
    for (int w = 0; w < 8; ++w) { tot += rs[w]; tot2 += rss[w]; }
    float mu   = tot * (1.f / 2048.f);
    float var  = tot2 * (1.f / 2048.f) - mu * mu;
    float rstd = rsqrtf(var + 1e-5f);
    ln_store(xv, mu, rstd, t, nw, nb, H, base, tid);
}

// ----------------------------------------------------------------- resid + LN fused
__global__ __launch_bounds__(256) void resid_ln_kernel(
    float* __restrict__ st, const float* __restrict__ x, const float* __restrict__ tg,
    const float* __restrict__ t, const float* __restrict__ nw, const float* __restrict__ nb,
    __half* __restrict__ H)
{
    int row = blockIdx.x, tid = threadIdx.x;
    size_t base = (size_t)row * C_DIM + tid * 8;
    const float* g = tg + 4096 + tid * 8;
    float4 s0 = *(float4*)&st[base],      s1 = *(float4*)&st[base + 4];
    float4 x0 = *(const float4*)&x[base], x1 = *(const float4*)&x[base + 4];
    float4 g0 = *(const float4*)&g[0],    g1 = *(const float4*)&g[4];
    float xv[8];
    xv[0] = s0.x + g0.x * x0.x; xv[1] = s0.y + g0.y * x0.y;
    xv[2] = s0.z + g0.z * x0.z; xv[3] = s0.w + g0.w * x0.w;
    xv[4] = s1.x + g1.x * x1.x; xv[5] = s1.y + g1.y * x1.y;
    xv[6] = s1.z + g1.z * x1.z; xv[7] = s1.w + g1.w * x1.w;
    *(float4*)&st[base]     = make_float4(xv[0], xv[1], xv[2], xv[3]);
    *(float4*)&st[base + 4] = make_float4(xv[4], xv[5], xv[6], xv[7]);
    float s = 0.f, ss = 0.f;
#pragma unroll
    for (int e = 0; e < 8; ++e) { s += xv[e]; ss += xv[e] * xv[e]; }
#pragma unroll
    for (int o = 16; o > 0; o >>= 1) {
        s  += __shfl_xor_sync(0xffffffffu, s, o);
        ss += __shfl_xor_sync(0xffffffffu, ss, o);
    }
    __shared__ float rs[8], rss[8];
    if ((tid & 31) == 0) { rs[tid >> 5] = s; rss[tid >> 5] = ss; }
    __syncthreads();
    float tot = 0.f, tot2 = 0.f;
#pragma unroll
    for (int w = 0; w < 8; ++w) { tot += rs[w]; tot2 += rss[w]; }
    float mu   = tot * (1.f / 2048.f);
    float var  = tot2 * (1.f / 2048.f) - mu * mu;
    float rstd = rsqrtf(var + 1e-5f);
    ln_store(xv, mu, rstd, t, nw, nb, H, base, tid);
}

// ----------------------------------------------------------------- weight transpose -> fp16
__global__ __launch_bounds__(256) void wconv_kernel(
    const float* __restrict__ W, __half* __restrict__ T, int K, int N)
{
    __shared__ float t[32][33];
    int n0 = blockIdx.x * 32, k0 = blockIdx.y * 32;
    int tx = threadIdx.x & 31, ty = threadIdx.x >> 5;
#pragma unroll
    for (int i = 0; i < 4; ++i)
        t[ty * 4 + i][tx] = W[(size_t)(k0 + ty * 4 + i) * N + n0 + tx];
    __syncthreads();
#pragma unroll
    for (int i = 0; i < 4; ++i) {
        int r = ty * 4 + i;
        T[(size_t)(n0 + r) * K + k0 + tx] = __float2half(t[tx][r]);
    }
}

// ----------------------------------------------------------------- mma.sync HGEMM (fp32 accum)
// D[M,N] = A[M,K] * B[N,K]^T; BK=64, 3-stage, 1 bar/iter.
// act: 0=fp32+bias; 1=gelu->fp16; 2=bias->fp16
#define MG_TILE_B  18432            // 128 rows * 72 halves * 2B
#define MG_STAGE_B (2 * MG_TILE_B)
#define MG_SMEM    (3 * MG_STAGE_B) // 110592

__global__ __launch_bounds__(256) void mma_gemm(
    const __half* __restrict__ A, const __half* __restrict__ B,
    const float* __restrict__ bias, float* __restrict__ outF,
    __half* __restrict__ outH, int N, int K, int act)
{
    extern __shared__ char smc[];
    const uint32_t sb = smem_u32(smc);
    const int tid = threadIdx.x, lane = tid & 31, wid = tid >> 5;
    const int wm = wid & 3, wn = wid >> 2;
    const int m0 = blockIdx.y << 7, n0 = blockIdx.x << 7;

    auto load_chunk = [&](int c, int buf) {
        int k0 = c << 6;
        uint32_t st = sb + buf * MG_STAGE_B;
#pragma unroll
        for (int j = 0; j < 4; ++j) {
            int q = tid + j * 256;
            int r = q >> 3, c8 = q & 7;
            uint32_t d = st + r * 144 + c8 * 16;
            CP16(d,             A + (size_t)(m0 + r) * K + k0 + c8 * 8);
            CP16(d + MG_TILE_B, B + (size_t)(n0 + r) * K + k0 + c8 * 8);
        }
    };

    const int mrow = (lane & 7) + ((lane >> 3) & 1) * 8;
    const int achk = lane >> 4;
    const int nrow = (lane & 7) + (lane >> 4) * 8;
    const int bchk = (lane >> 3) & 1;
    const uint32_t aoff = (uint32_t)(wm * 32 + mrow) * 144 + achk * 16;
    const uint32_t boff = (uint32_t)(wn * 64 + nrow) * 144 + bchk * 16;

    float acc[2][8][4];
#pragma unroll
    for (int i = 0; i < 2; ++i)
#pragma unroll
        for (int j = 0; j < 8; ++j)
#pragma unroll
            for (int e = 0; e < 4; ++e) acc[i][j][e] = 0.f;

    const int NC = K >> 6;
    load_chunk(0, 0); CP_COMMIT();
    load_chunk(1, 1); CP_COMMIT();

    int buf = 0, pbuf = 2;
    for (int c = 0; c < NC; ++c) {
        CP_WAIT1();
        __syncthreads();
        uint32_t st = sb + buf * MG_STAGE_B;
#pragma unroll
        for (int ks = 0; ks < 4; ++ks) {
            uint32_t ah[2][4], bh[4][4];
#pragma unroll
            for (int mt = 0; mt < 2; ++mt)
                LDSM4(ah[mt], st + aoff + mt * (16 * 144) + ks * 32);
#pragma unroll
            for (int g = 0; g < 4; ++g)
                LDSM4(bh[g], st + MG_TILE_B + boff + g * (16 * 144) + ks * 32);
#pragma unroll
            for (int mt = 0; mt < 2; ++mt)
#pragma unroll
                for (int g = 0; g < 4; ++g)
#pragma unroll
                    for (int h = 0; h < 2; ++h)
                        mma_f16(acc[mt][g * 2 + h], ah[mt], &bh[g][h * 2]);
        }
        if (c + 2 < NC) load_chunk(c + 2, pbuf);
        CP_COMMIT();
        buf  = (buf  == 2) ? 0 : buf  + 1;
        pbuf = (pbuf == 2) ? 0 : pbuf + 1;
    }

    const int g = lane >> 2, t4 = lane & 3;
#pragma unroll
    for (int mt = 0; mt < 2; ++mt) {
#pragma unroll
        for (int nt = 0; nt < 8; ++nt) {
            float* a = acc[mt][nt];
            int row = m0 + wm * 32 + mt * 16 + g;
            int col = n0 + wn * 64 + nt * 8 + 2 * t4;
            float b0 = bias[col], b1 = bias[col + 1];
            float v0 = a[0] + b0, v1 = a[1] + b1;
            float v2 = a[2] + b0, v3 = a[3] + b1;
            if (act == 0) {
                float2 u0; u0.x = v0; u0.y = v1;
                float2 u1; u1.x = v2; u1.y = v3;
                *(float2*)(outF + (size_t)row * N + col)       = u0;
                *(float2*)(outF + (size_t)(row + 8) * N + col) = u1;
            } else {
                if (act == 1) { v0 = gelu_t(v0); v1 = gelu_t(v1); v2 = gelu_t(v2); v3 = gelu_t(v3); }
                __half2 p;
                p.x = __float2half(v0); p.y = __float2half(v1);
                *(__half2*)(outH + (size_t)row * N + col) = p;
                p.x = __float2half(v2); p.y = __float2half(v3);
                *(__half2*)(outH + (size_t)(row + 8) * N + col) = p;
            }
        }
    }
}

// ----------------------------------------------------------------- RMSNorm + RoPE in-place fp16
__global__ __launch_bounds__(256) void rmsrope_kernel(
    __half* __restrict__ Qm, __half* __restrict__ Km,
    const float* __restrict__ nq, const float* __restrict__ nk,
    const float* __restrict__ cos_h, const float* __restrict__ sin_h,
    const float* __restrict__ cos_r, const float* __restrict__ sin_r)
{
    int row = blockIdx.x, tid = threadIdx.x;
    int isk = blockIdx.y;
    __half* x = (isk ? Km : Qm) + (size_t)row * C_DIM;
    const float* nw = isk ? nk : nq;
    float oscale = isk ? 1.f : C_SCALE;
    int isr = row >= C_SEQ;
    int pos = isr ? row - C_SEQ : row;
    const float* cp = (isr ? cos_r : cos_h) + (size_t)pos * 128;
    const float* sp = (isr ? sin_r : sin_h) + (size_t)pos * 128;
    float4 raw = *(const float4*)(x + tid * 8);
    __half2* hp2 = (__half2*)&raw;
    float xv[8];
#pragma unroll
    for (int p = 0; p < 4; ++p) {
        float2 f = __half22float2(hp2[p]);
        xv[2 * p] = f.x; xv[2 * p + 1] = f.y;
    }
    float ss = 0.f;
#pragma unroll
    for (int e = 0; e < 8; ++e) ss += xv[e] * xv[e];
#pragma unroll
    for (int o = 16; o > 0; o >>= 1) ss += __shfl_xor_sync(0xffffffffu, ss, o);
    __shared__ float rss[8];
    if ((tid & 31) == 0) rss[tid >> 5] = ss;
    __syncthreads();
    float tot = 0.f;
#pragma unroll
    for (int w = 0; w < 8; ++w) tot += rss[w];
    float rstd = rsqrtf(tot * (1.f / 2048.f) + 1e-6f);
    float4 outr;
    __half2* op2 = (__half2*)&outr;
#pragma unroll
    for (int p = 0; p < 4; ++p) {
        int ce = tid * 8 + 2 * p;
        int de = ce & 127;
        float x1 = xv[2 * p]     * rstd * nw[ce];
        float x2 = xv[2 * p + 1] * rstd * nw[ce + 1];
        float cv = cp[de], sv = sp[de + 1];
        __half2 hp;
        hp.x = __float2half((x1 * cv - x2 * sv) * oscale);
        hp.y = __float2half((x1 * sv + x2 * cv) * oscale);
        op2[p] = hp;
    }
    *(float4*)(x + tid * 8) = outr;
}

// ----------------------------------------------------------------- attention (fp16 mma flash, register softmax)
__device__ __forceinline__ int combined_row(int fi, int j) {
    int hi = j / 48;
    int wi = j - hi * 48;
    int base = (wi < 24) ? 0 : C_SEQ;
    int ww   = (wi < 24) ? wi : wi - 24;
    return base + fi * 576 + hi * 24 + ww;
}

#define AQ_STR 136
#define AP_STR 72
#define A_TILE  17408                 // 64*136*2 bytes
#define AO_Q    0
#define AO_K(b) (17408 + (b) * A_TILE)
#define AO_V(b) (52224 + (b) * A_TILE)
#define AO_PH   87040                 // fp16 [64][72]
#define AO_PMAX 96256                 // fp32 [2][64]
#define AO_PSUM 96768                 // fp32 [2][64]
#define AO_M    97280
#define AO_LR   97536
#define ATTN_SMEM 97792

__global__ __launch_bounds__(256) void attn_kernel(
    const __half* __restrict__ QhG, const __half* __restrict__ KhG,
    const __half* __restrict__ VhG, __half* __restrict__ OH)
{
    extern __shared__ char smc[];
    const uint32_t sb = smem_u32(smc);
    float* pmax = (float*)(smc + AO_PMAX);
    float* psum = (float*)(smc + AO_PSUM);
    float* mrow = (float*)(smc + AO_M);
    float* lrow = (float*)(smc + AO_LR);

    const int tid  = threadIdx.x, lane = tid & 31, wid = tid >> 5;
    const int wm = wid & 3, wn = wid >> 2;
    const int fi = blockIdx.y >> 4;
    const int coloff = (blockIdx.y & 15) * 128;
    const int q0 = blockIdx.x * 64;
    const int t4 = lane & 3;
    const int r1 = wm * 16 + (lane >> 2), r2 = r1 + 8;

    const int mrow_a = (lane & 7) + ((lane >> 3) & 1) * 8;
    const int achk   = lane >> 4;
    const int nrow_b = (lane & 7) + (lane >> 4) * 8;
    const int bchk   = (lane >> 3) & 1;
    const int vrow   = mrow_a;
    const int vc8    = (lane >> 4) * 8;

#pragma unroll
    for (int i = 0; i < 4; ++i) {
        int c = tid + i * 256;
        int r = c >> 4, ch8 = (c & 15) * 8;
        int grow = combined_row(fi, q0 + r);
        uint32_t d = (uint32_t)(r * AQ_STR + ch8) * 2;
        CP16(sb + AO_Q + d, QhG + (size_t)grow * C_DIM + coloff + ch8);
    }
    auto load_kv = [&](int kc, int buf) {
        int k0 = kc * 64;
#pragma unroll
        for (int i = 0; i < 4; ++i) {
            int c = tid + i * 256;
            int r = c >> 4, ch8 = (c & 15) * 8;
            int grow = combined_row(fi, k0 + r);
            size_t g = (size_t)grow * C_DIM + coloff + ch8;
            uint32_t d = (uint32_t)(r * AQ_STR + ch8) * 2;
            CP16(sb + AO_K(buf) + d, KhG + g);
            CP16(sb + AO_V(buf) + d, VhG + g);
        }
    };
    load_kv(0, 0);
    CP_COMMIT();
    if (tid < 64) { mrow[tid] = -1e30f; lrow[tid] = 0.f; }

    float oacc[8][4];
#pragma unroll
    for (int f = 0; f < 8; ++f)
#pragma unroll
        for (int e = 0; e < 4; ++e) oacc[f][e] = 0.f;

    const uint32_t qoff = (uint32_t)((wm * 16 + mrow_a) * AQ_STR + achk * 8) * 2;
    const uint32_t poff = (uint32_t)((wm * 16 + mrow_a) * AP_STR + achk * 8) * 2;

    for (int kc = 0; kc < 18; ++kc) {
        if (kc + 1 < 18) load_kv(kc + 1, (kc + 1) & 1);
        CP_COMMIT();
        CP_WAIT1();
        __syncthreads();                          // B1: KV visible
        const int buf = kc & 1;
        const uint32_t kb = sb + AO_K(buf), vb = sb + AO_V(buf);

        // ---- S = Q K^T (register-resident)
        float sacc[4][4];
#pragma unroll
        for (int f = 0; f < 4; ++f)
#pragma unroll
            for (int e = 0; e < 4; ++e) sacc[f][e] = 0.f;
        const uint32_t koff = (uint32_t)((wn * 32 + nrow_b) * AQ_STR + bchk * 8) * 2;
#pragma unroll
        for (int ks = 0; ks < 8; ++ks) {
            uint32_t ah[4];
            LDSM4(ah, sb + AO_Q + qoff + ks * 32);
#pragma unroll
            for (int g2 = 0; g2 < 2; ++g2) {
                uint32_t bh[4];
                LDSM4(bh, kb + koff + g2 * (16 * AQ_STR * 2) + ks * 32);
#pragma unroll
                for (int h = 0; h < 2; ++h)
                    mma_f16(sacc[g2 * 2 + h], ah, &bh[h * 2]);
            }
        }

        // ---- register softmax: warp-local partial max
        float m1 = -1e30f, m2 = -1e30f;
#pragma unroll
        for (int f = 0; f < 4; ++f) {
            m1 = fmaxf(m1, fmaxf(sacc[f][0], sacc[f][1]));
            m2 = fmaxf(m2, fmaxf(sacc[f][2], sacc[f][3]));
        }
        m1 = fmaxf(m1, __shfl_xor_sync(0xffffffffu, m1, 1));
        m1 = fmaxf(m1, __shfl_xor_sync(0xffffffffu, m1, 2));
        m2 = fmaxf(m2, __shfl_xor_sync(0xffffffffu, m2, 1));
        m2 = fmaxf(m2, __shfl_xor_sync(0xffffffffu, m2, 2));
        if (t4 == 0) { pmax[wn * 64 + r1] = m1; pmax[wn * 64 + r2] = m2; }
        __syncthreads();                          // B2: pmax ready

        float mo1 = mrow[r1], mo2 = mrow[r2];
        float mx1 = fmaxf(mo1, fmaxf(pmax[r1], pmax[64 + r1]));
        float mx2 = fmaxf(mo2, fmaxf(pmax[r2], pmax[64 + r2]));
        float fac1 = __expf(mo1 - mx1), fac2 = __expf(mo2 - mx2);
        float s1 = 0.f, s2 = 0.f;
        __half* PH = (__half*)(smc + AO_PH);
#pragma unroll
        for (int f = 0; f < 4; ++f) {
            int cc = wn * 32 + f * 8 + 2 * t4;
            float e0 = __expf(sacc[f][0] - mx1), e1 = __expf(sacc[f][1] - mx1);
            float e2 = __expf(sacc[f][2] - mx2), e3 = __expf(sacc[f][3] - mx2);
            s1 += e0 + e1; s2 += e2 + e3;
            __half2 hp;
            hp.x = __float2half(e0); hp.y = __float2half(e1);
            *(__half2*)(PH + r1 * AP_STR + cc) = hp;
            hp.x = __float2half(e2); hp.y = __float2half(e3);
            *(__half2*)(PH + r2 * AP_STR + cc) = hp;
        }
        s1 += __shfl_xor_sync(0xffffffffu, s1, 1);
        s1 += __shfl_xor_sync(0xffffffffu, s1, 2);
        s2 += __shfl_xor_sync(0xffffffffu, s2, 1);
        s2 += __shfl_xor_sync(0xffffffffu, s2, 2);
        if (t4 == 0) { psum[wn * 64 + r1] = s1; psum[wn * 64 + r2] = s2; }
#pragma unroll
        for (int f = 0; f < 8; ++f) {
            oacc[f][0] *= fac1; oacc[f][1] *= fac1;
            oacc[f][2] *= fac2; oacc[f][3] *= fac2;
        }
        __syncthreads();                          // B3: PH + psum visible
        if (wn == 0 && t4 == 0) {
            lrow[r1] = lrow[r1] * fac1 + psum[r1] + psum[64 + r1];
            mrow[r1] = mx1;
            lrow[r2] = lrow[r2] * fac2 + psum[r2] + psum[64 + r2];
            mrow[r2] = mx2;
        }

        // ---- O += P V
#pragma unroll
        for (int ks = 0; ks < 4; ++ks) {
            uint32_t ph[4];
            LDSM4(ph, sb + AO_PH + poff + ks * 32);
#pragma unroll
            for (int g2 = 0; g2 < 4; ++g2) {
                uint32_t vh[4];
                uint32_t p = (uint32_t)((ks * 16 + vrow) * AQ_STR + wn * 64 + g2 * 16 + vc8) * 2;
                LDSM4T(vh, vb + p);
#pragma unroll
                for (int h = 0; h < 2; ++h)
                    mma_f16(oacc[g2 * 2 + h], ph, &vh[h * 2]);
            }
        }
        __syncthreads();                          // B4
    }

    // ---- epilogue
    {
        float i1 = 1.f / lrow[r1], i2 = 1.f / lrow[r2];
        int g1 = combined_row(fi, q0 + r1), g2r = combined_row(fi, q0 + r2);
#pragma unroll
        for (int f = 0; f < 8; ++f) {
            int col = coloff + wn * 64 + f * 8 + 2 * t4;
            __half2 p;
            p.x = __float2half(oacc[f][0] * i1); p.y = __float2half(oacc[f][1] * i1);
            *(__half2*)(OH + (size_t)g1 * C_DIM + col) = p;
            p.x = __float2half(oacc[f][2] * i2); p.y = __float2half(oacc[f][3] * i2);
            *(__half2*)(OH + (size_t)g2r * C_DIM + col) = p;
        }
    }
}

// ----------------------------------------------------------------- residual gate
__global__ __launch_bounds__(256) void resid_kernel(
    float* __restrict__ st, const float* __restrict__ x, const float* __restrict__ t)
{
    size_t base = (size_t)blockIdx.x * C_DIM + threadIdx.x * 8;
    const float* g = t + 4096 + threadIdx.x * 8;
    float4 s0 = *(float4*)&st[base],      s1 = *(float4*)&st[base + 4];
    float4 x0 = *(const float4*)&x[base], x1 = *(const float4*)&x[base + 4];
    float4 g0 = *(const float4*)&g[0],    g1 = *(const float4*)&g[4];
    s0.x += g0.x * x0.x; s0.y += g0.y * x0.y; s0.z += g0.z * x0.z; s0.w += g0.w * x0.w;
    s1.x += g1.x * x1.x; s1.y += g1.y * x1.y; s1.z += g1.z * x1.z; s1.w += g1.w * x1.w;
    *(float4*)&st[base]     = s0;
    *(float4*)&st[base + 4] = s1;
}

// ----------------------------------------------------------------- launch
extern "C" void kernel_launch(void* const* d_in, const int* in_sizes, int n_in,
                              void* d_out, int out_size)
{
    const float* temb  = (const float*)d_in[2];
    const float* cos_h = (const float*)d_in[3];
    const float* sin_h = (const float*)d_in[4];
    const float* cos_r = (const float*)d_in[5];
    const float* sin_r = (const float*)d_in[6];
    const float* l1lw = (const float*)d_in[7],  *l1lb = (const float*)d_in[8];
    const float* l1nw = (const float*)d_in[9],  *l1nb = (const float*)d_in[10];
    const float* l2lw = (const float*)d_in[11], *l2lb = (const float*)d_in[12];
    const float* l2nw = (const float*)d_in[13], *l2nb = (const float*)d_in[14];
    const float* wq = (const float*)d_in[15], *bq = (const float*)d_in[16];
    const float* wk = (const float*)d_in[17], *bk = (const float*)d_in[18];
    const float* wv = (const float*)d_in[19], *bv = (const float*)d_in[20];
    const float* nqw = (const float*)d_in[21], *nkw = (const float*)d_in[22];
    const float* wo = (const float*)d_in[23], *bo = (const float*)d_in[24];
    const float* fw1 = (const float*)d_in[25], *fb1 = (const float*)d_in[26];
    const float* fw2 = (const float*)d_in[27], *fb2 = (const float*)d_in[28];
    float* st = (float*)d_out;

    float *t1, *t2, *tp;
    __half *nrm, *qH, *kH, *vH, *aoH, *mid;
    __half *wqh, *wkh, *wvh, *woh, *f1h, *f2h;
    cudaGetSymbolAddress((void**)&t1,  g_t1);
    cudaGetSymbolAddress((void**)&t2,  g_t2);
    cudaGetSymbolAddress((void**)&tp,  g_tp);
    cudaGetSymbolAddress((void**)&nrm, g_nrm);
    cudaGetSymbolAddress((void**)&qH, g_qH);
    cudaGetSymbolAddress((void**)&kH, g_kH);
    cudaGetSymbolAddress((void**)&vH, g_vH);
    cudaGetSymbolAddress((void**)&aoH, g_aoH);
    cudaGetSymbolAddress((void**)&mid, g_mid);
    cudaGetSymbolAddress((void**)&wqh, g_wq);
    cudaGetSymbolAddress((void**)&wkh, g_wk);
    cudaGetSymbolAddress((void**)&wvh, g_wv);
    cudaGetSymbolAddress((void**)&woh, g_wo);
    cudaGetSymbolAddress((void**)&f1h, g_f1);
    cudaGetSymbolAddress((void**)&f2h, g_f2);

    cudaFuncSetAttribute(attn_kernel, cudaFuncAttributeMaxDynamicSharedMemorySize, ATTN_SMEM);
    cudaFuncSetAttribute(mma_gemm,    cudaFuncAttributeMaxDynamicSharedMemorySize, MG_SMEM);

    wconv_kernel<<<dim3(64, 64),   256>>>(wq,  wqh, C_DIM, C_DIM);
    wconv_kernel<<<dim3(64, 64),   256>>>(wk,  wkh, C_DIM, C_DIM);
    wconv_kernel<<<dim3(64, 64),   256>>>(wv,  wvh, C_DIM, C_DIM);
    wconv_kernel<<<dim3(64, 64),   256>>>(wo,  woh, C_DIM, C_DIM);
    wconv_kernel<<<dim3(256, 64),  256>>>(fw1, f1h, C_DIM, C_FFN);
    wconv_kernel<<<dim3(64, 256),  256>>>(fw2, f2h, C_FFN, C_DIM);

    temb_kernel<<<dim3(24, 2), 256>>>(temb, l1lw, l1lb, l2lw, l2lb, t1, t2);
    ln_mod_first<<<C_ROWS, 256>>>((const float*)d_in[0], (const float*)d_in[1],
                                  t1, l1nw, l1nb, nrm, st);
    mma_gemm<<<dim3(16, 36), 256, MG_SMEM>>>(nrm, wqh, bq, 0, qH, C_DIM, C_DIM, 2);
    mma_gemm<<<dim3(16, 36), 256, MG_SMEM>>>(nrm, wkh, bk, 0, kH, C_DIM, C_DIM, 2);
    mma_gemm<<<dim3(16, 36), 256, MG_SMEM>>>(nrm, wvh, bv, 0, vH, C_DIM, C_DIM, 2);
    rmsrope_kernel<<<dim3(C_ROWS, 2), 256>>>(qH, kH, nqw, nkw, cos_h, sin_h, cos_r, sin_r);
    attn_kernel<<<dim3(18, 64), 256, ATTN_SMEM>>>(qH, kH, vH, aoH);
    mma_gemm<<<dim3(16, 36), 256, MG_SMEM>>>(aoH, woh, bo, tp, 0, C_DIM, C_DIM, 0);
    resid_ln_kernel<<<C_ROWS, 256>>>(st, tp, t1, t2, l2nw, l2nb, nrm);
    mma_gemm<<<dim3(64, 36), 256, MG_SMEM>>>(nrm, f1h, fb1, 0, mid, C_FFN, C_DIM, 1);
    mma_gemm<<<dim3(16, 36), 256, MG_SMEM>>>(mid, f2h, fb2, tp, 0, C_DIM, C_FFN, 0);
    resid_kernel<<<C_ROWS, 256>>>(st, tp, t2);
}